// round 2
// baseline (speedup 1.0000x reference)
#include <cuda_runtime.h>

#define NF 8192
#define DMODEL 512
#define NHEADS 8
#define DH 64
#define NLAND 256
#define NBATCH 2
#define NBH 16
#define QKVW 1536
#define NROWS (NBATCH*NF)
#define KCONV 33

// ------------------------- scratch (device globals; no allocs allowed) -----
__device__ __align__(16) float g_X  [(size_t)NBATCH*NF*DMODEL];
__device__ __align__(16) float g_XLN[(size_t)NBATCH*NF*DMODEL];
__device__ __align__(16) float g_QKV[(size_t)NBATCH*NF*QKVW];
__device__ __align__(16) float g_QL [(size_t)NBH*NLAND*DH];
__device__ __align__(16) float g_KL [(size_t)NBH*NLAND*DH];
__device__ __align__(16) float g_S1 [(size_t)NBH*NF*NLAND];
__device__ __align__(16) float g_S3 [(size_t)NBH*NF*NLAND];
__device__ __align__(16) float g_S2 [(size_t)NBH*NLAND*NLAND];
__device__ __align__(16) float g_T  [(size_t)NBH*NLAND*NLAND];
__device__ __align__(16) float g_U  [(size_t)NBH*NLAND*NLAND];
__device__ __align__(16) float g_R  [(size_t)NBH*NLAND*NLAND];
__device__ __align__(16) float g_Z  [(size_t)NBH*NLAND*NLAND];
__device__ __align__(16) float g_Z2 [(size_t)NBH*NLAND*NLAND];
__device__ __align__(16) float g_W  [(size_t)NBH*NLAND*DH];
__device__ __align__(16) float g_Wp [(size_t)8*NBH*NLAND*DH];
__device__ __align__(16) float g_O  [(size_t)NBH*NF*DH];
__device__ __align__(16) float g_OC [(size_t)NBATCH*NF*DMODEL];
__device__ float g_scal[2];

// ------------------------------- SGEMM -------------------------------------
// C[M,N] = alpha * A[M,K] @ (TRANSB ? B[N,K]^T : B[K,N]) (+bias)(+resid)(relu)
// Batched over gridDim.z = nb*nsplit; batch z decomposed as b = z/8, h = z%8
// with separate strides for each, so both (b,h)-strided views of QKV and
// contiguous per-z buffers are expressible. SPLITK writes per-split partials
// (deterministic; reduced by a separate kernel).
template<bool TRANSB, bool SPLITK>
__global__ __launch_bounds__(256) void sgemm(
    const float* __restrict__ A, const float* __restrict__ B, float* __restrict__ C,
    int M, int N, int K, int lda, int ldb, int ldc,
    long long sAb, long long sAh, long long sBb, long long sBh,
    long long sCb, long long sCh,
    const float* __restrict__ bias, const float* __restrict__ resid, int ldr,
    float alpha, int relu, int nsplit, int Kc, long long sSp)
{
    int zAll = blockIdx.z;
    int zb = zAll / nsplit;
    int sp = zAll - zb * nsplit;
    int bb = zb >> 3, hh = zb & 7;
    const float* Ap = A + bb*sAb + hh*sAh;
    const float* Bp = B + bb*sBb + hh*sBh;
    float*       Cp = C + bb*sCb + hh*sCh + (SPLITK ? (long long)sp * sSp : 0LL);

    int bm0 = blockIdx.y * 128;
    int bn0 = blockIdx.x * 128;
    int k0   = SPLITK ? sp * Kc : 0;
    int kEnd = SPLITK ? min(K, k0 + Kc) : K;

    __shared__ __align__(16) float As[8][128];
    __shared__ __align__(16) float Bs[8][128];

    int tid = threadIdx.x;
    int tx = tid & 15, ty = tid >> 4;
    float acc[8][8];
    #pragma unroll
    for (int i = 0; i < 8; i++)
        #pragma unroll
        for (int j = 0; j < 8; j++) acc[i][j] = 0.f;

    int arow = bm0 + (tid >> 1);
    int akq  = (tid & 1) * 4;

    for (int kk = k0; kk < kEnd; kk += 8) {
        // ---- load A tile (128 rows x 8 k), transposed into As[k][m]
        float4 av = make_float4(0.f,0.f,0.f,0.f);
        if (arow < M) av = *(const float4*)(Ap + (long long)arow*lda + kk + akq);
        As[akq+0][tid>>1] = av.x;
        As[akq+1][tid>>1] = av.y;
        As[akq+2][tid>>1] = av.z;
        As[akq+3][tid>>1] = av.w;
        // ---- load B tile
        if (TRANSB) {
            int n = bn0 + (tid >> 1);
            float4 bv = make_float4(0.f,0.f,0.f,0.f);
            if (n < N) bv = *(const float4*)(Bp + (long long)n*ldb + kk + akq);
            Bs[akq+0][tid>>1] = bv.x;
            Bs[akq+1][tid>>1] = bv.y;
            Bs[akq+2][tid>>1] = bv.z;
            Bs[akq+3][tid>>1] = bv.w;
        } else {
            int bk = tid >> 5;
            int bn = (tid & 31) * 4;
            int gc = bn0 + bn;
            const float* p = Bp + (long long)(kk + bk)*ldb + gc;
            float4 bv;
            if (gc + 3 < N) bv = *(const float4*)p;
            else {
                bv.x = (gc+0 < N) ? p[0] : 0.f;
                bv.y = (gc+1 < N) ? p[1] : 0.f;
                bv.z = (gc+2 < N) ? p[2] : 0.f;
                bv.w = (gc+3 < N) ? p[3] : 0.f;
            }
            *(float4*)&Bs[bk][bn] = bv;
        }
        __syncthreads();
        #pragma unroll
        for (int k = 0; k < 8; k++) {
            float ra[8], rb[8];
            *(float4*)&ra[0] = *(const float4*)&As[k][ty*4];
            *(float4*)&ra[4] = *(const float4*)&As[k][64 + ty*4];
            *(float4*)&rb[0] = *(const float4*)&Bs[k][tx*4];
            *(float4*)&rb[4] = *(const float4*)&Bs[k][64 + tx*4];
            #pragma unroll
            for (int i = 0; i < 8; i++)
                #pragma unroll
                for (int j = 0; j < 8; j++)
                    acc[i][j] += ra[i] * rb[j];
        }
        __syncthreads();
    }

    #pragma unroll
    for (int i = 0; i < 8; i++) {
        int r = bm0 + ((i < 4) ? (ty*4 + i) : (64 + ty*4 + i - 4));
        if (r >= M) continue;
        #pragma unroll
        for (int j = 0; j < 8; j++) {
            int c = bn0 + ((j < 4) ? (tx*4 + j) : (64 + tx*4 + j - 4));
            if (c >= N) continue;
            float v = acc[i][j] * alpha;
            long long off = (long long)r*ldc + c;
            if (SPLITK) {
                Cp[off] = v;
            } else {
                if (bias)  v += bias[c];
                if (resid) v += resid[(long long)r*ldr + c];
                if (relu)  v = fmaxf(v, 0.f);
                Cp[off] = v;
            }
        }
    }
}

// ------------------------------ helpers ------------------------------------
__global__ void reduce_split_kernel(const float* __restrict__ Wp, float* __restrict__ W,
                                    int ns, long long stride)
{
    long long idx = (long long)blockIdx.x * blockDim.x + threadIdx.x;
    float s = 0.f;
    for (int k = 0; k < 8; k++) s += Wp[(long long)k*stride + idx];
    W[idx] = s;
}

__global__ void ln_kernel(const float* __restrict__ X, float* __restrict__ Y,
                          const float* __restrict__ g, const float* __restrict__ b)
{
    long long r = blockIdx.x;
    int tid = threadIdx.x;   // 128
    float4 v = ((const float4*)(X + r*DMODEL))[tid];
    float s = v.x+v.y+v.z+v.w;
    float q = v.x*v.x + v.y*v.y + v.z*v.z + v.w*v.w;
    #pragma unroll
    for (int o = 16; o; o >>= 1) {
        s += __shfl_xor_sync(0xffffffffu, s, o);
        q += __shfl_xor_sync(0xffffffffu, q, o);
    }
    __shared__ float ss[4], qq[4];
    if ((tid & 31) == 0) { ss[tid>>5] = s; qq[tid>>5] = q; }
    __syncthreads();
    s = ss[0]+ss[1]+ss[2]+ss[3];
    q = qq[0]+qq[1]+qq[2]+qq[3];
    float mu = s * (1.f/DMODEL);
    float var = q * (1.f/DMODEL) - mu*mu;
    float rs = rsqrtf(var + 1e-5f);
    float4 gv = ((const float4*)g)[tid];
    float4 bv = ((const float4*)b)[tid];
    float4 o;
    o.x = (v.x-mu)*rs*gv.x + bv.x;
    o.y = (v.y-mu)*rs*gv.y + bv.y;
    o.z = (v.z-mu)*rs*gv.z + bv.z;
    o.w = (v.w-mu)*rs*gv.w + bv.w;
    ((float4*)(Y + r*DMODEL))[tid] = o;
}

__global__ void cls_copy_kernel(float* __restrict__ X, const float* __restrict__ cls)
{
    int c = threadIdx.x;  // 512
    X[c] = cls[c];
    X[(long long)NF*DMODEL + c] = cls[c];
}

__global__ void landmark_kernel(const float* __restrict__ QKV, float* __restrict__ out, int off)
{
    int j = blockIdx.x;          // landmark 0..255
    int z = blockIdx.y;          // bh 0..15
    int d = threadIdx.x;         // 0..63
    int b = z >> 3, h = z & 7;
    const float* base = QKV + ((long long)b*NF + (long long)j*32)*QKVW + off + h*DH + d;
    float s = 0.f;
    #pragma unroll
    for (int t = 0; t < 32; t++) s += base[(long long)t*QKVW];
    out[((long long)z*NLAND + j)*DH + d] = s * (1.f/32.f);
}

__global__ void softmax_kernel(float* __restrict__ X, int cols)
{
    long long row = blockIdx.x;
    float* p = X + row * cols;
    int tid = threadIdx.x;   // 256
    __shared__ float sred[8];
    __shared__ float sval;
    float m = -1e30f;
    for (int c = tid; c < cols; c += 256) m = fmaxf(m, p[c]);
    #pragma unroll
    for (int o = 16; o; o >>= 1) m = fmaxf(m, __shfl_xor_sync(0xffffffffu, m, o));
    if ((tid & 31) == 0) sred[tid>>5] = m;
    __syncthreads();
    if (tid == 0) {
        float mm = sred[0];
        for (int i = 1; i < 8; i++) mm = fmaxf(mm, sred[i]);
        sval = mm;
    }
    __syncthreads();
    m = sval;
    __syncthreads();
    float s = 0.f;
    for (int c = tid; c < cols; c += 256) {
        float e = __expf(p[c] - m);
        p[c] = e;
        s += e;
    }
    #pragma unroll
    for (int o = 16; o; o >>= 1) s += __shfl_xor_sync(0xffffffffu, s, o);
    if ((tid & 31) == 0) sred[tid>>5] = s;
    __syncthreads();
    if (tid == 0) {
        float t = 0.f;
        for (int i = 0; i < 8; i++) t += sred[i];
        sval = t;
    }
    __syncthreads();
    float inv = 1.f / sval;
    for (int c = tid; c < cols; c += 256) p[c] *= inv;
}

__device__ __forceinline__ void atomicMaxF(float* addr, float v)
{
    atomicMax((int*)addr, __float_as_int(v));   // valid for non-negative floats
}

__global__ void pinv_reduce_kernel(const float* __restrict__ S2, float* __restrict__ scal)
{
    int z = blockIdx.x;
    int tid = threadIdx.x;   // 256
    const float* Mz = S2 + (long long)z * NLAND * NLAND;
    float rs = 0.f, cs = 0.f;
    for (int j = 0; j < NLAND; j++) rs += Mz[(long long)tid*NLAND + j];
    for (int i = 0; i < NLAND; i++) cs += Mz[(long long)i*NLAND + tid];
    __shared__ float sm[256];
    sm[tid] = rs; __syncthreads();
    for (int s = 128; s; s >>= 1) { if (tid < s) sm[tid] = fmaxf(sm[tid], sm[tid+s]); __syncthreads(); }
    if (tid == 0) atomicMaxF(&scal[0], sm[0]);
    __syncthreads();
    sm[tid] = cs; __syncthreads();
    for (int s = 128; s; s >>= 1) { if (tid < s) sm[tid] = fmaxf(sm[tid], sm[tid+s]); __syncthreads(); }
    if (tid == 0) atomicMaxF(&scal[1], sm[0]);
}

__global__ void zinit_kernel(float* __restrict__ Z, const float* __restrict__ S2,
                             const float* __restrict__ scal)
{
    long long idx = (long long)blockIdx.x * blockDim.x + threadIdx.x;
    float rcp = 1.f / (scal[0] * scal[1]);
    long long z = idx >> 16;
    int r = (int)((idx >> 8) & 255);
    int c = (int)(idx & 255);
    Z[idx] = S2[(z << 16) + ((long long)c << 8) + r] * rcp;
}

__global__ void diagsub_kernel(float* __restrict__ Out, const float* __restrict__ In, float cc)
{
    long long idx = (long long)blockIdx.x * blockDim.x + threadIdx.x;
    int r = (int)((idx >> 8) & 255);
    int c = (int)(idx & 255);
    Out[idx] = cc * (r == c ? 1.f : 0.f) - In[idx];
}

__global__ void conv_kernel(float* __restrict__ O, const float* __restrict__ QKV,
                            const float* __restrict__ cw)
{
    int t0 = blockIdx.x * 128;
    int h = blockIdx.y;
    int b = blockIdx.z;
    __shared__ float sv[160*64];
    __shared__ float ws[KCONV];
    int tid = threadIdx.x;   // 256
    if (tid < KCONV) ws[tid] = cw[h*KCONV + tid];
    for (int i = tid; i < 160*64; i += 256) {
        int tl = i >> 6, d = i & 63;
        int t = t0 + tl - 16;
        float v = 0.f;
        if (t >= 0 && t < NF)
            v = QKV[((long long)b*NF + t)*QKVW + 2*DMODEL + h*DH + d];
        sv[i] = v;
    }
    __syncthreads();
    float* Op = O + (((long long)(b*NHEADS + h))*NF + t0)*DH;
    for (int i = tid; i < 128*64; i += 256) {
        int tl = i >> 6, d = i & 63;
        float acc = 0.f;
        #pragma unroll
        for (int k = 0; k < KCONV; k++) acc += ws[k] * sv[(tl + k)*64 + d];
        Op[i] += acc;
    }
}

__global__ void merge_kernel(const float* __restrict__ O, float* __restrict__ OC)
{
    long long idx = (long long)blockIdx.x * blockDim.x + threadIdx.x;
    int c = (int)(idx & 511);
    int n = (int)((idx >> 9) & (NF - 1));
    int b = (int)(idx >> 22);
    int h = c >> 6, d = c & 63;
    OC[idx] = O[(((long long)(b*NHEADS + h))*NF + n)*DH + d];
}

__global__ void final_kernel(const float* __restrict__ X, const float* __restrict__ g,
                             const float* __restrict__ bt, const float* __restrict__ w2,
                             const float* __restrict__ b2, float* __restrict__ out)
{
    int b = blockIdx.x;
    int tid = threadIdx.x;  // 128
    const float* x = X + (long long)b*NF*DMODEL;
    float4 v = ((const float4*)x)[tid];
    float s = v.x+v.y+v.z+v.w;
    float q = v.x*v.x + v.y*v.y + v.z*v.z + v.w*v.w;
    #pragma unroll
    for (int o = 16; o; o >>= 1) {
        s += __shfl_xor_sync(0xffffffffu, s, o);
        q += __shfl_xor_sync(0xffffffffu, q, o);
    }
    __shared__ float ss[4], qq[4];
    if ((tid & 31) == 0) { ss[tid>>5] = s; qq[tid>>5] = q; }
    __syncthreads();
    s = ss[0]+ss[1]+ss[2]+ss[3];
    q = qq[0]+qq[1]+qq[2]+qq[3];
    float mu = s * (1.f/DMODEL);
    float var = q * (1.f/DMODEL) - mu*mu;
    float rs = rsqrtf(var + 1e-5f);
    __shared__ float xn[DMODEL];
    float4 gv = ((const float4*)g)[tid];
    float4 bv = ((const float4*)bt)[tid];
    xn[tid*4+0] = (v.x-mu)*rs*gv.x + bv.x;
    xn[tid*4+1] = (v.y-mu)*rs*gv.y + bv.y;
    xn[tid*4+2] = (v.z-mu)*rs*gv.z + bv.z;
    xn[tid*4+3] = (v.w-mu)*rs*gv.w + bv.w;
    __syncthreads();
    float s0 = 0.f, s1 = 0.f;
    for (int d = tid; d < DMODEL; d += 128) {
        float xv = xn[d];
        s0 += xv * w2[d*2+0];
        s1 += xv * w2[d*2+1];
    }
    __shared__ float r0[128], r1[128];
    r0[tid] = s0; r1[tid] = s1;
    __syncthreads();
    for (int st = 64; st; st >>= 1) {
        if (tid < st) { r0[tid] += r0[tid+st]; r1[tid] += r1[tid+st]; }
        __syncthreads();
    }
    if (tid == 0) {
        out[b*2+0] = r0[0] + b2[0];
        out[b*2+1] = r1[0] + b2[1];
    }
}

// ------------------------------ host side ----------------------------------
struct Bufs {
    float *X,*XLN,*QKV,*QL,*KL,*S1,*S3,*S2,*T,*U,*Rb,*Z,*Z2,*W,*Wp,*O,*OC,*scal;
};

static Bufs init_bufs()
{
    Bufs b;
    cudaGetSymbolAddress((void**)&b.X,   g_X);
    cudaGetSymbolAddress((void**)&b.XLN, g_XLN);
    cudaGetSymbolAddress((void**)&b.QKV, g_QKV);
    cudaGetSymbolAddress((void**)&b.QL,  g_QL);
    cudaGetSymbolAddress((void**)&b.KL,  g_KL);
    cudaGetSymbolAddress((void**)&b.S1,  g_S1);
    cudaGetSymbolAddress((void**)&b.S3,  g_S3);
    cudaGetSymbolAddress((void**)&b.S2,  g_S2);
    cudaGetSymbolAddress((void**)&b.T,   g_T);
    cudaGetSymbolAddress((void**)&b.U,   g_U);
    cudaGetSymbolAddress((void**)&b.Rb,  g_R);
    cudaGetSymbolAddress((void**)&b.Z,   g_Z);
    cudaGetSymbolAddress((void**)&b.Z2,  g_Z2);
    cudaGetSymbolAddress((void**)&b.W,   g_W);
    cudaGetSymbolAddress((void**)&b.Wp,  g_Wp);
    cudaGetSymbolAddress((void**)&b.O,   g_O);
    cudaGetSymbolAddress((void**)&b.OC,  g_OC);
    cudaGetSymbolAddress((void**)&b.scal,g_scal);
    return b;
}

static inline void gemm_call(const float* A, const float* B, float* C,
    int M, int N, int K, int lda, int ldb, int ldc, int nb,
    long long sAb, long long sAh, long long sBb, long long sBh,
    long long sCb, long long sCh,
    const float* bias, const float* resid, int ldr,
    float alpha, int relu, bool transb,
    int nsplit = 1, int Kc = 0, long long sSp = 0)
{
    dim3 gr((N + 127)/128, (M + 127)/128, nb * nsplit);
    if (nsplit > 1) {
        if (transb)
            sgemm<true,true><<<gr,256>>>(A,B,C,M,N,K,lda,ldb,ldc,sAb,sAh,sBb,sBh,sCb,sCh,bias,resid,ldr,alpha,relu,nsplit,Kc,sSp);
        else
            sgemm<false,true><<<gr,256>>>(A,B,C,M,N,K,lda,ldb,ldc,sAb,sAh,sBb,sBh,sCb,sCh,bias,resid,ldr,alpha,relu,nsplit,Kc,sSp);
    } else {
        if (transb)
            sgemm<true,false><<<gr,256>>>(A,B,C,M,N,K,lda,ldb,ldc,sAb,sAh,sBb,sBh,sCb,sCh,bias,resid,ldr,alpha,relu,1,0,0);
        else
            sgemm<false,false><<<gr,256>>>(A,B,C,M,N,K,lda,ldb,ldc,sAb,sAh,sBb,sBh,sCb,sCh,bias,resid,ldr,alpha,relu,1,0,0);
    }
}

static void run_layer(const Bufs& bu, int L, void* const* d_in)
{
    const float* lng  = (const float*)d_in[4] + (size_t)L*DMODEL;
    const float* lnb  = (const float*)d_in[5] + (size_t)L*DMODEL;
    const float* wqkv = (const float*)d_in[6] + (size_t)L*DMODEL*QKVW;
    const float* wout = (const float*)d_in[7] + (size_t)L*DMODEL*DMODEL;
    const float* bout = (const float*)d_in[8] + (size_t)L*DMODEL;
    const float* cw   = (const float*)d_in[9] + (size_t)L*NHEADS*KCONV;

    const long long sQKVb = (long long)NF*QKVW;   // per-batch stride in QKV
    const long long sLh = (long long)NLAND*DH;    // landmark per-head
    const long long sLb = (long long)NHEADS*sLh;
    const long long sS1h = (long long)NF*NLAND;
    const long long sS1b = (long long)NHEADS*sS1h;
    const long long sS3h = (long long)NLAND*NF;
    const long long sS3b = (long long)NHEADS*sS3h;
    const long long sm = (long long)NLAND*NLAND;
    const long long smb = (long long)NHEADS*sm;
    const long long sOh = (long long)NF*DH;
    const long long sOb = (long long)NHEADS*sOh;

    // x_ln = LN(x)
    ln_kernel<<<NROWS,128>>>(bu.X, bu.XLN, lng, lnb);
    // QKV = x_ln @ w_qkv
    gemm_call(bu.XLN, wqkv, bu.QKV, NROWS, QKVW, DMODEL, DMODEL, QKVW, QKVW, 1,
              0,0,0,0,0,0, nullptr,nullptr,0, 1.f,0,false);
    // landmarks (means of contiguous 32-chunks)
    landmark_kernel<<<dim3(NLAND,NBH),64>>>(bu.QKV, bu.QL, 0);
    landmark_kernel<<<dim3(NLAND,NBH),64>>>(bu.QKV, bu.KL, DMODEL);
    // sim1 = (q*scale) @ k_l^T   (q read strided from QKV)
    gemm_call(bu.QKV, bu.KL, bu.S1, NF, NLAND, DH, QKVW, DH, NLAND, NBH,
              sQKVb, DH, sLb, sLh, sS1b, sS1h, nullptr,nullptr,0, 0.125f,0,true);
    // sim2 = (q_l*scale) @ k_l^T
    gemm_call(bu.QL, bu.KL, bu.S2, NLAND, NLAND, DH, DH, DH, NLAND, NBH,
              sLb, sLh, sLb, sLh, smb, sm, nullptr,nullptr,0, 0.125f,0,true);
    // sim3 = (q_l*scale) @ k^T   (k read strided from QKV)
    gemm_call(bu.QL, bu.QKV + DMODEL, bu.S3, NLAND, NF, DH, DH, QKVW, NF, NBH,
              sLb, sLh, sQKVb, DH, sS3b, sS3h, nullptr,nullptr,0, 0.125f,0,true);
    // softmaxes
    softmax_kernel<<<NBH*NF,256>>>(bu.S1, NLAND);
    softmax_kernel<<<NBH*NLAND,256>>>(bu.S2, NLAND);
    softmax_kernel<<<NBH*NLAND,256>>>(bu.S3, NF);
    // Moore-Penrose pinv of S2 (global-scaled Newton-Schulz, 6 iters)
    cudaMemsetAsync(bu.scal, 0, 2*sizeof(float));
    pinv_reduce_kernel<<<NBH,256>>>(bu.S2, bu.scal);
    zinit_kernel<<<(NBH*NLAND*NLAND)/256,256>>>(bu.Z, bu.S2, bu.scal);
    float* za = bu.Z;
    float* zb = bu.Z2;
    for (int it = 0; it < 6; it++) {
        gemm_call(bu.S2, za, bu.T, NLAND,NLAND,NLAND, NLAND,NLAND,NLAND, NBH,
                  smb,sm, smb,sm, smb,sm, nullptr,nullptr,0, 1.f,0,false);
        diagsub_kernel<<<(NBH*NLAND*NLAND)/256,256>>>(bu.U, bu.T, 7.f);
        gemm_call(bu.T, bu.U, bu.Rb, NLAND,NLAND,NLAND, NLAND,NLAND,NLAND, NBH,
                  smb,sm, smb,sm, smb,sm, nullptr,nullptr,0, 1.f,0,false);
        diagsub_kernel<<<(NBH*NLAND*NLAND)/256,256>>>(bu.Rb, bu.Rb, 15.f);
        gemm_call(bu.T, bu.Rb, bu.U, NLAND,NLAND,NLAND, NLAND,NLAND,NLAND, NBH,
                  smb,sm, smb,sm, smb,sm, nullptr,nullptr,0, 1.f,0,false);
        diagsub_kernel<<<(NBH*NLAND*NLAND)/256,256>>>(bu.U, bu.U, 13.f);
        gemm_call(za, bu.U, zb, NLAND,NLAND,NLAND, NLAND,NLAND,NLAND, NBH,
                  smb,sm, smb,sm, smb,sm, nullptr,nullptr,0, 0.25f,0,false);
        float* tp = za; za = zb; zb = tp;
    }
    // W = attn3 @ v  (deterministic split-K into partials, then reduce)
    gemm_call(bu.S3, bu.QKV + 2*DMODEL, bu.Wp, NLAND, DH, NF, NF, QKVW, DH, NBH,
              sS3b, sS3h, sQKVb, DH, sLb, sLh, nullptr,nullptr,0, 1.f,0,false,
              8, 1024, (long long)NBH*NLAND*DH);
    reduce_split_kernel<<<(NBH*NLAND*DH)/256,256>>>(bu.Wp, bu.W, 8, (long long)NBH*NLAND*DH);
    // P = attn1 @ Z   (reuse S3 buffer)
    gemm_call(bu.S1, za, bu.S3, NF, NLAND, NLAND, NLAND, NLAND, NLAND, NBH,
              sS1b, sS1h, smb, sm, sS1b, sS1h, nullptr,nullptr,0, 1.f,0,false);
    // O = P @ W
    gemm_call(bu.S3, bu.W, bu.O, NF, DH, NLAND, NLAND, DH, DH, NBH,
              sS1b, sS1h, sLb, sLh, sOb, sOh, nullptr,nullptr,0, 1.f,0,false);
    // O += depthwise conv of V over sequence
    conv_kernel<<<dim3(NF/128, NHEADS, NBATCH),256>>>(bu.O, bu.QKV, cw);
    // concat heads
    merge_kernel<<<((long long)NBATCH*NF*DMODEL)/256,256>>>(bu.O, bu.OC);
    // x = x + (OC @ w_out + b_out)
    gemm_call(bu.OC, wout, bu.X, NROWS, DMODEL, DMODEL, DMODEL, DMODEL, DMODEL, 1,
              0,0,0,0,0,0, bout, bu.X, DMODEL, 1.f,0,false);
}

extern "C" void kernel_launch(void* const* d_in, const int* in_sizes, int n_in,
                              void* d_out, int out_size)
{
    static Bufs bu = init_bufs();
    const float* h    = (const float*)d_in[0];
    const float* w1   = (const float*)d_in[1];
    const float* b1   = (const float*)d_in[2];
    const float* cls  = (const float*)d_in[3];
    const float* fng  = (const float*)d_in[10];
    const float* fnb  = (const float*)d_in[11];
    const float* w2   = (const float*)d_in[12];
    const float* b2   = (const float*)d_in[13];

    // x = relu(h @ w1 + b1), placed at rows 1..8191; cls at row 0
    for (int b = 0; b < NBATCH; b++)
        gemm_call(h + (long long)b*8191*1024, w1, bu.X + ((long long)b*NF + 1)*DMODEL,
                  8191, DMODEL, 1024, 1024, DMODEL, DMODEL, 1,
                  0,0,0,0,0,0, b1, nullptr,0, 1.f, 1, false);
    cls_copy_kernel<<<1,512>>>(bu.X, cls);

    run_layer(bu, 0, d_in);
    run_layer(bu, 1, d_in);

    final_kernel<<<NBATCH,128>>>(bu.X, fng, fnb, w2, b2, (float*)d_out);
}

// round 5
// speedup vs baseline: 1.0277x; 1.0277x over previous
#include <cuda_runtime.h>

#define NF 8192
#define DMODEL 512
#define NHEADS 8
#define DH 64
#define NLAND 256
#define NBATCH 2
#define NBH 16
#define QKVW 1536
#define NROWS (NBATCH*NF)
#define KCONV 33

// ------------------------- scratch (device globals; no allocs allowed) -----
__device__ __align__(16) float g_X  [(size_t)NBATCH*NF*DMODEL];
__device__ __align__(16) float g_XLN[(size_t)NBATCH*NF*DMODEL];
__device__ __align__(16) float g_QKV[(size_t)NBATCH*NF*QKVW];
__device__ __align__(16) float g_QL [(size_t)NBH*NLAND*DH];
__device__ __align__(16) float g_KL [(size_t)NBH*NLAND*DH];
__device__ __align__(16) float g_S1 [(size_t)NBH*NF*NLAND];
__device__ __align__(16) float g_S3 [(size_t)NBH*NF*NLAND];
__device__ __align__(16) float g_S2 [(size_t)NBH*NLAND*NLAND];
__device__ __align__(16) float g_T  [(size_t)NBH*NLAND*NLAND];
__device__ __align__(16) float g_U  [(size_t)NBH*NLAND*NLAND];
__device__ __align__(16) float g_R  [(size_t)NBH*NLAND*NLAND];
__device__ __align__(16) float g_Z  [(size_t)NBH*NLAND*NLAND];
__device__ __align__(16) float g_Z2 [(size_t)NBH*NLAND*NLAND];
__device__ __align__(16) float g_W  [(size_t)NBH*NLAND*DH];
__device__ __align__(16) float g_Wp [(size_t)8*NBH*NLAND*DH];
__device__ __align__(16) float g_O  [(size_t)NBH*NF*DH];
__device__ __align__(16) float g_OC [(size_t)NBATCH*NF*DMODEL];
__device__ __align__(16) float g_RS1[(size_t)NBH*NF];
__device__ __align__(16) float g_RS3[(size_t)NBH*NLAND];
__device__ float g_scal[2];

// ------------------------- f32x2 packed helpers ----------------------------
__device__ __forceinline__ unsigned long long pack2_dup(float x)
{
    unsigned long long r;
    unsigned int u = __float_as_uint(x);
    asm("mov.b64 %0, {%1, %1};" : "=l"(r) : "r"(u));
    return r;
}
__device__ __forceinline__ void ffma2(unsigned long long& d,
                                      unsigned long long a, unsigned long long b)
{
    asm("fma.rn.f32x2 %0, %1, %2, %0;" : "+l"(d) : "l"(a), "l"(b));
}
__device__ __forceinline__ float2 unpack2(unsigned long long v)
{
    unsigned int lo, hi;
    asm("mov.b64 {%0, %1}, %2;" : "=r"(lo), "=r"(hi) : "l"(v));
    return make_float2(__uint_as_float(lo), __uint_as_float(hi));
}

// ------------------------------- SGEMM -------------------------------------
// C[M,N] = alpha * A[M,K] @ (TRANSB ? B[N,K]^T : B[K,N])
// Epilogue (non-SPLITK): v*=rowscale; aux=v (raw); v = diagc*I - v; +bias;
// +resid; relu.  Batched over gridDim.z = nb*nsplit; z -> (b=z/8, h=z%8)
// strides.  SPLITK writes deterministic per-split partials.
template<int BM, bool TRANSB, bool SPLITK>
__global__ __launch_bounds__(256) void sgemm(
    const float* __restrict__ A, const float* __restrict__ B, float* __restrict__ C,
    int M, int N, int K, int lda, int ldb, int ldc,
    long long sAb, long long sAh, long long sBb, long long sBh,
    long long sCb, long long sCh,
    const float* __restrict__ bias, const float* __restrict__ resid, int ldr,
    float alpha, int relu, int nsplit, int Kc, long long sSp,
    const float* __restrict__ rsA, int rsStride,
    float* __restrict__ aux, float diagc)
{
    constexpr int NI = BM / 16;
    int zAll = blockIdx.z;
    int zb = zAll / nsplit;
    int sp = zAll - zb * nsplit;
    int bb = zb >> 3, hh = zb & 7;
    const float* Ap = A + bb*sAb + hh*sAh;
    const float* Bp = B + bb*sBb + hh*sBh;
    float*       Cp = C + bb*sCb + hh*sCh + (SPLITK ? (long long)sp * sSp : 0LL);
    float*       Xp = aux ? aux + bb*sCb + hh*sCh : (float*)0;
    const float* rsp = rsA ? rsA + (long long)zb * rsStride : (const float*)0;

    int bm0 = blockIdx.y * BM;
    int bn0 = blockIdx.x * 128;
    int k0   = SPLITK ? sp * Kc : 0;
    int kEnd = SPLITK ? min(K, k0 + Kc) : K;

    __shared__ __align__(16) float As[8][128];
    __shared__ __align__(16) float Bs[8][128];

    int tid = threadIdx.x;
    int tx = tid & 15, ty = tid >> 4;
    unsigned long long acc[NI][4];
    #pragma unroll
    for (int i = 0; i < NI; i++)
        #pragma unroll
        for (int j = 0; j < 4; j++) acc[i][j] = 0ULL;

    int arow = bm0 + (tid >> 1);
    int akq  = (tid & 1) * 4;

    for (int kk = k0; kk < kEnd; kk += 8) {
        // ---- load A tile (BM rows x 8 k), transposed into As[k][m]
        if (BM == 128 || tid < 128) {
            float4 av = make_float4(0.f,0.f,0.f,0.f);
            if (arow < M) av = *(const float4*)(Ap + (long long)arow*lda + kk + akq);
            As[akq+0][tid>>1] = av.x;
            As[akq+1][tid>>1] = av.y;
            As[akq+2][tid>>1] = av.z;
            As[akq+3][tid>>1] = av.w;
        }
        // ---- load B tile (8 k x 128 n)
        if (TRANSB) {
            int n = bn0 + (tid >> 1);
            float4 bv = make_float4(0.f,0.f,0.f,0.f);
            if (n < N) bv = *(const float4*)(Bp + (long long)n*ldb + kk + akq);
            Bs[akq+0][tid>>1] = bv.x;
            Bs[akq+1][tid>>1] = bv.y;
            Bs[akq+2][tid>>1] = bv.z;
            Bs[akq+3][tid>>1] = bv.w;
        } else {
            int bk = tid >> 5;
            int bn = (tid & 31) * 4;
            int gc = bn0 + bn;
            const float* p = Bp + (long long)(kk + bk)*ldb + gc;
            float4 bv;
            if (gc + 3 < N) bv = *(const float4*)p;
            else {
                bv.x = (gc+0 < N) ? p[0] : 0.f;
                bv.y = (gc+1 < N) ? p[1] : 0.f;
                bv.z = (gc+2 < N) ? p[2] : 0.f;
                bv.w = (gc+3 < N) ? p[3] : 0.f;
            }
            *(float4*)&Bs[bk][bn] = bv;
        }
        __syncthreads();
        #pragma unroll
        for (int k = 0; k < 8; k++) {
            float ra[NI];
            *(float4*)&ra[0] = *(const float4*)&As[k][ty*4];
            if (BM == 128)
                *(float4*)&ra[4] = *(const float4*)&As[k][64 + ty*4];
            ulonglong2 bq0 = *(const ulonglong2*)&Bs[k][tx*4];
            ulonglong2 bq1 = *(const ulonglong2*)&Bs[k][64 + tx*4];
            unsigned long long rb0 = bq0.x, rb1 = bq0.y, rb2 = bq1.x, rb3 = bq1.y;
            #pragma unroll
            for (int i = 0; i < NI; i++) {
                unsigned long long aa = pack2_dup(ra[i]);
                ffma2(acc[i][0], aa, rb0);
                ffma2(acc[i][1], aa, rb1);
                ffma2(acc[i][2], aa, rb2);
                ffma2(acc[i][3], aa, rb3);
            }
        }
        __syncthreads();
    }

    #pragma unroll
    for (int i = 0; i < NI; i++) {
        int r = bm0 + ((i < 4) ? (ty*4 + i) : (64 + ty*4 + i - 4));
        if (r >= M) continue;
        float rsv = rsp ? rsp[r] : 1.f;
        #pragma unroll
        for (int jp = 0; jp < 4; jp++) {
            float2 pv = unpack2(acc[i][jp]);
            int cbase = bn0 + ((jp < 2) ? (tx*4 + jp*2) : (64 + tx*4 + (jp-2)*2));
            float vv[2] = {pv.x, pv.y};
            #pragma unroll
            for (int e = 0; e < 2; e++) {
                int c = cbase + e;
                if (c >= N) continue;
                float v = vv[e] * alpha;
                long long off = (long long)r*ldc + c;
                if (SPLITK) {
                    if (rsp) v *= rsv;
                    Cp[off] = v;
                } else {
                    if (rsp)  v *= rsv;
                    if (Xp)   Xp[off] = v;
                    if (diagc != 0.f) v = (r == c ? diagc : 0.f) - v;
                    if (bias)  v += bias[c];
                    if (resid) v += resid[(long long)r*ldr + c];
                    if (relu)  v = fmaxf(v, 0.f);
                    Cp[off] = v;
                }
            }
        }
    }
}

// ------------------------------ helpers ------------------------------------
__global__ void reduce_split_kernel(const float* __restrict__ Wp, float* __restrict__ W,
                                    long long stride)
{
    long long idx = (long long)blockIdx.x * blockDim.x + threadIdx.x;
    float s = 0.f;
    for (int k = 0; k < 8; k++) s += Wp[(long long)k*stride + idx];
    W[idx] = s;
}

__global__ void ln_kernel(const float* __restrict__ X, float* __restrict__ Y,
                          const float* __restrict__ g, const float* __restrict__ b)
{
    long long r = blockIdx.x;
    int tid = threadIdx.x;   // 128
    float4 v = ((const float4*)(X + r*DMODEL))[tid];
    float s = v.x+v.y+v.z+v.w;
    float q = v.x*v.x + v.y*v.y + v.z*v.z + v.w*v.w;
    #pragma unroll
    for (int o = 16; o; o >>= 1) {
        s += __shfl_xor_sync(0xffffffffu, s, o);
        q += __shfl_xor_sync(0xffffffffu, q, o);
    }
    __shared__ float ss[4], qq[4];
    if ((tid & 31) == 0) { ss[tid>>5] = s; qq[tid>>5] = q; }
    __syncthreads();
    s = ss[0]+ss[1]+ss[2]+ss[3];
    q = qq[0]+qq[1]+qq[2]+qq[3];
    float mu = s * (1.f/DMODEL);
    float var = q * (1.f/DMODEL) - mu*mu;
    float rs = rsqrtf(var + 1e-5f);
    float4 gv = ((const float4*)g)[tid];
    float4 bv = ((const float4*)b)[tid];
    float4 o;
    o.x = (v.x-mu)*rs*gv.x + bv.x;
    o.y = (v.y-mu)*rs*gv.y + bv.y;
    o.z = (v.z-mu)*rs*gv.z + bv.z;
    o.w = (v.w-mu)*rs*gv.w + bv.w;
    ((float4*)(Y + r*DMODEL))[tid] = o;
}

__global__ void cls_copy_kernel(float* __restrict__ X, const float* __restrict__ cls)
{
    int c = threadIdx.x;  // 512
    X[c] = cls[c];
    X[(long long)NF*DMODEL + c] = cls[c];
}

__global__ void landmark_kernel(const float* __restrict__ QKV, float* __restrict__ out, int off)
{
    int j = blockIdx.x;          // landmark 0..255
    int z = blockIdx.y;          // bh 0..15
    int d = threadIdx.x;         // 0..63
    int b = z >> 3, h = z & 7;
    const float* base = QKV + ((long long)b*NF + (long long)j*32)*QKVW + off + h*DH + d;
    float s = 0.f;
    #pragma unroll
    for (int t = 0; t < 32; t++) s += base[(long long)t*QKVW];
    out[((long long)z*NLAND + j)*DH + d] = s * (1.f/32.f);
}

// full 3-pass softmax (used for S2, which must be fully normalized for pinv)
__global__ void softmax_kernel(float* __restrict__ X, int cols)
{
    long long row = blockIdx.x;
    float* p = X + row * cols;
    int tid = threadIdx.x;   // 256
    __shared__ float sred[8];
    __shared__ float sval;
    float m = -1e30f;
    for (int c = tid; c < cols; c += 256) m = fmaxf(m, p[c]);
    #pragma unroll
    for (int o = 16; o; o >>= 1) m = fmaxf(m, __shfl_xor_sync(0xffffffffu, m, o));
    if ((tid & 31) == 0) sred[tid>>5] = m;
    __syncthreads();
    if (tid == 0) {
        float mm = sred[0];
        for (int i = 1; i < 8; i++) mm = fmaxf(mm, sred[i]);
        sval = mm;
    }
    __syncthreads();
    m = sval;
    __syncthreads();
    float s = 0.f;
    for (int c = tid; c < cols; c += 256) {
        float e = __expf(p[c] - m);
        p[c] = e;
        s += e;
    }
    #pragma unroll
    for (int o = 16; o; o >>= 1) s += __shfl_xor_sync(0xffffffffu, s, o);
    if ((tid & 31) == 0) sred[tid>>5] = s;
    __syncthreads();
    if (tid == 0) {
        float t = 0.f;
        for (int i = 0; i < 8; i++) t += sred[i];
        sval = t;
    }
    __syncthreads();
    float inv = 1.f / sval;
    for (int c = tid; c < cols; c += 256) p[c] *= inv;
}

// 2-pass: leaves exp(x-max) in place, stores 1/sum to rs[row]; normalization
// is folded into the consuming GEMM's epilogue row-scale.
__global__ void softmax2_kernel(float* __restrict__ X, int cols, float* __restrict__ rs)
{
    long long row = blockIdx.x;
    float* p = X + row * cols;
    int tid = threadIdx.x;   // 256
    __shared__ float sred[8];
    __shared__ float sval;
    float m = -1e30f;
    for (int c = tid; c < cols; c += 256) m = fmaxf(m, p[c]);
    #pragma unroll
    for (int o = 16; o; o >>= 1) m = fmaxf(m, __shfl_xor_sync(0xffffffffu, m, o));
    if ((tid & 31) == 0) sred[tid>>5] = m;
    __syncthreads();
    if (tid == 0) {
        float mm = sred[0];
        for (int i = 1; i < 8; i++) mm = fmaxf(mm, sred[i]);
        sval = mm;
    }
    __syncthreads();
    m = sval;
    __syncthreads();
    float s = 0.f;
    for (int c = tid; c < cols; c += 256) {
        float e = __expf(p[c] - m);
        p[c] = e;
        s += e;
    }
    #pragma unroll
    for (int o = 16; o; o >>= 1) s += __shfl_xor_sync(0xffffffffu, s, o);
    if ((tid & 31) == 0) sred[tid>>5] = s;
    __syncthreads();
    if (tid == 0) {
        float t = 0.f;
        for (int i = 0; i < 8; i++) t += sred[i];
        rs[row] = 1.f / t;
    }
}

__device__ __forceinline__ void atomicMaxF(float* addr, float v)
{
    atomicMax((int*)addr, __float_as_int(v));   // valid for non-negative floats
}

__global__ void pinv_reduce_kernel(const float* __restrict__ S2, float* __restrict__ scal)
{
    int z = blockIdx.x;
    int tid = threadIdx.x;   // 256
    const float* Mz = S2 + (long long)z * NLAND * NLAND;
    float rs = 0.f, cs = 0.f;
    for (int j = 0; j < NLAND; j++) rs += Mz[(long long)tid*NLAND + j];
    for (int i = 0; i < NLAND; i++) cs += Mz[(long long)i*NLAND + tid];
    __shared__ float sm[256];
    sm[tid] = rs; __syncthreads();
    for (int s = 128; s; s >>= 1) { if (tid < s) sm[tid] = fmaxf(sm[tid], sm[tid+s]); __syncthreads(); }
    if (tid == 0) atomicMaxF(&scal[0], sm[0]);
    __syncthreads();
    sm[tid] = cs; __syncthreads();
    for (int s = 128; s; s >>= 1) { if (tid < s) sm[tid] = fmaxf(sm[tid], sm[tid+s]); __syncthreads(); }
    if (tid == 0) atomicMaxF(&scal[1], sm[0]);
}

__global__ void zinit_kernel(float* __restrict__ Z, const float* __restrict__ S2,
                             const float* __restrict__ scal)
{
    long long idx = (long long)blockIdx.x * blockDim.x + threadIdx.x;
    float rcp = 1.f / (scal[0] * scal[1]);
    long long z = idx >> 16;
    int r = (int)((idx >> 8) & 255);
    int c = (int)(idx & 255);
    Z[idx] = S2[(z << 16) + ((long long)c << 8) + r] * rcp;
}

__global__ void conv_kernel(float* __restrict__ O, const float* __restrict__ QKV,
                            const float* __restrict__ cw)
{
    int t0 = blockIdx.x * 128;
    int h = blockIdx.y;
    int b = blockIdx.z;
    __shared__ float sv[160*64];
    __shared__ float ws[KCONV];
    int tid = threadIdx.x;   // 256
    if (tid < KCONV) ws[tid] = cw[h*KCONV + tid];
    for (int i = tid; i < 160*64; i += 256) {
        int tl = i >> 6, d = i & 63;
        int t = t0 + tl - 16;
        float v = 0.f;
        if (t >= 0 && t < NF)
            v = QKV[((long long)b*NF + t)*QKVW + 2*DMODEL + h*DH + d];
        sv[i] = v;
    }
    __syncthreads();
    float* Op = O + (((long long)(b*NHEADS + h))*NF + t0)*DH;
    for (int i = tid; i < 128*64; i += 256) {
        int tl = i >> 6, d = i & 63;
        float acc = 0.f;
        #pragma unroll
        for (int k = 0; k < KCONV; k++) acc += ws[k] * sv[(tl + k)*64 + d];
        Op[i] += acc;
    }
}

__global__ void merge_kernel(const float* __restrict__ O, float* __restrict__ OC)
{
    long long idx = (long long)blockIdx.x * blockDim.x + threadIdx.x;
    int c = (int)(idx & 511);
    int n = (int)((idx >> 9) & (NF - 1));
    int b = (int)(idx >> 22);
    int h = c >> 6, d = c & 63;
    OC[idx] = O[(((long long)(b*NHEADS + h))*NF + n)*DH + d];
}

__global__ void final_kernel(const float* __restrict__ X, const float* __restrict__ g,
                             const float* __restrict__ bt, const float* __restrict__ w2,
                             const float* __restrict__ b2, float* __restrict__ out)
{
    int b = blockIdx.x;
    int tid = threadIdx.x;  // 128
    const float* x = X + (long long)b*NF*DMODEL;
    float4 v = ((const float4*)x)[tid];
    float s = v.x+v.y+v.z+v.w;
    float q = v.x*v.x + v.y*v.y + v.z*v.z + v.w*v.w;
    #pragma unroll
    for (int o = 16; o; o >>= 1) {
        s += __shfl_xor_sync(0xffffffffu, s, o);
        q += __shfl_xor_sync(0xffffffffu, q, o);
    }
    __shared__ float ss[4], qq[4];
    if ((tid & 31) == 0) { ss[tid>>5] = s; qq[tid>>5] = q; }
    __syncthreads();
    s = ss[0]+ss[1]+ss[2]+ss[3];
    q = qq[0]+qq[1]+qq[2]+qq[3];
    float mu = s * (1.f/DMODEL);
    float var = q * (1.f/DMODEL) - mu*mu;
    float rs = rsqrtf(var + 1e-5f);
    __shared__ float xn[DMODEL];
    float4 gv = ((const float4*)g)[tid];
    float4 bv = ((const float4*)bt)[tid];
    xn[tid*4+0] = (v.x-mu)*rs*gv.x + bv.x;
    xn[tid*4+1] = (v.y-mu)*rs*gv.y + bv.y;
    xn[tid*4+2] = (v.z-mu)*rs*gv.z + bv.z;
    xn[tid*4+3] = (v.w-mu)*rs*gv.w + bv.w;
    __syncthreads();
    float s0 = 0.f, s1 = 0.f;
    for (int d = tid; d < DMODEL; d += 128) {
        float xv = xn[d];
        s0 += xv * w2[d*2+0];
        s1 += xv * w2[d*2+1];
    }
    __shared__ float r0[128], r1[128];
    r0[tid] = s0; r1[tid] = s1;
    __syncthreads();
    for (int st = 64; st; st >>= 1) {
        if (tid < st) { r0[tid] += r0[tid+st]; r1[tid] += r1[tid+st]; }
        __syncthreads();
    }
    if (tid == 0) {
        out[b*2+0] = r0[0] + b2[0];
        out[b*2+1] = r1[0] + b2[1];
    }
}

// ------------------------------ host side ----------------------------------
struct Bufs {
    float *X,*XLN,*QKV,*QL,*KL,*S1,*S3,*S2,*T,*U,*Rb,*Z,*Z2,*W,*Wp,*O,*OC,*RS1,*RS3,*scal;
};

static Bufs init_bufs()
{
    Bufs b;
    cudaGetSymbolAddress((void**)&b.X,   g_X);
    cudaGetSymbolAddress((void**)&b.XLN, g_XLN);
    cudaGetSymbolAddress((void**)&b.QKV, g_QKV);
    cudaGetSymbolAddress((void**)&b.QL,  g_QL);
    cudaGetSymbolAddress((void**)&b.KL,  g_KL);
    cudaGetSymbolAddress((void**)&b.S1,  g_S1);
    cudaGetSymbolAddress((void**)&b.S3,  g_S3);
    cudaGetSymbolAddress((void**)&b.S2,  g_S2);
    cudaGetSymbolAddress((void**)&b.T,   g_T);
    cudaGetSymbolAddress((void**)&b.U,   g_U);
    cudaGetSymbolAddress((void**)&b.Rb,  g_R);
    cudaGetSymbolAddress((void**)&b.Z,   g_Z);
    cudaGetSymbolAddress((void**)&b.Z2,  g_Z2);
    cudaGetSymbolAddress((void**)&b.W,   g_W);
    cudaGetSymbolAddress((void**)&b.Wp,  g_Wp);
    cudaGetSymbolAddress((void**)&b.O,   g_O);
    cudaGetSymbolAddress((void**)&b.OC,  g_OC);
    cudaGetSymbolAddress((void**)&b.RS1, g_RS1);
    cudaGetSymbolAddress((void**)&b.RS3, g_RS3);
    cudaGetSymbolAddress((void**)&b.scal,g_scal);
    return b;
}

static inline void gemm_call(int bm, const float* A, const float* B, float* C,
    int M, int N, int K, int lda, int ldb, int ldc, int nb,
    long long sAb, long long sAh, long long sBb, long long sBh,
    long long sCb, long long sCh,
    const float* bias, const float* resid, int ldr,
    float alpha, int relu, bool transb,
    int nsplit = 1, int Kc = 0, long long sSp = 0,
    const float* rs = nullptr, int rsStride = 0,
    float* aux = nullptr, float diagc = 0.f)
{
    dim3 gr((N + 127)/128, (M + bm - 1)/bm, nb * nsplit);
    if (bm == 128) {
        if (nsplit > 1) {
            if (transb) sgemm<128,true ,true ><<<gr,256>>>(A,B,C,M,N,K,lda,ldb,ldc,sAb,sAh,sBb,sBh,sCb,sCh,bias,resid,ldr,alpha,relu,nsplit,Kc,sSp,rs,rsStride,aux,diagc);
            else        sgemm<128,false,true ><<<gr,256>>>(A,B,C,M,N,K,lda,ldb,ldc,sAb,sAh,sBb,sBh,sCb,sCh,bias,resid,ldr,alpha,relu,nsplit,Kc,sSp,rs,rsStride,aux,diagc);
        } else {
            if (transb) sgemm<128,true ,false><<<gr,256>>>(A,B,C,M,N,K,lda,ldb,ldc,sAb,sAh,sBb,sBh,sCb,sCh,bias,resid,ldr,alpha,relu,1,0,0,rs,rsStride,aux,diagc);
            else        sgemm<128,false,false><<<gr,256>>>(A,B,C,M,N,K,lda,ldb,ldc,sAb,sAh,sBb,sBh,sCb,sCh,bias,resid,ldr,alpha,relu,1,0,0,rs,rsStride,aux,diagc);
        }
    } else {
        if (nsplit > 1) {
            if (transb) sgemm<64,true ,true ><<<gr,256>>>(A,B,C,M,N,K,lda,ldb,ldc,sAb,sAh,sBb,sBh,sCb,sCh,bias,resid,ldr,alpha,relu,nsplit,Kc,sSp,rs,rsStride,aux,diagc);
            else        sgemm<64,false,true ><<<gr,256>>>(A,B,C,M,N,K,lda,ldb,ldc,sAb,sAh,sBb,sBh,sCb,sCh,bias,resid,ldr,alpha,relu,nsplit,Kc,sSp,rs,rsStride,aux,diagc);
        } else {
            if (transb) sgemm<64,true ,false><<<gr,256>>>(A,B,C,M,N,K,lda,ldb,ldc,sAb,sAh,sBb,sBh,sCb,sCh,bias,resid,ldr,alpha,relu,1,0,0,rs,rsStride,aux,diagc);
            else        sgemm<64,false,false><<<gr,256>>>(A,B,C,M,N,K,lda,ldb,ldc,sAb,sAh,sBb,sBh,sCb,sCh,bias,resid,ldr,alpha,relu,1,0,0,rs,rsStride,aux,diagc);
        }
    }
}

static void run_layer(const Bufs& bu, int L, void* const* d_in)
{
    const float* lng  = (const float*)d_in[4] + (size_t)L*DMODEL;
    const float* lnb  = (const float*)d_in[5] + (size_t)L*DMODEL;
    const float* wqkv = (const float*)d_in[6] + (size_t)L*DMODEL*QKVW;
    const float* wout = (const float*)d_in[7] + (size_t)L*DMODEL*DMODEL;
    const float* bout = (const float*)d_in[8] + (size_t)L*DMODEL;
    const float* cw   = (const float*)d_in[9] + (size_t)L*NHEADS*KCONV;

    const long long sQKVb = (long long)NF*QKVW;
    const long long sLh = (long long)NLAND*DH;
    const long long sLb = (long long)NHEADS*sLh;
    const long long sS1h = (long long)NF*NLAND;
    const long long sS1b = (long long)NHEADS*sS1h;
    const long long sS3h = (long long)NLAND*NF;
    const long long sS3b = (long long)NHEADS*sS3h;
    const long long sm = (long long)NLAND*NLAND;
    const long long smb = (long long)NHEADS*sm;
    const long long sOh = (long long)NF*DH;
    const long long sOb = (long long)NHEADS*sOh;

    // x_ln = LN(x)
    ln_kernel<<<NROWS,128>>>(bu.X, bu.XLN, lng, lnb);
    // QKV = x_ln @ w_qkv
    gemm_call(128, bu.XLN, wqkv, bu.QKV, NROWS, QKVW, DMODEL, DMODEL, QKVW, QKVW, 1,
              0,0,0,0,0,0, nullptr,nullptr,0, 1.f,0,false);
    // landmarks
    landmark_kernel<<<dim3(NLAND,NBH),64>>>(bu.QKV, bu.QL, 0);
    landmark_kernel<<<dim3(NLAND,NBH),64>>>(bu.QKV, bu.KL, DMODEL);
    // sim1 = (q*scale) @ k_l^T
    gemm_call(128, bu.QKV, bu.KL, bu.S1, NF, NLAND, DH, QKVW, DH, NLAND, NBH,
              sQKVb, DH, sLb, sLh, sS1b, sS1h, nullptr,nullptr,0, 0.125f,0,true);
    // sim2 = (q_l*scale) @ k_l^T
    gemm_call(64, bu.QL, bu.KL, bu.S2, NLAND, NLAND, DH, DH, DH, NLAND, NBH,
              sLb, sLh, sLb, sLh, smb, sm, nullptr,nullptr,0, 0.125f,0,true);
    // sim3 = (q_l*scale) @ k^T
    gemm_call(64, bu.QL, bu.QKV + DMODEL, bu.S3, NLAND, NF, DH, DH, QKVW, NF, NBH,
              sLb, sLh, sQKVb, DH, sS3b, sS3h, nullptr,nullptr,0, 0.125f,0,true);
    // softmaxes: S1/S3 keep exp + rowscale; S2 fully normalized
    softmax2_kernel<<<NBH*NF,256>>>(bu.S1, NLAND, bu.RS1);
    softmax_kernel<<<NBH*NLAND,256>>>(bu.S2, NLAND);
    softmax2_kernel<<<NBH*NLAND,256>>>(bu.S3, NF, bu.RS3);
    // Moore-Penrose pinv (Newton-Schulz with fused diag epilogues)
    cudaMemsetAsync(bu.scal, 0, 2*sizeof(float));
    pinv_reduce_kernel<<<NBH,256>>>(bu.S2, bu.scal);
    zinit_kernel<<<(NBH*NLAND*NLAND)/256,256>>>(bu.Z, bu.S2, bu.scal);
    float* za = bu.Z;
    float* zb = bu.Z2;
    for (int it = 0; it < 6; it++) {
        // T = S2@Z (aux raw) ; U = 7I - T
        gemm_call(64, bu.S2, za, bu.U, NLAND,NLAND,NLAND, NLAND,NLAND,NLAND, NBH,
                  smb,sm, smb,sm, smb,sm, nullptr,nullptr,0, 1.f,0,false,
                  1,0,0, nullptr,0, bu.T, 7.f);
        // R' = 15I - T@U
        gemm_call(64, bu.T, bu.U, bu.Rb, NLAND,NLAND,NLAND, NLAND,NLAND,NLAND, NBH,
                  smb,sm, smb,sm, smb,sm, nullptr,nullptr,0, 1.f,0,false,
                  1,0,0, nullptr,0, nullptr, 15.f);
        // U2 = 13I - T@R'
        gemm_call(64, bu.T, bu.Rb, bu.U, NLAND,NLAND,NLAND, NLAND,NLAND,NLAND, NBH,
                  smb,sm, smb,sm, smb,sm, nullptr,nullptr,0, 1.f,0,false,
                  1,0,0, nullptr,0, nullptr, 13.f);
        // Z' = 0.25 * Z @ U2
        gemm_call(64, za, bu.U, zb, NLAND,NLAND,NLAND, NLAND,NLAND,NLAND, NBH,
                  smb,sm, smb,sm, smb,sm, nullptr,nullptr,0, 0.25f,0,false);
        float* tp = za; za = zb; zb = tp;
    }
    // W = attn3 @ v (rowscale = 1/sum3; deterministic split-K + reduce)
    gemm_call(64, bu.S3, bu.QKV + 2*DMODEL, bu.Wp, NLAND, DH, NF, NF, QKVW, DH, NBH,
              sS3b, sS3h, sQKVb, DH, sLb, sLh, nullptr,nullptr,0, 1.f,0,false,
              8, 1024, (long long)NBH*NLAND*DH, bu.RS3, NLAND);
    reduce_split_kernel<<<(NBH*NLAND*DH)/256,256>>>(bu.Wp, bu.W, (long long)NBH*NLAND*DH);
    // P = attn1 @ Z (rowscale = 1/sum1); reuse S3 buffer
    gemm_call(128, bu.S1, za, bu.S3, NF, NLAND, NLAND, NLAND, NLAND, NLAND, NBH,
              sS1b, sS1h, smb, sm, sS1b, sS1h, nullptr,nullptr,0, 1.f,0,false,
              1,0,0, bu.RS1, NF);
    // O = P @ W
    gemm_call(128, bu.S3, bu.W, bu.O, NF, DH, NLAND, NLAND, DH, DH, NBH,
              sS1b, sS1h, sLb, sLh, sOb, sOh, nullptr,nullptr,0, 1.f,0,false);
    // O += depthwise conv of V
    conv_kernel<<<dim3(NF/128, NHEADS, NBATCH),256>>>(bu.O, bu.QKV, cw);
    // concat heads
    merge_kernel<<<((long long)NBATCH*NF*DMODEL)/256,256>>>(bu.O, bu.OC);
    // x = x + (OC @ w_out + b_out)
    gemm_call(128, bu.OC, wout, bu.X, NROWS, DMODEL, DMODEL, DMODEL, DMODEL, DMODEL, 1,
              0,0,0,0,0,0, bout, bu.X, DMODEL, 1.f,0,false);
}

extern "C" void kernel_launch(void* const* d_in, const int* in_sizes, int n_in,
                              void* d_out, int out_size)
{
    static Bufs bu = init_bufs();
    const float* h    = (const float*)d_in[0];
    const float* w1   = (const float*)d_in[1];
    const float* b1   = (const float*)d_in[2];
    const float* cls  = (const float*)d_in[3];
    const float* fng  = (const float*)d_in[10];
    const float* fnb  = (const float*)d_in[11];
    const float* w2   = (const float*)d_in[12];
    const float* b2   = (const float*)d_in[13];

    // x = relu(h @ w1 + b1) rows 1..8191 per batch; batched via hh stride
    gemm_call(128, h, w1, bu.X + DMODEL, 8191, DMODEL, 1024, 1024, DMODEL, DMODEL, 2,
              0, (long long)8191*1024, 0, 0, 0, (long long)NF*DMODEL,
              b1, nullptr, 0, 1.f, 1, false);
    cls_copy_kernel<<<1,512>>>(bu.X, cls);

    run_layer(bu, 0, d_in);
    run_layer(bu, 1, d_in);

    final_kernel<<<NBATCH,128>>>(bu.X, fng, fnb, w2, b2, (float*)d_out);
}

// round 7
// speedup vs baseline: 1.2519x; 1.2182x over previous
#include <cuda_runtime.h>

#define NF 8192
#define DMODEL 512
#define NHEADS 8
#define DH 64
#define NLAND 256
#define NBATCH 2
#define NBH 16
#define QKVW 1536
#define NROWS (NBATCH*NF)
#define KCONV 33

// ------------------------- scratch (device globals; no allocs allowed) -----
__device__ __align__(16) float g_X  [(size_t)NBATCH*NF*DMODEL];
__device__ __align__(16) float g_XLN[(size_t)NBATCH*NF*DMODEL];
__device__ __align__(16) float g_QKV[(size_t)NBATCH*NF*QKVW];
__device__ __align__(16) float g_QL [(size_t)NBH*NLAND*DH];
__device__ __align__(16) float g_KL [(size_t)NBH*NLAND*DH];
__device__ __align__(16) float g_S1 [(size_t)NBH*NF*NLAND];
__device__ __align__(16) float g_S3 [(size_t)NBH*NF*NLAND];
__device__ __align__(16) float g_S2 [(size_t)NBH*NLAND*NLAND];
__device__ __align__(16) float g_T  [(size_t)NBH*NLAND*NLAND];
__device__ __align__(16) float g_U  [(size_t)NBH*NLAND*NLAND];
__device__ __align__(16) float g_R  [(size_t)NBH*NLAND*NLAND];
__device__ __align__(16) float g_Z  [(size_t)NBH*NLAND*NLAND];
__device__ __align__(16) float g_Z2 [(size_t)NBH*NLAND*NLAND];
__device__ __align__(16) float g_W  [(size_t)NBH*NLAND*DH];
__device__ __align__(16) float g_Wp [(size_t)8*NBH*NLAND*DH];
__device__ __align__(16) float g_O  [(size_t)NBH*NF*DH];
__device__ __align__(16) float g_OC [(size_t)NBATCH*NF*DMODEL];
__device__ __align__(16) float g_RS1[(size_t)NBH*NF];
__device__ __align__(16) float g_RS3[(size_t)NBH*NLAND];
__device__ float g_scal[2];

// ------------------------- f32x2 packed helpers ----------------------------
__device__ __forceinline__ unsigned long long pack2_dup(float x)
{
    unsigned long long r;
    unsigned int u = __float_as_uint(x);
    asm("mov.b64 %0, {%1, %1};" : "=l"(r) : "r"(u));
    return r;
}
__device__ __forceinline__ void ffma2(unsigned long long& d,
                                      unsigned long long a, unsigned long long b)
{
    asm("fma.rn.f32x2 %0, %1, %2, %0;" : "+l"(d) : "l"(a), "l"(b));
}
__device__ __forceinline__ float2 unpack2(unsigned long long v)
{
    unsigned int lo, hi;
    asm("mov.b64 {%0, %1}, %2;" : "=r"(lo), "=r"(hi) : "l"(v));
    return make_float2(__uint_as_float(lo), __uint_as_float(hi));
}

// ------------------------------- SGEMM -------------------------------------
// C[M,N] = alpha * A[M,K] @ (TRANSB ? B[N,K]^T : B[K,N])
// Double-buffered smem pipeline: prefetch tile t+1 into registers while
// computing tile t; single __syncthreads per K-tile.
// Epilogue (non-SPLITK): v*=rowscale; aux=v (raw); v = diagc*I - v; +bias;
// +resid; relu.  Batched over gridDim.z = nb*nsplit; z -> (b=z/8, h=z%8).
// SPLITK writes deterministic per-split partials. All K are multiples of 8.
template<int BM, bool TRANSB, bool SPLITK>
__global__ __launch_bounds__(256) void sgemm(
    const float* __restrict__ A, const float* __restrict__ B, float* __restrict__ C,
    int M, int N, int K, int lda, int ldb, int ldc,
    long long sAb, long long sAh, long long sBb, long long sBh,
    long long sCb, long long sCh,
    const float* __restrict__ bias, const float* __restrict__ resid, int ldr,
    float alpha, int relu, int nsplit, int Kc, long long sSp,
    const float* __restrict__ rsA, int rsStride,
    float* __restrict__ aux, float diagc)
{
    constexpr int NI = BM / 16;
    int zAll = blockIdx.z;
    int zb = zAll / nsplit;
    int sp = zAll - zb * nsplit;
    int bb = zb >> 3, hh = zb & 7;
    const float* Ap = A + bb*sAb + hh*sAh;
    const float* Bp = B + bb*sBb + hh*sBh;
    float*       Cp = C + bb*sCb + hh*sCh + (SPLITK ? (long long)sp * sSp : 0LL);
    float*       Xp = aux ? aux + bb*sCb + hh*sCh : (float*)0;
    const float* rsp = rsA ? rsA + (long long)zb * rsStride : (const float*)0;

    int bm0 = blockIdx.y * BM;
    int bn0 = blockIdx.x * 128;
    int k0   = SPLITK ? sp * Kc : 0;
    int kEnd = SPLITK ? min(K, k0 + Kc) : K;

    __shared__ __align__(16) float As[2][8][128];
    __shared__ __align__(16) float Bs[2][8][128];

    int tid = threadIdx.x;
    int tx = tid & 15, ty = tid >> 4;
    unsigned long long acc[NI][4];
    #pragma unroll
    for (int i = 0; i < NI; i++)
        #pragma unroll
        for (int j = 0; j < 4; j++) acc[i][j] = 0ULL;

    int arow = bm0 + (tid >> 1);
    int akq  = (tid & 1) * 4;
    int bk = tid >> 5;            // NN B-load indices
    int bn = (tid & 31) * 4;
    int gc = bn0 + bn;
    int nB = bn0 + (tid >> 1);    // TRANSB B-load row

    float4 avS, bvS;

    auto loadTile = [&](int kk) {
        avS = make_float4(0.f,0.f,0.f,0.f);
        if ((BM == 128 || tid < 128) && arow < M)
            avS = *(const float4*)(Ap + (long long)arow*lda + kk + akq);
        if (TRANSB) {
            bvS = make_float4(0.f,0.f,0.f,0.f);
            if (nB < N) bvS = *(const float4*)(Bp + (long long)nB*ldb + kk + akq);
        } else {
            const float* p = Bp + (long long)(kk + bk)*ldb + gc;
            if (gc + 3 < N) bvS = *(const float4*)p;
            else {
                bvS.x = (gc+0 < N) ? p[0] : 0.f;
                bvS.y = (gc+1 < N) ? p[1] : 0.f;
                bvS.z = (gc+2 < N) ? p[2] : 0.f;
                bvS.w = (gc+3 < N) ? p[3] : 0.f;
            }
        }
    };
    auto storeTile = [&](int pb) {
        if (BM == 128 || tid < 128) {
            As[pb][akq+0][tid>>1] = avS.x;
            As[pb][akq+1][tid>>1] = avS.y;
            As[pb][akq+2][tid>>1] = avS.z;
            As[pb][akq+3][tid>>1] = avS.w;
        }
        if (TRANSB) {
            Bs[pb][akq+0][tid>>1] = bvS.x;
            Bs[pb][akq+1][tid>>1] = bvS.y;
            Bs[pb][akq+2][tid>>1] = bvS.z;
            Bs[pb][akq+3][tid>>1] = bvS.w;
        } else {
            *(float4*)&Bs[pb][bk][bn] = bvS;
        }
    };

    int nt = (kEnd - k0) >> 3;
    loadTile(k0);
    storeTile(0);
    __syncthreads();

    for (int t = 0; t < nt; t++) {
        if (t + 1 < nt) loadTile(k0 + ((t + 1) << 3));
        int pb = t & 1;
        #pragma unroll
        for (int k = 0; k < 8; k++) {
            float ra[NI];
            *(float4*)&ra[0] = *(const float4*)&As[pb][k][ty*4];
            if (BM == 128)
                *(float4*)&ra[4] = *(const float4*)&As[pb][k][64 + ty*4];
            ulonglong2 bq0 = *(const ulonglong2*)&Bs[pb][k][tx*4];
            ulonglong2 bq1 = *(const ulonglong2*)&Bs[pb][k][64 + tx*4];
            unsigned long long rb0 = bq0.x, rb1 = bq0.y, rb2 = bq1.x, rb3 = bq1.y;
            #pragma unroll
            for (int i = 0; i < NI; i++) {
                unsigned long long aa = pack2_dup(ra[i]);
                ffma2(acc[i][0], aa, rb0);
                ffma2(acc[i][1], aa, rb1);
                ffma2(acc[i][2], aa, rb2);
                ffma2(acc[i][3], aa, rb3);
            }
        }
        if (t + 1 < nt) {
            storeTile((t + 1) & 1);
            __syncthreads();
        }
    }

    #pragma unroll
    for (int i = 0; i < NI; i++) {
        int r = bm0 + ((i < 4) ? (ty*4 + i) : (64 + ty*4 + i - 4));
        if (r >= M) continue;
        float rsv = rsp ? rsp[r] : 1.f;
        #pragma unroll
        for (int jp = 0; jp < 4; jp++) {
            float2 pv = unpack2(acc[i][jp]);
            int cbase = bn0 + ((jp < 2) ? (tx*4 + jp*2) : (64 + tx*4 + (jp-2)*2));
            float vv[2] = {pv.x, pv.y};
            #pragma unroll
            for (int e = 0; e < 2; e++) {
                int c = cbase + e;
                if (c >= N) continue;
                float v = vv[e] * alpha;
                long long off = (long long)r*ldc + c;
                if (SPLITK) {
                    if (rsp) v *= rsv;
                    Cp[off] = v;
                } else {
                    if (rsp)  v *= rsv;
                    if (Xp)   Xp[off] = v;
                    if (diagc != 0.f) v = (r == c ? diagc : 0.f) - v;
                    if (bias)  v += bias[c];
                    if (resid) v += resid[(long long)r*ldr + c];
                    if (relu)  v = fmaxf(v, 0.f);
                    Cp[off] = v;
                }
            }
        }
    }
}

// ------------------------------ helpers ------------------------------------
__global__ void reduce_split_kernel(const float* __restrict__ Wp, float* __restrict__ W,
                                    long long stride)
{
    long long idx = (long long)blockIdx.x * blockDim.x + threadIdx.x;
    float s = 0.f;
    for (int k = 0; k < 8; k++) s += Wp[(long long)k*stride + idx];
    W[idx] = s;
}

__global__ void ln_kernel(const float* __restrict__ X, float* __restrict__ Y,
                          const float* __restrict__ g, const float* __restrict__ b)
{
    long long r = blockIdx.x;
    int tid = threadIdx.x;   // 128
    float4 v = ((const float4*)(X + r*DMODEL))[tid];
    float s = v.x+v.y+v.z+v.w;
    float q = v.x*v.x + v.y*v.y + v.z*v.z + v.w*v.w;
    #pragma unroll
    for (int o = 16; o; o >>= 1) {
        s += __shfl_xor_sync(0xffffffffu, s, o);
        q += __shfl_xor_sync(0xffffffffu, q, o);
    }
    __shared__ float ss[4], qq[4];
    if ((tid & 31) == 0) { ss[tid>>5] = s; qq[tid>>5] = q; }
    __syncthreads();
    s = ss[0]+ss[1]+ss[2]+ss[3];
    q = qq[0]+qq[1]+qq[2]+qq[3];
    float mu = s * (1.f/DMODEL);
    float var = q * (1.f/DMODEL) - mu*mu;
    float rs = rsqrtf(var + 1e-5f);
    float4 gv = ((const float4*)g)[tid];
    float4 bv = ((const float4*)b)[tid];
    float4 o;
    o.x = (v.x-mu)*rs*gv.x + bv.x;
    o.y = (v.y-mu)*rs*gv.y + bv.y;
    o.z = (v.z-mu)*rs*gv.z + bv.z;
    o.w = (v.w-mu)*rs*gv.w + bv.w;
    ((float4*)(Y + r*DMODEL))[tid] = o;
}

__global__ void cls_copy_kernel(float* __restrict__ X, const float* __restrict__ cls)
{
    int c = threadIdx.x;  // 512
    X[c] = cls[c];
    X[(long long)NF*DMODEL + c] = cls[c];
}

__global__ void landmark_kernel(const float* __restrict__ QKV, float* __restrict__ out, int off)
{
    int j = blockIdx.x;          // landmark 0..255
    int z = blockIdx.y;          // bh 0..15
    int d = threadIdx.x;         // 0..63
    int b = z >> 3, h = z & 7;
    const float* base = QKV + ((long long)b*NF + (long long)j*32)*QKVW + off + h*DH + d;
    float s = 0.f;
    #pragma unroll
    for (int t = 0; t < 32; t++) s += base[(long long)t*QKVW];
    out[((long long)z*NLAND + j)*DH + d] = s * (1.f/32.f);
}

// full 3-pass softmax (used for S2, which must be fully normalized for pinv)
__global__ void softmax_kernel(float* __restrict__ X, int cols)
{
    long long row = blockIdx.x;
    float* p = X + row * cols;
    int tid = threadIdx.x;   // 256
    __shared__ float sred[8];
    __shared__ float sval;
    float m = -1e30f;
    for (int c = tid; c < cols; c += 256) m = fmaxf(m, p[c]);
    #pragma unroll
    for (int o = 16; o; o >>= 1) m = fmaxf(m, __shfl_xor_sync(0xffffffffu, m, o));
    if ((tid & 31) == 0) sred[tid>>5] = m;
    __syncthreads();
    if (tid == 0) {
        float mm = sred[0];
        for (int i = 1; i < 8; i++) mm = fmaxf(mm, sred[i]);
        sval = mm;
    }
    __syncthreads();
    m = sval;
    __syncthreads();
    float s = 0.f;
    for (int c = tid; c < cols; c += 256) {
        float e = __expf(p[c] - m);
        p[c] = e;
        s += e;
    }
    #pragma unroll
    for (int o = 16; o; o >>= 1) s += __shfl_xor_sync(0xffffffffu, s, o);
    if ((tid & 31) == 0) sred[tid>>5] = s;
    __syncthreads();
    if (tid == 0) {
        float t = 0.f;
        for (int i = 0; i < 8; i++) t += sred[i];
        sval = t;
    }
    __syncthreads();
    float inv = 1.f / sval;
    for (int c = tid; c < cols; c += 256) p[c] *= inv;
}

// 2-pass: leaves exp(x-max) in place, stores 1/sum to rs[row]; normalization
// is folded into the consuming GEMM's epilogue row-scale.
__global__ void softmax2_kernel(float* __restrict__ X, int cols, float* __restrict__ rs)
{
    long long row = blockIdx.x;
    float* p = X + row * cols;
    int tid = threadIdx.x;   // 256
    __shared__ float sred[8];
    __shared__ float sval;
    float m = -1e30f;
    for (int c = tid; c < cols; c += 256) m = fmaxf(m, p[c]);
    #pragma unroll
    for (int o = 16; o; o >>= 1) m = fmaxf(m, __shfl_xor_sync(0xffffffffu, m, o));
    if ((tid & 31) == 0) sred[tid>>5] = m;
    __syncthreads();
    if (tid == 0) {
        float mm = sred[0];
        for (int i = 1; i < 8; i++) mm = fmaxf(mm, sred[i]);
        sval = mm;
    }
    __syncthreads();
    m = sval;
    __syncthreads();
    float s = 0.f;
    for (int c = tid; c < cols; c += 256) {
        float e = __expf(p[c] - m);
        p[c] = e;
        s += e;
    }
    #pragma unroll
    for (int o = 16; o; o >>= 1) s += __shfl_xor_sync(0xffffffffu, s, o);
    if ((tid & 31) == 0) sred[tid>>5] = s;
    __syncthreads();
    if (tid == 0) {
        float t = 0.f;
        for (int i = 0; i < 8; i++) t += sred[i];
        rs[row] = 1.f / t;
    }
}

__device__ __forceinline__ void atomicMaxF(float* addr, float v)
{
    atomicMax((int*)addr, __float_as_int(v));   // valid for non-negative floats
}

__global__ void pinv_reduce_kernel(const float* __restrict__ S2, float* __restrict__ scal)
{
    int z = blockIdx.x;
    int tid = threadIdx.x;   // 256
    const float* Mz = S2 + (long long)z * NLAND * NLAND;
    float rs = 0.f, cs = 0.f;
    for (int j = 0; j < NLAND; j++) rs += Mz[(long long)tid*NLAND + j];
    for (int i = 0; i < NLAND; i++) cs += Mz[(long long)i*NLAND + tid];
    __shared__ float sm[256];
    sm[tid] = rs; __syncthreads();
    for (int s = 128; s; s >>= 1) { if (tid < s) sm[tid] = fmaxf(sm[tid], sm[tid+s]); __syncthreads(); }
    if (tid == 0) atomicMaxF(&scal[0], sm[0]);
    __syncthreads();
    sm[tid] = cs; __syncthreads();
    for (int s = 128; s; s >>= 1) { if (tid < s) sm[tid] = fmaxf(sm[tid], sm[tid+s]); __syncthreads(); }
    if (tid == 0) atomicMaxF(&scal[1], sm[0]);
}

__global__ void zinit_kernel(float* __restrict__ Z, const float* __restrict__ S2,
                             const float* __restrict__ scal)
{
    long long idx = (long long)blockIdx.x * blockDim.x + threadIdx.x;
    float rcp = 1.f / (scal[0] * scal[1]);
    long long z = idx >> 16;
    int r = (int)((idx >> 8) & 255);
    int c = (int)(idx & 255);
    Z[idx] = S2[(z << 16) + ((long long)c << 8) + r] * rcp;
}

__global__ void conv_kernel(float* __restrict__ O, const float* __restrict__ QKV,
                            const float* __restrict__ cw)
{
    int t0 = blockIdx.x * 128;
    int h = blockIdx.y;
    int b = blockIdx.z;
    __shared__ float sv[160*64];
    __shared__ float ws[KCONV];
    int tid = threadIdx.x;   // 256
    if (tid < KCONV) ws[tid] = cw[h*KCONV + tid];
    for (int i = tid; i < 160*64; i += 256) {
        int tl = i >> 6, d = i & 63;
        int t = t0 + tl - 16;
        float v = 0.f;
        if (t >= 0 && t < NF)
            v = QKV[((long long)b*NF + t)*QKVW + 2*DMODEL + h*DH + d];
        sv[i] = v;
    }
    __syncthreads();
    float* Op = O + (((long long)(b*NHEADS + h))*NF + t0)*DH;
    for (int i = tid; i < 128*64; i += 256) {
        int tl = i >> 6, d = i & 63;
        float acc = 0.f;
        #pragma unroll
        for (int k = 0; k < KCONV; k++) acc += ws[k] * sv[(tl + k)*64 + d];
        Op[i] += acc;
    }
}

__global__ void merge_kernel(const float* __restrict__ O, float* __restrict__ OC)
{
    long long idx = (long long)blockIdx.x * blockDim.x + threadIdx.x;
    int c = (int)(idx & 511);
    int n = (int)((idx >> 9) & (NF - 1));
    int b = (int)(idx >> 22);
    int h = c >> 6, d = c & 63;
    OC[idx] = O[(((long long)(b*NHEADS + h))*NF + n)*DH + d];
}

__global__ void final_kernel(const float* __restrict__ X, const float* __restrict__ g,
                             const float* __restrict__ bt, const float* __restrict__ w2,
                             const float* __restrict__ b2, float* __restrict__ out)
{
    int b = blockIdx.x;
    int tid = threadIdx.x;  // 128
    const float* x = X + (long long)b*NF*DMODEL;
    float4 v = ((const float4*)x)[tid];
    float s = v.x+v.y+v.z+v.w;
    float q = v.x*v.x + v.y*v.y + v.z*v.z + v.w*v.w;
    #pragma unroll
    for (int o = 16; o; o >>= 1) {
        s += __shfl_xor_sync(0xffffffffu, s, o);
        q += __shfl_xor_sync(0xffffffffu, q, o);
    }
    __shared__ float ss[4], qq[4];
    if ((tid & 31) == 0) { ss[tid>>5] = s; qq[tid>>5] = q; }
    __syncthreads();
    s = ss[0]+ss[1]+ss[2]+ss[3];
    q = qq[0]+qq[1]+qq[2]+qq[3];
    float mu = s * (1.f/DMODEL);
    float var = q * (1.f/DMODEL) - mu*mu;
    float rs = rsqrtf(var + 1e-5f);
    __shared__ float xn[DMODEL];
    float4 gv = ((const float4*)g)[tid];
    float4 bv = ((const float4*)bt)[tid];
    xn[tid*4+0] = (v.x-mu)*rs*gv.x + bv.x;
    xn[tid*4+1] = (v.y-mu)*rs*gv.y + bv.y;
    xn[tid*4+2] = (v.z-mu)*rs*gv.z + bv.z;
    xn[tid*4+3] = (v.w-mu)*rs*gv.w + bv.w;
    __syncthreads();
    float s0 = 0.f, s1 = 0.f;
    for (int d = tid; d < DMODEL; d += 128) {
        float xv = xn[d];
        s0 += xv * w2[d*2+0];
        s1 += xv * w2[d*2+1];
    }
    __shared__ float r0[128], r1[128];
    r0[tid] = s0; r1[tid] = s1;
    __syncthreads();
    for (int st = 64; st; st >>= 1) {
        if (tid < st) { r0[tid] += r0[tid+st]; r1[tid] += r1[tid+st]; }
        __syncthreads();
    }
    if (tid == 0) {
        out[b*2+0] = r0[0] + b2[0];
        out[b*2+1] = r1[0] + b2[1];
    }
}

// ------------------------------ host side ----------------------------------
struct Bufs {
    float *X,*XLN,*QKV,*QL,*KL,*S1,*S3,*S2,*T,*U,*Rb,*Z,*Z2,*W,*Wp,*O,*OC,*RS1,*RS3,*scal;
};

static Bufs init_bufs()
{
    Bufs b;
    cudaGetSymbolAddress((void**)&b.X,   g_X);
    cudaGetSymbolAddress((void**)&b.XLN, g_XLN);
    cudaGetSymbolAddress((void**)&b.QKV, g_QKV);
    cudaGetSymbolAddress((void**)&b.QL,  g_QL);
    cudaGetSymbolAddress((void**)&b.KL,  g_KL);
    cudaGetSymbolAddress((void**)&b.S1,  g_S1);
    cudaGetSymbolAddress((void**)&b.S3,  g_S3);
    cudaGetSymbolAddress((void**)&b.S2,  g_S2);
    cudaGetSymbolAddress((void**)&b.T,   g_T);
    cudaGetSymbolAddress((void**)&b.U,   g_U);
    cudaGetSymbolAddress((void**)&b.Rb,  g_R);
    cudaGetSymbolAddress((void**)&b.Z,   g_Z);
    cudaGetSymbolAddress((void**)&b.Z2,  g_Z2);
    cudaGetSymbolAddress((void**)&b.W,   g_W);
    cudaGetSymbolAddress((void**)&b.Wp,  g_Wp);
    cudaGetSymbolAddress((void**)&b.O,   g_O);
    cudaGetSymbolAddress((void**)&b.OC,  g_OC);
    cudaGetSymbolAddress((void**)&b.RS1, g_RS1);
    cudaGetSymbolAddress((void**)&b.RS3, g_RS3);
    cudaGetSymbolAddress((void**)&b.scal,g_scal);
    return b;
}

static inline void gemm_call(int bm, const float* A, const float* B, float* C,
    int M, int N, int K, int lda, int ldb, int ldc, int nb,
    long long sAb, long long sAh, long long sBb, long long sBh,
    long long sCb, long long sCh,
    const float* bias, const float* resid, int ldr,
    float alpha, int relu, bool transb,
    int nsplit = 1, int Kc = 0, long long sSp = 0,
    const float* rs = nullptr, int rsStride = 0,
    float* aux = nullptr, float diagc = 0.f)
{
    dim3 gr((N + 127)/128, (M + bm - 1)/bm, nb * nsplit);
    if (bm == 128) {
        if (nsplit > 1) {
            if (transb) sgemm<128,true ,true ><<<gr,256>>>(A,B,C,M,N,K,lda,ldb,ldc,sAb,sAh,sBb,sBh,sCb,sCh,bias,resid,ldr,alpha,relu,nsplit,Kc,sSp,rs,rsStride,aux,diagc);
            else        sgemm<128,false,true ><<<gr,256>>>(A,B,C,M,N,K,lda,ldb,ldc,sAb,sAh,sBb,sBh,sCb,sCh,bias,resid,ldr,alpha,relu,nsplit,Kc,sSp,rs,rsStride,aux,diagc);
        } else {
            if (transb) sgemm<128,true ,false><<<gr,256>>>(A,B,C,M,N,K,lda,ldb,ldc,sAb,sAh,sBb,sBh,sCb,sCh,bias,resid,ldr,alpha,relu,1,0,0,rs,rsStride,aux,diagc);
            else        sgemm<128,false,false><<<gr,256>>>(A,B,C,M,N,K,lda,ldb,ldc,sAb,sAh,sBb,sBh,sCb,sCh,bias,resid,ldr,alpha,relu,1,0,0,rs,rsStride,aux,diagc);
        }
    } else {
        if (nsplit > 1) {
            if (transb) sgemm<64,true ,true ><<<gr,256>>>(A,B,C,M,N,K,lda,ldb,ldc,sAb,sAh,sBb,sBh,sCb,sCh,bias,resid,ldr,alpha,relu,nsplit,Kc,sSp,rs,rsStride,aux,diagc);
            else        sgemm<64,false,true ><<<gr,256>>>(A,B,C,M,N,K,lda,ldb,ldc,sAb,sAh,sBb,sBh,sCb,sCh,bias,resid,ldr,alpha,relu,nsplit,Kc,sSp,rs,rsStride,aux,diagc);
        } else {
            if (transb) sgemm<64,true ,false><<<gr,256>>>(A,B,C,M,N,K,lda,ldb,ldc,sAb,sAh,sBb,sBh,sCb,sCh,bias,resid,ldr,alpha,relu,1,0,0,rs,rsStride,aux,diagc);
            else        sgemm<64,false,false><<<gr,256>>>(A,B,C,M,N,K,lda,ldb,ldc,sAb,sAh,sBb,sBh,sCb,sCh,bias,resid,ldr,alpha,relu,1,0,0,rs,rsStride,aux,diagc);
        }
    }
}

static void run_layer(const Bufs& bu, int L, void* const* d_in)
{
    const float* lng  = (const float*)d_in[4] + (size_t)L*DMODEL;
    const float* lnb  = (const float*)d_in[5] + (size_t)L*DMODEL;
    const float* wqkv = (const float*)d_in[6] + (size_t)L*DMODEL*QKVW;
    const float* wout = (const float*)d_in[7] + (size_t)L*DMODEL*DMODEL;
    const float* bout = (const float*)d_in[8] + (size_t)L*DMODEL;
    const float* cw   = (const float*)d_in[9] + (size_t)L*NHEADS*KCONV;

    const long long sQKVb = (long long)NF*QKVW;
    const long long sLh = (long long)NLAND*DH;
    const long long sLb = (long long)NHEADS*sLh;
    const long long sS1h = (long long)NF*NLAND;
    const long long sS1b = (long long)NHEADS*sS1h;
    const long long sS3h = (long long)NLAND*NF;
    const long long sS3b = (long long)NHEADS*sS3h;
    const long long sm = (long long)NLAND*NLAND;
    const long long smb = (long long)NHEADS*sm;
    const long long sOh = (long long)NF*DH;
    const long long sOb = (long long)NHEADS*sOh;

    // x_ln = LN(x)
    ln_kernel<<<NROWS,128>>>(bu.X, bu.XLN, lng, lnb);
    // QKV = x_ln @ w_qkv
    gemm_call(128, bu.XLN, wqkv, bu.QKV, NROWS, QKVW, DMODEL, DMODEL, QKVW, QKVW, 1,
              0,0,0,0,0,0, nullptr,nullptr,0, 1.f,0,false);
    // landmarks
    landmark_kernel<<<dim3(NLAND,NBH),64>>>(bu.QKV, bu.QL, 0);
    landmark_kernel<<<dim3(NLAND,NBH),64>>>(bu.QKV, bu.KL, DMODEL);
    // sim1 = (q*scale) @ k_l^T
    gemm_call(128, bu.QKV, bu.KL, bu.S1, NF, NLAND, DH, QKVW, DH, NLAND, NBH,
              sQKVb, DH, sLb, sLh, sS1b, sS1h, nullptr,nullptr,0, 0.125f,0,true);
    // sim2 = (q_l*scale) @ k_l^T
    gemm_call(64, bu.QL, bu.KL, bu.S2, NLAND, NLAND, DH, DH, DH, NLAND, NBH,
              sLb, sLh, sLb, sLh, smb, sm, nullptr,nullptr,0, 0.125f,0,true);
    // sim3 = (q_l*scale) @ k^T
    gemm_call(64, bu.QL, bu.QKV + DMODEL, bu.S3, NLAND, NF, DH, DH, QKVW, NF, NBH,
              sLb, sLh, sQKVb, DH, sS3b, sS3h, nullptr,nullptr,0, 0.125f,0,true);
    // softmaxes: S1/S3 keep exp + rowscale; S2 fully normalized
    softmax2_kernel<<<NBH*NF,256>>>(bu.S1, NLAND, bu.RS1);
    softmax_kernel<<<NBH*NLAND,256>>>(bu.S2, NLAND);
    softmax2_kernel<<<NBH*NLAND,256>>>(bu.S3, NF, bu.RS3);
    // Moore-Penrose pinv (Newton-Schulz with fused diag epilogues)
    cudaMemsetAsync(bu.scal, 0, 2*sizeof(float));
    pinv_reduce_kernel<<<NBH,256>>>(bu.S2, bu.scal);
    zinit_kernel<<<(NBH*NLAND*NLAND)/256,256>>>(bu.Z, bu.S2, bu.scal);
    float* za = bu.Z;
    float* zb = bu.Z2;
    for (int it = 0; it < 6; it++) {
        // T = S2@Z (aux raw) ; U = 7I - T
        gemm_call(64, bu.S2, za, bu.U, NLAND,NLAND,NLAND, NLAND,NLAND,NLAND, NBH,
                  smb,sm, smb,sm, smb,sm, nullptr,nullptr,0, 1.f,0,false,
                  1,0,0, nullptr,0, bu.T, 7.f);
        // R' = 15I - T@U
        gemm_call(64, bu.T, bu.U, bu.Rb, NLAND,NLAND,NLAND, NLAND,NLAND,NLAND, NBH,
                  smb,sm, smb,sm, smb,sm, nullptr,nullptr,0, 1.f,0,false,
                  1,0,0, nullptr,0, nullptr, 15.f);
        // U2 = 13I - T@R'
        gemm_call(64, bu.T, bu.Rb, bu.U, NLAND,NLAND,NLAND, NLAND,NLAND,NLAND, NBH,
                  smb,sm, smb,sm, smb,sm, nullptr,nullptr,0, 1.f,0,false,
                  1,0,0, nullptr,0, nullptr, 13.f);
        // Z' = 0.25 * Z @ U2
        gemm_call(64, za, bu.U, zb, NLAND,NLAND,NLAND, NLAND,NLAND,NLAND, NBH,
                  smb,sm, smb,sm, smb,sm, nullptr,nullptr,0, 0.25f,0,false);
        float* tp = za; za = zb; zb = tp;
    }
    // W = attn3 @ v (rowscale = 1/sum3; deterministic split-K + reduce)
    gemm_call(64, bu.S3, bu.QKV + 2*DMODEL, bu.Wp, NLAND, DH, NF, NF, QKVW, DH, NBH,
              sS3b, sS3h, sQKVb, DH, sLb, sLh, nullptr,nullptr,0, 1.f,0,false,
              8, 1024, (long long)NBH*NLAND*DH, bu.RS3, NLAND);
    reduce_split_kernel<<<(NBH*NLAND*DH)/256,256>>>(bu.Wp, bu.W, (long long)NBH*NLAND*DH);
    // P = attn1 @ Z (rowscale = 1/sum1); reuse S3 buffer
    gemm_call(128, bu.S1, za, bu.S3, NF, NLAND, NLAND, NLAND, NLAND, NLAND, NBH,
              sS1b, sS1h, smb, sm, sS1b, sS1h, nullptr,nullptr,0, 1.f,0,false,
              1,0,0, bu.RS1, NF);
    // O = P @ W
    gemm_call(128, bu.S3, bu.W, bu.O, NF, DH, NLAND, NLAND, DH, DH, NBH,
              sS1b, sS1h, sLb, sLh, sOb, sOh, nullptr,nullptr,0, 1.f,0,false);
    // O += depthwise conv of V
    conv_kernel<<<dim3(NF/128, NHEADS, NBATCH),256>>>(bu.O, bu.QKV, cw);
    // concat heads
    merge_kernel<<<((long long)NBATCH*NF*DMODEL)/256,256>>>(bu.O, bu.OC);
    // x = x + (OC @ w_out + b_out)
    gemm_call(128, bu.OC, wout, bu.X, NROWS, DMODEL, DMODEL, DMODEL, DMODEL, DMODEL, 1,
              0,0,0,0,0,0, bout, bu.X, DMODEL, 1.f,0,false);
}

extern "C" void kernel_launch(void* const* d_in, const int* in_sizes, int n_in,
                              void* d_out, int out_size)
{
    static Bufs bu = init_bufs();
    const float* h    = (const float*)d_in[0];
    const float* w1   = (const float*)d_in[1];
    const float* b1   = (const float*)d_in[2];
    const float* cls  = (const float*)d_in[3];
    const float* fng  = (const float*)d_in[10];
    const float* fnb  = (const float*)d_in[11];
    const float* w2   = (const float*)d_in[12];
    const float* b2   = (const float*)d_in[13];

    // x = relu(h @ w1 + b1) rows 1..8191 per batch; batched via hh stride
    gemm_call(128, h, w1, bu.X + DMODEL, 8191, DMODEL, 1024, 1024, DMODEL, DMODEL, 2,
              0, (long long)8191*1024, 0, 0, 0, (long long)NF*DMODEL,
              b1, nullptr, 0, 1.f, 1, false);
    cls_copy_kernel<<<1,512>>>(bu.X, cls);

    run_layer(bu, 0, d_in);
    run_layer(bu, 1, d_in);

    final_kernel<<<NBATCH,128>>>(bu.X, fng, fnb, w2, b2, (float*)d_out);
}

// round 9
// speedup vs baseline: 1.4313x; 1.1434x over previous
#include <cuda_runtime.h>
#include <cuda_bf16.h>

#define NF 8192
#define DMODEL 512
#define NHEADS 8
#define DH 64
#define NLAND 256
#define NBATCH 2
#define NBH 16
#define QKVW 1536
#define NROWS (NBATCH*NF)
#define KCONV 33

// ------------------------- scratch (device globals; no allocs allowed) -----
__device__ __align__(16) float g_X  [(size_t)NBATCH*NF*DMODEL];
__device__ __align__(16) float g_XLN[(size_t)NBATCH*NF*DMODEL];
__device__ __align__(16) float g_QKV[(size_t)NBATCH*NF*QKVW];
__device__ __align__(16) float g_QL [(size_t)NBH*NLAND*DH];
__device__ __align__(16) float g_KL [(size_t)NBH*NLAND*DH];
__device__ __align__(16) float g_S1 [(size_t)NBH*NF*NLAND];
__device__ __align__(16) float g_S3 [(size_t)NBH*NF*NLAND];
__device__ __align__(16) float g_S2 [(size_t)NBH*NLAND*NLAND];
__device__ __align__(16) float g_T  [(size_t)NBH*NLAND*NLAND];
__device__ __align__(16) float g_U  [(size_t)NBH*NLAND*NLAND];
__device__ __align__(16) float g_R  [(size_t)NBH*NLAND*NLAND];
__device__ __align__(16) float g_Z  [(size_t)NBH*NLAND*NLAND];
__device__ __align__(16) float g_Z2 [(size_t)NBH*NLAND*NLAND];
__device__ __align__(16) float g_W  [(size_t)NBH*NLAND*DH];
__device__ __align__(16) float g_Wp [(size_t)8*NBH*NLAND*DH];
__device__ __align__(16) float g_O  [(size_t)NBH*NF*DH];
__device__ __align__(16) float g_OC [(size_t)NBATCH*NF*DMODEL];
__device__ __align__(16) float g_RS1[(size_t)NBH*NF];
__device__ __align__(16) float g_RS3[(size_t)NBH*NLAND];
__device__ float g_scal[2];
// bf16 split operand buffers for the tensor-core path
__device__ __align__(16) __nv_bfloat16 g_Ah[(size_t)NBH*NF*NLAND];
__device__ __align__(16) __nv_bfloat16 g_Al[(size_t)NBH*NF*NLAND];
__device__ __align__(16) __nv_bfloat16 g_Bh[(size_t)1048576];
__device__ __align__(16) __nv_bfloat16 g_Bl[(size_t)1048576];

// ------------------------- f32x2 packed helpers ----------------------------
__device__ __forceinline__ unsigned long long pack2_dup(float x)
{
    unsigned long long r;
    unsigned int u = __float_as_uint(x);
    asm("mov.b64 %0, {%1, %1};" : "=l"(r) : "r"(u));
    return r;
}
__device__ __forceinline__ void ffma2(unsigned long long& d,
                                      unsigned long long a, unsigned long long b)
{
    asm("fma.rn.f32x2 %0, %1, %2, %0;" : "+l"(d) : "l"(a), "l"(b));
}
__device__ __forceinline__ float2 unpack2(unsigned long long v)
{
    unsigned int lo, hi;
    asm("mov.b64 {%0, %1}, %2;" : "=r"(lo), "=r"(hi) : "l"(v));
    return make_float2(__uint_as_float(lo), __uint_as_float(hi));
}

// -------- warp mma helper: m16n8k16 bf16 x bf16 -> f32 accumulate ----------
#define MMA16816(d, A, B)                                                      \
    asm volatile("mma.sync.aligned.m16n8k16.row.col.f32.bf16.bf16.f32 "        \
                 "{%0,%1,%2,%3},{%4,%5,%6,%7},{%8,%9},{%0,%1,%2,%3};"          \
                 : "+f"((d)[0]), "+f"((d)[1]), "+f"((d)[2]), "+f"((d)[3])      \
                 : "r"((A)[0]), "r"((A)[1]), "r"((A)[2]), "r"((A)[3]),         \
                   "r"((B)[0]), "r"((B)[1]))

// ---------------- tensor-core bf16-split GEMM: C[M,N] = A@B^T ---------------
// A: bf16 hi/lo [z][M][K]; B: bf16 hi/lo [z][N][K]. K mult of 16, M,N mult of
// 128. fp32 accumulators hold AhBh + AlBh + AhBl (lo*lo dropped, ~2^-16 rel).
__global__ __launch_bounds__(256, 2) void mma_gemm(
    const __nv_bfloat16* __restrict__ Ah, const __nv_bfloat16* __restrict__ Al,
    const __nv_bfloat16* __restrict__ Bh, const __nv_bfloat16* __restrict__ Bl,
    float* __restrict__ C, int Kv, int ldc,
    long long sA, long long sB, long long sC,
    const float* __restrict__ bias, const float* __restrict__ resid, int ldr)
{
    __shared__ __nv_bfloat16 sAh[2][128*16], sAl[2][128*16];
    __shared__ __nv_bfloat16 sBh[2][128*16], sBl[2][128*16];

    int tid = threadIdx.x;
    int lane = tid & 31, wid = tid >> 5;
    int z = blockIdx.z;
    int m0 = blockIdx.y * 128, n0 = blockIdx.x * 128;
    const __nv_bfloat16* pAh = Ah + (long long)z*sA + (long long)m0*Kv;
    const __nv_bfloat16* pAl = Al + (long long)z*sA + (long long)m0*Kv;
    const __nv_bfloat16* pBh = Bh + (long long)z*sB + (long long)n0*Kv;
    const __nv_bfloat16* pBl = Bl + (long long)z*sB + (long long)n0*Kv;
    float* Cz = C + (long long)z*sC;

    int row = tid >> 1, half = tid & 1;
    long long goff = (long long)row*Kv + half*8;
    int soff = row*16 + half*8;

    uint4 va_h, va_l, vb_h, vb_l;
    auto load = [&](int kk) {
        va_h = *(const uint4*)(pAh + goff + kk);
        va_l = *(const uint4*)(pAl + goff + kk);
        vb_h = *(const uint4*)(pBh + goff + kk);
        vb_l = *(const uint4*)(pBl + goff + kk);
    };
    auto store = [&](int pb) {
        *(uint4*)&sAh[pb][soff] = va_h;
        *(uint4*)&sAl[pb][soff] = va_l;
        *(uint4*)&sBh[pb][soff] = vb_h;
        *(uint4*)&sBl[pb][soff] = vb_l;
    };

    float acc[2][8][4];
    #pragma unroll
    for (int i = 0; i < 2; i++)
        #pragma unroll
        for (int j = 0; j < 8; j++)
            #pragma unroll
            for (int e = 0; e < 4; e++) acc[i][j][e] = 0.f;

    int warpM = (wid & 3) * 32, warpN = (wid >> 2) * 64;
    int ar = warpM + (lane >> 2);
    int kc = 2 * (lane & 3);
    int bro = (lane >> 2);

    int nchunk = Kv >> 4;
    load(0);
    store(0);
    __syncthreads();

    for (int t = 0; t < nchunk; t++) {
        if (t + 1 < nchunk) load((t + 1) << 4);
        int pb = t & 1;
        const __nv_bfloat16* a_h = sAh[pb];
        const __nv_bfloat16* a_l = sAl[pb];
        const __nv_bfloat16* b_h = sBh[pb];
        const __nv_bfloat16* b_l = sBl[pb];

        unsigned Af[2][4], Ag[2][4];
        #pragma unroll
        for (int mt = 0; mt < 2; mt++) {
            int base = (ar + mt*16)*16 + kc;
            Af[mt][0] = *(const unsigned*)&a_h[base];
            Af[mt][1] = *(const unsigned*)&a_h[base + 128];
            Af[mt][2] = *(const unsigned*)&a_h[base + 8];
            Af[mt][3] = *(const unsigned*)&a_h[base + 136];
            Ag[mt][0] = *(const unsigned*)&a_l[base];
            Ag[mt][1] = *(const unsigned*)&a_l[base + 128];
            Ag[mt][2] = *(const unsigned*)&a_l[base + 8];
            Ag[mt][3] = *(const unsigned*)&a_l[base + 136];
        }
        #pragma unroll
        for (int nt = 0; nt < 8; nt++) {
            int bb = (warpN + nt*8 + bro)*16 + kc;
            unsigned bh[2], bl[2];
            bh[0] = *(const unsigned*)&b_h[bb];
            bh[1] = *(const unsigned*)&b_h[bb + 8];
            bl[0] = *(const unsigned*)&b_l[bb];
            bl[1] = *(const unsigned*)&b_l[bb + 8];
            #pragma unroll
            for (int mt = 0; mt < 2; mt++) {
                MMA16816(acc[mt][nt], Af[mt], bh);
                MMA16816(acc[mt][nt], Ag[mt], bh);
                MMA16816(acc[mt][nt], Af[mt], bl);
            }
        }
        if (t + 1 < nchunk) {
            store((t + 1) & 1);
            __syncthreads();
        }
    }

    // epilogue
    #pragma unroll
    for (int mt = 0; mt < 2; mt++) {
        int r0 = m0 + warpM + mt*16 + (lane >> 2);
        #pragma unroll
        for (int nt = 0; nt < 8; nt++) {
            int c0 = n0 + warpN + nt*8 + kc;
            float v0 = acc[mt][nt][0], v1 = acc[mt][nt][1];
            float v2 = acc[mt][nt][2], v3 = acc[mt][nt][3];
            if (bias) {
                float b0 = bias[c0], b1 = bias[c0 + 1];
                v0 += b0; v1 += b1; v2 += b0; v3 += b1;
            }
            if (resid) {
                v0 += resid[(long long)r0*ldr + c0];
                v1 += resid[(long long)r0*ldr + c0 + 1];
                v2 += resid[(long long)(r0 + 8)*ldr + c0];
                v3 += resid[(long long)(r0 + 8)*ldr + c0 + 1];
            }
            *(float2*)&Cz[(long long)r0*ldc + c0] = make_float2(v0, v1);
            *(float2*)&Cz[(long long)(r0 + 8)*ldc + c0] = make_float2(v2, v3);
        }
    }
}

// ------------- fp32 -> bf16 hi/lo conversion (straight, batched) ------------
__global__ void cvt_a_kernel(const float* __restrict__ src,
    __nv_bfloat16* __restrict__ hi, __nv_bfloat16* __restrict__ lo,
    int kshift, int lds, long long sb, long long sh, long long RK,
    const float* __restrict__ rowscale, long long rsStride, float scale)
{
    long long idx = (long long)blockIdx.x * 256 + threadIdx.x;
    int z = blockIdx.y;
    int r = (int)(idx >> kshift);
    int k = (int)(idx & ((1 << kshift) - 1));
    float v = src[(long long)(z>>3)*sb + (long long)(z&7)*sh + (long long)r*lds + k] * scale;
    if (rowscale) v *= rowscale[(long long)z*rsStride + r];
    __nv_bfloat16 h = __float2bfloat16(v);
    float rem = v - __bfloat162float(h);
    long long o = (long long)z*RK + idx;
    hi[o] = h;
    lo[o] = __float2bfloat16(rem);
}

// ------ fp32 [K,N] -> bf16 hi/lo [N,K] (transpose conversion, batched) ------
__global__ void cvt_t_kernel(const float* __restrict__ src,
    __nv_bfloat16* __restrict__ hi, __nv_bfloat16* __restrict__ lo,
    int Kv, int Nv, long long sz)
{
    __shared__ float t[32][33];
    int z = blockIdx.z;
    const float* s = src + (long long)z*sz;
    int n = blockIdx.x*32 + threadIdx.x;
    #pragma unroll
    for (int i = 0; i < 4; i++) {
        int k = blockIdx.y*32 + threadIdx.y + i*8;
        t[threadIdx.y + i*8][threadIdx.x] = s[(long long)k*Nv + n];
    }
    __syncthreads();
    int k2 = blockIdx.y*32 + threadIdx.x;
    #pragma unroll
    for (int i = 0; i < 4; i++) {
        int n2 = blockIdx.x*32 + threadIdx.y + i*8;
        float v = t[threadIdx.x][threadIdx.y + i*8];
        __nv_bfloat16 h = __float2bfloat16(v);
        float rem = v - __bfloat162float(h);
        long long o = ((long long)z*Nv + n2)*Kv + k2;
        hi[o] = h;
        lo[o] = __float2bfloat16(rem);
    }
}

// ------------------------------- SGEMM (scalar f32x2) -----------------------
template<int BM, bool TRANSB, bool SPLITK>
__global__ __launch_bounds__(256) void sgemm(
    const float* __restrict__ A, const float* __restrict__ B, float* __restrict__ C,
    int M, int N, int K, int lda, int ldb, int ldc,
    long long sAb, long long sAh, long long sBb, long long sBh,
    long long sCb, long long sCh,
    const float* __restrict__ bias, const float* __restrict__ resid, int ldr,
    float alpha, int relu, int nsplit, int Kc, long long sSp,
    const float* __restrict__ rsA, int rsStride,
    float* __restrict__ aux, float diagc)
{
    constexpr int NI = BM / 16;
    int zAll = blockIdx.z;
    int zb = zAll / nsplit;
    int sp = zAll - zb * nsplit;
    int bb = zb >> 3, hh = zb & 7;
    const float* Ap = A + bb*sAb + hh*sAh;
    const float* Bp = B + bb*sBb + hh*sBh;
    float*       Cp = C + bb*sCb + hh*sCh + (SPLITK ? (long long)sp * sSp : 0LL);
    float*       Xp = aux ? aux + bb*sCb + hh*sCh : (float*)0;
    const float* rsp = rsA ? rsA + (long long)zb * rsStride : (const float*)0;

    int bm0 = blockIdx.y * BM;
    int bn0 = blockIdx.x * 128;
    int k0   = SPLITK ? sp * Kc : 0;
    int kEnd = SPLITK ? min(K, k0 + Kc) : K;

    __shared__ __align__(16) float As[2][8][128];
    __shared__ __align__(16) float Bs[2][8][128];

    int tid = threadIdx.x;
    int tx = tid & 15, ty = tid >> 4;
    unsigned long long acc[NI][4];
    #pragma unroll
    for (int i = 0; i < NI; i++)
        #pragma unroll
        for (int j = 0; j < 4; j++) acc[i][j] = 0ULL;

    int arow = bm0 + (tid >> 1);
    int akq  = (tid & 1) * 4;
    int bk = tid >> 5;
    int bn = (tid & 31) * 4;
    int gc = bn0 + bn;
    int nB = bn0 + (tid >> 1);

    float4 avS, bvS;

    auto loadTile = [&](int kk) {
        avS = make_float4(0.f,0.f,0.f,0.f);
        if ((BM == 128 || tid < 128) && arow < M)
            avS = *(const float4*)(Ap + (long long)arow*lda + kk + akq);
        if (TRANSB) {
            bvS = make_float4(0.f,0.f,0.f,0.f);
            if (nB < N) bvS = *(const float4*)(Bp + (long long)nB*ldb + kk + akq);
        } else {
            const float* p = Bp + (long long)(kk + bk)*ldb + gc;
            if (gc + 3 < N) bvS = *(const float4*)p;
            else {
                bvS.x = (gc+0 < N) ? p[0] : 0.f;
                bvS.y = (gc+1 < N) ? p[1] : 0.f;
                bvS.z = (gc+2 < N) ? p[2] : 0.f;
                bvS.w = (gc+3 < N) ? p[3] : 0.f;
            }
        }
    };
    auto storeTile = [&](int pb) {
        if (BM == 128 || tid < 128) {
            As[pb][akq+0][tid>>1] = avS.x;
            As[pb][akq+1][tid>>1] = avS.y;
            As[pb][akq+2][tid>>1] = avS.z;
            As[pb][akq+3][tid>>1] = avS.w;
        }
        if (TRANSB) {
            Bs[pb][akq+0][tid>>1] = bvS.x;
            Bs[pb][akq+1][tid>>1] = bvS.y;
            Bs[pb][akq+2][tid>>1] = bvS.z;
            Bs[pb][akq+3][tid>>1] = bvS.w;
        } else {
            *(float4*)&Bs[pb][bk][bn] = bvS;
        }
    };

    int nt = (kEnd - k0) >> 3;
    loadTile(k0);
    storeTile(0);
    __syncthreads();

    for (int t = 0; t < nt; t++) {
        if (t + 1 < nt) loadTile(k0 + ((t + 1) << 3));
        int pb = t & 1;
        #pragma unroll
        for (int k = 0; k < 8; k++) {
            float ra[NI];
            *(float4*)&ra[0] = *(const float4*)&As[pb][k][ty*4];
            if (BM == 128)
                *(float4*)&ra[4] = *(const float4*)&As[pb][k][64 + ty*4];
            ulonglong2 bq0 = *(const ulonglong2*)&Bs[pb][k][tx*4];
            ulonglong2 bq1 = *(const ulonglong2*)&Bs[pb][k][64 + tx*4];
            unsigned long long rb0 = bq0.x, rb1 = bq0.y, rb2 = bq1.x, rb3 = bq1.y;
            #pragma unroll
            for (int i = 0; i < NI; i++) {
                unsigned long long aa = pack2_dup(ra[i]);
                ffma2(acc[i][0], aa, rb0);
                ffma2(acc[i][1], aa, rb1);
                ffma2(acc[i][2], aa, rb2);
                ffma2(acc[i][3], aa, rb3);
            }
        }
        if (t + 1 < nt) {
            storeTile((t + 1) & 1);
            __syncthreads();
        }
    }

    #pragma unroll
    for (int i = 0; i < NI; i++) {
        int r = bm0 + ((i < 4) ? (ty*4 + i) : (64 + ty*4 + i - 4));
        if (r >= M) continue;
        float rsv = rsp ? rsp[r] : 1.f;
        #pragma unroll
        for (int jp = 0; jp < 4; jp++) {
            float2 pv = unpack2(acc[i][jp]);
            int cbase = bn0 + ((jp < 2) ? (tx*4 + jp*2) : (64 + tx*4 + (jp-2)*2));
            float vv[2] = {pv.x, pv.y};
            #pragma unroll
            for (int e = 0; e < 2; e++) {
                int c = cbase + e;
                if (c >= N) continue;
                float v = vv[e] * alpha;
                long long off = (long long)r*ldc + c;
                if (SPLITK) {
                    if (rsp) v *= rsv;
                    Cp[off] = v;
                } else {
                    if (rsp)  v *= rsv;
                    if (Xp)   Xp[off] = v;
                    if (diagc != 0.f) v = (r == c ? diagc : 0.f) - v;
                    if (bias)  v += bias[c];
                    if (resid) v += resid[(long long)r*ldr + c];
                    if (relu)  v = fmaxf(v, 0.f);
                    Cp[off] = v;
                }
            }
        }
    }
}

// ------------------------------ helpers ------------------------------------
__global__ void reduce_split_kernel(const float* __restrict__ Wp, float* __restrict__ W,
                                    long long stride)
{
    long long idx = (long long)blockIdx.x * blockDim.x + threadIdx.x;
    float s = 0.f;
    for (int k = 0; k < 8; k++) s += Wp[(long long)k*stride + idx];
    W[idx] = s;
}

__global__ void ln_kernel(const float* __restrict__ X, float* __restrict__ Y,
                          const float* __restrict__ g, const float* __restrict__ b)
{
    long long r = blockIdx.x;
    int tid = threadIdx.x;   // 128
    float4 v = ((const float4*)(X + r*DMODEL))[tid];
    float s = v.x+v.y+v.z+v.w;
    float q = v.x*v.x + v.y*v.y + v.z*v.z + v.w*v.w;
    #pragma unroll
    for (int o = 16; o; o >>= 1) {
        s += __shfl_xor_sync(0xffffffffu, s, o);
        q += __shfl_xor_sync(0xffffffffu, q, o);
    }
    __shared__ float ss[4], qq[4];
    if ((tid & 31) == 0) { ss[tid>>5] = s; qq[tid>>5] = q; }
    __syncthreads();
    s = ss[0]+ss[1]+ss[2]+ss[3];
    q = qq[0]+qq[1]+qq[2]+qq[3];
    float mu = s * (1.f/DMODEL);
    float var = q * (1.f/DMODEL) - mu*mu;
    float rs = rsqrtf(var + 1e-5f);
    float4 gv = ((const float4*)g)[tid];
    float4 bv = ((const float4*)b)[tid];
    float4 o;
    o.x = (v.x-mu)*rs*gv.x + bv.x;
    o.y = (v.y-mu)*rs*gv.y + bv.y;
    o.z = (v.z-mu)*rs*gv.z + bv.z;
    o.w = (v.w-mu)*rs*gv.w + bv.w;
    ((float4*)(Y + r*DMODEL))[tid] = o;
}

__global__ void cls_copy_kernel(float* __restrict__ X, const float* __restrict__ cls)
{
    int c = threadIdx.x;  // 512
    X[c] = cls[c];
    X[(long long)NF*DMODEL + c] = cls[c];
}

__global__ void landmark_kernel(const float* __restrict__ QKV, float* __restrict__ out, int off)
{
    int j = blockIdx.x;
    int z = blockIdx.y;
    int d = threadIdx.x;
    int b = z >> 3, h = z & 7;
    const float* base = QKV + ((long long)b*NF + (long long)j*32)*QKVW + off + h*DH + d;
    float s = 0.f;
    #pragma unroll
    for (int t = 0; t < 32; t++) s += base[(long long)t*QKVW];
    out[((long long)z*NLAND + j)*DH + d] = s * (1.f/32.f);
}

__global__ void softmax_kernel(float* __restrict__ X, int cols)
{
    long long row = blockIdx.x;
    float* p = X + row * cols;
    int tid = threadIdx.x;
    __shared__ float sred[8];
    __shared__ float sval;
    float m = -1e30f;
    for (int c = tid; c < cols; c += 256) m = fmaxf(m, p[c]);
    #pragma unroll
    for (int o = 16; o; o >>= 1) m = fmaxf(m, __shfl_xor_sync(0xffffffffu, m, o));
    if ((tid & 31) == 0) sred[tid>>5] = m;
    __syncthreads();
    if (tid == 0) {
        float mm = sred[0];
        for (int i = 1; i < 8; i++) mm = fmaxf(mm, sred[i]);
        sval = mm;
    }
    __syncthreads();
    m = sval;
    __syncthreads();
    float s = 0.f;
    for (int c = tid; c < cols; c += 256) {
        float e = __expf(p[c] - m);
        p[c] = e;
        s += e;
    }
    #pragma unroll
    for (int o = 16; o; o >>= 1) s += __shfl_xor_sync(0xffffffffu, s, o);
    if ((tid & 31) == 0) sred[tid>>5] = s;
    __syncthreads();
    if (tid == 0) {
        float t = 0.f;
        for (int i = 0; i < 8; i++) t += sred[i];
        sval = t;
    }
    __syncthreads();
    float inv = 1.f / sval;
    for (int c = tid; c < cols; c += 256) p[c] *= inv;
}

__global__ void softmax2_kernel(float* __restrict__ X, int cols, float* __restrict__ rs)
{
    long long row = blockIdx.x;
    float* p = X + row * cols;
    int tid = threadIdx.x;
    __shared__ float sred[8];
    __shared__ float sval;
    float m = -1e30f;
    for (int c = tid; c < cols; c += 256) m = fmaxf(m, p[c]);
    #pragma unroll
    for (int o = 16; o; o >>= 1) m = fmaxf(m, __shfl_xor_sync(0xffffffffu, m, o));
    if ((tid & 31) == 0) sred[tid>>5] = m;
    __syncthreads();
    if (tid == 0) {
        float mm = sred[0];
        for (int i = 1; i < 8; i++) mm = fmaxf(mm, sred[i]);
        sval = mm;
    }
    __syncthreads();
    m = sval;
    __syncthreads();
    float s = 0.f;
    for (int c = tid; c < cols; c += 256) {
        float e = __expf(p[c] - m);
        p[c] = e;
        s += e;
    }
    #pragma unroll
    for (int o = 16; o; o >>= 1) s += __shfl_xor_sync(0xffffffffu, s, o);
    if ((tid & 31) == 0) sred[tid>>5] = s;
    __syncthreads();
    if (tid == 0) {
        float t = 0.f;
        for (int i = 0; i < 8; i++) t += sred[i];
        rs[row] = 1.f / t;
    }
}

__device__ __forceinline__ void atomicMaxF(float* addr, float v)
{
    atomicMax((int*)addr, __float_as_int(v));
}

__global__ void pinv_reduce_kernel(const float* __restrict__ S2, float* __restrict__ scal)
{
    int z = blockIdx.x;
    int tid = threadIdx.x;
    const float* Mz = S2 + (long long)z * NLAND * NLAND;
    float rs = 0.f, cs = 0.f;
    for (int j = 0; j < NLAND; j++) rs += Mz[(long long)tid*NLAND + j];
    for (int i = 0; i < NLAND; i++) cs += Mz[(long long)i*NLAND + tid];
    __shared__ float sm[256];
    sm[tid] = rs; __syncthreads();
    for (int s = 128; s; s >>= 1) { if (tid < s) sm[tid] = fmaxf(sm[tid], sm[tid+s]); __syncthreads(); }
    if (tid == 0) atomicMaxF(&scal[0], sm[0]);
    __syncthreads();
    sm[tid] = cs; __syncthreads();
    for (int s = 128; s; s >>= 1) { if (tid < s) sm[tid] = fmaxf(sm[tid], sm[tid+s]); __syncthreads(); }
    if (tid == 0) atomicMaxF(&scal[1], sm[0]);
}

__global__ void zinit_kernel(float* __restrict__ Z, const float* __restrict__ S2,
                             const float* __restrict__ scal)
{
    long long idx = (long long)blockIdx.x * blockDim.x + threadIdx.x;
    float rcp = 1.f / (scal[0] * scal[1]);
    long long z = idx >> 16;
    int r = (int)((idx >> 8) & 255);
    int c = (int)(idx & 255);
    Z[idx] = S2[(z << 16) + ((long long)c << 8) + r] * rcp;
}

__global__ void conv_kernel(float* __restrict__ O, const float* __restrict__ QKV,
                            const float* __restrict__ cw)
{
    int t0 = blockIdx.x * 128;
    int h = blockIdx.y;
    int b = blockIdx.z;
    __shared__ float sv[160*64];
    __shared__ float ws[KCONV];
    int tid = threadIdx.x;
    if (tid < KCONV) ws[tid] = cw[h*KCONV + tid];
    for (int i = tid; i < 160*64; i += 256) {
        int tl = i >> 6, d = i & 63;
        int t = t0 + tl - 16;
        float v = 0.f;
        if (t >= 0 && t < NF)
            v = QKV[((long long)b*NF + t)*QKVW + 2*DMODEL + h*DH + d];
        sv[i] = v;
    }
    __syncthreads();
    float* Op = O + (((long long)(b*NHEADS + h))*NF + t0)*DH;
    for (int i = tid; i < 128*64; i += 256) {
        int tl = i >> 6, d = i & 63;
        float acc = 0.f;
        #pragma unroll
        for (int k = 0; k < KCONV; k++) acc += ws[k] * sv[(tl + k)*64 + d];
        Op[i] += acc;
    }
}

__global__ void merge_kernel(const float* __restrict__ O, float* __restrict__ OC)
{
    long long idx = (long long)blockIdx.x * blockDim.x + threadIdx.x;
    int c = (int)(idx & 511);
    int n = (int)((idx >> 9) & (NF - 1));
    int b = (int)(idx >> 22);
    int h = c >> 6, d = c & 63;
    OC[idx] = O[(((long long)(b*NHEADS + h))*NF + n)*DH + d];
}

__global__ void final_kernel(const float* __restrict__ X, const float* __restrict__ g,
                             const float* __restrict__ bt, const float* __restrict__ w2,
                             const float* __restrict__ b2, float* __restrict__ out)
{
    int b = blockIdx.x;
    int tid = threadIdx.x;
    const float* x = X + (long long)b*NF*DMODEL;
    float4 v = ((const float4*)x)[tid];
    float s = v.x+v.y+v.z+v.w;
    float q = v.x*v.x + v.y*v.y + v.z*v.z + v.w*v.w;
    #pragma unroll
    for (int o = 16; o; o >>= 1) {
        s += __shfl_xor_sync(0xffffffffu, s, o);
        q += __shfl_xor_sync(0xffffffffu, q, o);
    }
    __shared__ float ss[4], qq[4];
    if ((tid & 31) == 0) { ss[tid>>5] = s; qq[tid>>5] = q; }
    __syncthreads();
    s = ss[0]+ss[1]+ss[2]+ss[3];
    q = qq[0]+qq[1]+qq[2]+qq[3];
    float mu = s * (1.f/DMODEL);
    float var = q * (1.f/DMODEL) - mu*mu;
    float rs = rsqrtf(var + 1e-5f);
    __shared__ float xn[DMODEL];
    float4 gv = ((const float4*)g)[tid];
    float4 bv = ((const float4*)bt)[tid];
    xn[tid*4+0] = (v.x-mu)*rs*gv.x + bv.x;
    xn[tid*4+1] = (v.y-mu)*rs*gv.y + bv.y;
    xn[tid*4+2] = (v.z-mu)*rs*gv.z + bv.z;
    xn[tid*4+3] = (v.w-mu)*rs*gv.w + bv.w;
    __syncthreads();
    float s0 = 0.f, s1 = 0.f;
    for (int d = tid; d < DMODEL; d += 128) {
        float xv = xn[d];
        s0 += xv * w2[d*2+0];
        s1 += xv * w2[d*2+1];
    }
    __shared__ float r0[128], r1[128];
    r0[tid] = s0; r1[tid] = s1;
    __syncthreads();
    for (int st = 64; st; st >>= 1) {
        if (tid < st) { r0[tid] += r0[tid+st]; r1[tid] += r1[tid+st]; }
        __syncthreads();
    }
    if (tid == 0) {
        out[b*2+0] = r0[0] + b2[0];
        out[b*2+1] = r1[0] + b2[1];
    }
}

// ------------------------------ host side ----------------------------------
struct Bufs {
    float *X,*XLN,*QKV,*QL,*KL,*S1,*S3,*S2,*T,*U,*Rb,*Z,*Z2,*W,*Wp,*O,*OC,*RS1,*RS3,*scal;
    __nv_bfloat16 *Ah,*Al,*Bh,*Bl;
};

static Bufs init_bufs()
{
    Bufs b;
    cudaGetSymbolAddress((void**)&b.X,   g_X);
    cudaGetSymbolAddress((void**)&b.XLN, g_XLN);
    cudaGetSymbolAddress((void**)&b.QKV, g_QKV);
    cudaGetSymbolAddress((void**)&b.QL,  g_QL);
    cudaGetSymbolAddress((void**)&b.KL,  g_KL);
    cudaGetSymbolAddress((void**)&b.S1,  g_S1);
    cudaGetSymbolAddress((void**)&b.S3,  g_S3);
    cudaGetSymbolAddress((void**)&b.S2,  g_S2);
    cudaGetSymbolAddress((void**)&b.T,   g_T);
    cudaGetSymbolAddress((void**)&b.U,   g_U);
    cudaGetSymbolAddress((void**)&b.Rb,  g_R);
    cudaGetSymbolAddress((void**)&b.Z,   g_Z);
    cudaGetSymbolAddress((void**)&b.Z2,  g_Z2);
    cudaGetSymbolAddress((void**)&b.W,   g_W);
    cudaGetSymbolAddress((void**)&b.Wp,  g_Wp);
    cudaGetSymbolAddress((void**)&b.O,   g_O);
    cudaGetSymbolAddress((void**)&b.OC,  g_OC);
    cudaGetSymbolAddress((void**)&b.RS1, g_RS1);
    cudaGetSymbolAddress((void**)&b.RS3, g_RS3);
    cudaGetSymbolAddress((void**)&b.scal,g_scal);
    cudaGetSymbolAddress((void**)&b.Ah,  g_Ah);
    cudaGetSymbolAddress((void**)&b.Al,  g_Al);
    cudaGetSymbolAddress((void**)&b.Bh,  g_Bh);
    cudaGetSymbolAddress((void**)&b.Bl,  g_Bl);
    return b;
}

static inline void gemm_call(int bm, const float* A, const float* B, float* C,
    int M, int N, int K, int lda, int ldb, int ldc, int nb,
    long long sAb, long long sAh, long long sBb, long long sBh,
    long long sCb, long long sCh,
    const float* bias, const float* resid, int ldr,
    float alpha, int relu, bool transb,
    int nsplit = 1, int Kc = 0, long long sSp = 0,
    const float* rs = nullptr, int rsStride = 0,
    float* aux = nullptr, float diagc = 0.f)
{
    dim3 gr((N + 127)/128, (M + bm - 1)/bm, nb * nsplit);
    if (bm == 128) {
        if (nsplit > 1) {
            if (transb) sgemm<128,true ,true ><<<gr,256>>>(A,B,C,M,N,K,lda,ldb,ldc,sAb,sAh,sBb,sBh,sCb,sCh,bias,resid,ldr,alpha,relu,nsplit,Kc,sSp,rs,rsStride,aux,diagc);
            else        sgemm<128,false,true ><<<gr,256>>>(A,B,C,M,N,K,lda,ldb,ldc,sAb,sAh,sBb,sBh,sCb,sCh,bias,resid,ldr,alpha,relu,nsplit,Kc,sSp,rs,rsStride,aux,diagc);
        } else {
            if (transb) sgemm<128,true ,false><<<gr,256>>>(A,B,C,M,N,K,lda,ldb,ldc,sAb,sAh,sBb,sBh,sCb,sCh,bias,resid,ldr,alpha,relu,1,0,0,rs,rsStride,aux,diagc);
            else        sgemm<128,false,false><<<gr,256>>>(A,B,C,M,N,K,lda,ldb,ldc,sAb,sAh,sBb,sBh,sCb,sCh,bias,resid,ldr,alpha,relu,1,0,0,rs,rsStride,aux,diagc);
        }
    } else {
        if (nsplit > 1) {
            if (transb) sgemm<64,true ,true ><<<gr,256>>>(A,B,C,M,N,K,lda,ldb,ldc,sAb,sAh,sBb,sBh,sCb,sCh,bias,resid,ldr,alpha,relu,nsplit,Kc,sSp,rs,rsStride,aux,diagc);
            else        sgemm<64,false,true ><<<gr,256>>>(A,B,C,M,N,K,lda,ldb,ldc,sAb,sAh,sBb,sBh,sCb,sCh,bias,resid,ldr,alpha,relu,nsplit,Kc,sSp,rs,rsStride,aux,diagc);
        } else {
            if (transb) sgemm<64,true ,false><<<gr,256>>>(A,B,C,M,N,K,lda,ldb,ldc,sAb,sAh,sBb,sBh,sCb,sCh,bias,resid,ldr,alpha,relu,1,0,0,rs,rsStride,aux,diagc);
            else        sgemm<64,false,false><<<gr,256>>>(A,B,C,M,N,K,lda,ldb,ldc,sAb,sAh,sBb,sBh,sCb,sCh,bias,resid,ldr,alpha,relu,1,0,0,rs,rsStride,aux,diagc);
        }
    }
}

static inline void mma_call(const Bufs& bu, int M, int N, int K, float* C, int ldc,
                            long long sA, long long sB, long long sC, int nz,
                            const float* bias, const float* resid, int ldr)
{
    dim3 gr(N/128, M/128, nz);
    mma_gemm<<<gr,256>>>(bu.Ah, bu.Al, bu.Bh, bu.Bl, C, K, ldc,
                         sA, sB, sC, bias, resid, ldr);
}

static void run_layer(const Bufs& bu, int L, void* const* d_in)
{
    const float* lng  = (const float*)d_in[4] + (size_t)L*DMODEL;
    const float* lnb  = (const float*)d_in[5] + (size_t)L*DMODEL;
    const float* wqkv = (const float*)d_in[6] + (size_t)L*DMODEL*QKVW;
    const float* wout = (const float*)d_in[7] + (size_t)L*DMODEL*DMODEL;
    const float* bout = (const float*)d_in[8] + (size_t)L*DMODEL;
    const float* cw   = (const float*)d_in[9] + (size_t)L*NHEADS*KCONV;

    const long long sQKVb = (long long)NF*QKVW;
    const long long sLh = (long long)NLAND*DH;
    const long long sLb = (long long)NHEADS*sLh;
    const long long sS1h = (long long)NF*NLAND;
    const long long sS1b = (long long)NHEADS*sS1h;
    const long long sS3h = (long long)NLAND*NF;
    const long long sS3b = (long long)NHEADS*sS3h;
    const long long sm = (long long)NLAND*NLAND;
    const long long smb = (long long)NHEADS*sm;
    const long long sOh = (long long)NF*DH;
    const long long sOb = (long long)NHEADS*sOh;

    // x_ln = LN(x)
    ln_kernel<<<NROWS,128>>>(bu.X, bu.XLN, lng, lnb);

    // ---- QKV = x_ln @ w_qkv  (tensor cores) ----
    cvt_a_kernel<<<dim3((NROWS*DMODEL)/256,1),256>>>(bu.XLN, bu.Ah, bu.Al,
        9, DMODEL, 0, 0, (long long)NROWS*DMODEL, nullptr, 0, 1.f);
    cvt_t_kernel<<<dim3(QKVW/32, DMODEL/32, 1), dim3(32,8)>>>(wqkv, bu.Bh, bu.Bl,
        DMODEL, QKVW, 0);
    mma_call(bu, NROWS, QKVW, DMODEL, bu.QKV, QKVW, 0, 0, 0, 1, nullptr, nullptr, 0);

    // landmarks
    landmark_kernel<<<dim3(NLAND,NBH),64>>>(bu.QKV, bu.QL, 0);
    landmark_kernel<<<dim3(NLAND,NBH),64>>>(bu.QKV, bu.KL, DMODEL);

    // ---- sim1 = (q*scale) @ k_l^T  (tensor cores; 0.125 folded into q cvt) ----
    cvt_a_kernel<<<dim3((NF*DH)/256, NBH),256>>>(bu.QKV, bu.Ah, bu.Al,
        6, QKVW, sQKVb, DH, (long long)NF*DH, nullptr, 0, 0.125f);
    cvt_a_kernel<<<dim3((NLAND*DH)/256, NBH),256>>>(bu.KL, bu.Bh, bu.Bl,
        6, DH, 8*sLh, sLh, sLh, nullptr, 0, 1.f);
    mma_call(bu, NF, NLAND, DH, bu.S1, NLAND, (long long)NF*DH, sLh, sS1h, NBH,
             nullptr, nullptr, 0);

    // sim2 = (q_l*scale) @ k_l^T  (scalar)
    gemm_call(64, bu.QL, bu.KL, bu.S2, NLAND, NLAND, DH, DH, DH, NLAND, NBH,
              sLb, sLh, sLb, sLh, smb, sm, nullptr,nullptr,0, 0.125f,0,true);
    // sim3 = (q_l*scale) @ k^T  (scalar)
    gemm_call(64, bu.QL, bu.QKV + DMODEL, bu.S3, NLAND, NF, DH, DH, QKVW, NF, NBH,
              sLb, sLh, sQKVb, DH, sS3b, sS3h, nullptr,nullptr,0, 0.125f,0,true);

    // softmaxes: S1/S3 keep exp + rowscale; S2 fully normalized
    softmax2_kernel<<<NBH*NF,256>>>(bu.S1, NLAND, bu.RS1);
    softmax_kernel<<<NBH*NLAND,256>>>(bu.S2, NLAND);
    softmax2_kernel<<<NBH*NLAND,256>>>(bu.S3, NF, bu.RS3);

    // Moore-Penrose pinv (scalar Newton-Schulz with fused diag epilogues)
    cudaMemsetAsync(bu.scal, 0, 2*sizeof(float));
    pinv_reduce_kernel<<<NBH,256>>>(bu.S2, bu.scal);
    zinit_kernel<<<(NBH*NLAND*NLAND)/256,256>>>(bu.Z, bu.S2, bu.scal);
    float* za = bu.Z;
    float* zb = bu.Z2;
    for (int it = 0; it < 6; it++) {
        gemm_call(64, bu.S2, za, bu.U, NLAND,NLAND,NLAND, NLAND,NLAND,NLAND, NBH,
                  smb,sm, smb,sm, smb,sm, nullptr,nullptr,0, 1.f,0,false,
                  1,0,0, nullptr,0, bu.T, 7.f);
        gemm_call(64, bu.T, bu.U, bu.Rb, NLAND,NLAND,NLAND, NLAND,NLAND,NLAND, NBH,
                  smb,sm, smb,sm, smb,sm, nullptr,nullptr,0, 1.f,0,false,
                  1,0,0, nullptr,0, nullptr, 15.f);
        gemm_call(64, bu.T, bu.Rb, bu.U, NLAND,NLAND,NLAND, NLAND,NLAND,NLAND, NBH,
                  smb,sm, smb,sm, smb,sm, nullptr,nullptr,0, 1.f,0,false,
                  1,0,0, nullptr,0, nullptr, 13.f);
        gemm_call(64, za, bu.U, zb, NLAND,NLAND,NLAND, NLAND,NLAND,NLAND, NBH,
                  smb,sm, smb,sm, smb,sm, nullptr,nullptr,0, 0.25f,0,false);
        float* tp = za; za = zb; zb = tp;
    }

    // W = attn3 @ v (scalar split-K; rowscale = 1/sum3)
    gemm_call(64, bu.S3, bu.QKV + 2*DMODEL, bu.Wp, NLAND, DH, NF, NF, QKVW, DH, NBH,
              sS3b, sS3h, sQKVb, DH, sLb, sLh, nullptr,nullptr,0, 1.f,0,false,
              8, 1024, (long long)NBH*NLAND*DH, bu.RS3, NLAND);
    reduce_split_kernel<<<(NBH*NLAND*DH)/256,256>>>(bu.Wp, bu.W, (long long)NBH*NLAND*DH);

    // ---- P = attn1 @ Z  (tensor cores; 1/sum1 folded into S1 cvt) ----
    cvt_a_kernel<<<dim3((NF*NLAND)/256, NBH),256>>>(bu.S1, bu.Ah, bu.Al,
        8, NLAND, 8*sS1h, sS1h, sS1h, bu.RS1, NF, 1.f);
    cvt_t_kernel<<<dim3(NLAND/32, NLAND/32, NBH), dim3(32,8)>>>(za, bu.Bh, bu.Bl,
        NLAND, NLAND, sm);
    mma_call(bu, NF, NLAND, NLAND, bu.S3, NLAND, sS1h, sm, sS1h, NBH,
             nullptr, nullptr, 0);

    // O = P @ W  (scalar)
    gemm_call(128, bu.S3, bu.W, bu.O, NF, DH, NLAND, NLAND, DH, DH, NBH,
              sS1b, sS1h, sLb, sLh, sOb, sOh, nullptr,nullptr,0, 1.f,0,false);
    // O += depthwise conv of V
    conv_kernel<<<dim3(NF/128, NHEADS, NBATCH),256>>>(bu.O, bu.QKV, cw);
    // concat heads
    merge_kernel<<<((long long)NBATCH*NF*DMODEL)/256,256>>>(bu.O, bu.OC);

    // ---- x = x + (OC @ w_out + b_out)  (tensor cores) ----
    cvt_a_kernel<<<dim3((NROWS*DMODEL)/256,1),256>>>(bu.OC, bu.Ah, bu.Al,
        9, DMODEL, 0, 0, (long long)NROWS*DMODEL, nullptr, 0, 1.f);
    cvt_t_kernel<<<dim3(DMODEL/32, DMODEL/32, 1), dim3(32,8)>>>(wout, bu.Bh, bu.Bl,
        DMODEL, DMODEL, 0);
    mma_call(bu, NROWS, DMODEL, DMODEL, bu.X, DMODEL, 0, 0, 0, 1, bout, bu.X, DMODEL);
}

extern "C" void kernel_launch(void* const* d_in, const int* in_sizes, int n_in,
                              void* d_out, int out_size)
{
    static Bufs bu = init_bufs();
    const float* h    = (const float*)d_in[0];
    const float* w1   = (const float*)d_in[1];
    const float* b1   = (const float*)d_in[2];
    const float* cls  = (const float*)d_in[3];
    const float* fng  = (const float*)d_in[10];
    const float* fnb  = (const float*)d_in[11];
    const float* w2   = (const float*)d_in[12];
    const float* b2   = (const float*)d_in[13];

    // x = relu(h @ w1 + b1) rows 1..8191 per batch (scalar)
    gemm_call(128, h, w1, bu.X + DMODEL, 8191, DMODEL, 1024, 1024, DMODEL, DMODEL, 2,
              0, (long long)8191*1024, 0, 0, 0, (long long)NF*DMODEL,
              b1, nullptr, 0, 1.f, 1, false);
    cls_copy_kernel<<<1,512>>>(bu.X, cls);

    run_layer(bu, 0, d_in);
    run_layer(bu, 1, d_in);

    final_kernel<<<NBATCH,128>>>(bu.X, fng, fnb, w2, b2, (float*)d_out);
}

// round 10
// speedup vs baseline: 1.5766x; 1.1015x over previous
#include <cuda_runtime.h>
#include <cuda_bf16.h>

#define NF 8192
#define DMODEL 512
#define NHEADS 8
#define DH 64
#define NLAND 256
#define NBATCH 2
#define NBH 16
#define QKVW 1536
#define NROWS (NBATCH*NF)
#define KCONV 33

// ------------------------- scratch (device globals; no allocs allowed) -----
__device__ __align__(16) float g_X  [(size_t)NBATCH*NF*DMODEL];
__device__ __align__(16) float g_XLN[(size_t)NBATCH*NF*DMODEL];
__device__ __align__(16) float g_QKV[(size_t)NBATCH*NF*QKVW];
__device__ __align__(16) float g_QL [(size_t)NBH*NLAND*DH];
__device__ __align__(16) float g_KL [(size_t)NBH*NLAND*DH];
__device__ __align__(16) float g_S1 [(size_t)NBH*NF*NLAND];
__device__ __align__(16) float g_S3 [(size_t)NBH*NF*NLAND];
__device__ __align__(16) float g_S2 [(size_t)NBH*NLAND*NLAND];
__device__ __align__(16) float g_T  [(size_t)NBH*NLAND*NLAND];
__device__ __align__(16) float g_U  [(size_t)NBH*NLAND*NLAND];
__device__ __align__(16) float g_R  [(size_t)NBH*NLAND*NLAND];
__device__ __align__(16) float g_Z  [(size_t)NBH*NLAND*NLAND];
__device__ __align__(16) float g_Z2 [(size_t)NBH*NLAND*NLAND];
__device__ __align__(16) float g_W  [(size_t)NBH*NLAND*DH];
__device__ __align__(16) float g_Wp [(size_t)8*NBH*NLAND*DH];
__device__ __align__(16) float g_O  [(size_t)NBH*NF*DH];
__device__ __align__(16) float g_OC [(size_t)NBATCH*NF*DMODEL];
__device__ __align__(16) float g_RS3[(size_t)NBH*NLAND];
__device__ float g_scal[2];
// bf16 split operand buffers for the tensor-core path
__device__ __align__(16) __nv_bfloat16 g_Ah[(size_t)NBH*NF*NLAND];
__device__ __align__(16) __nv_bfloat16 g_Al[(size_t)NBH*NF*NLAND];
__device__ __align__(16) __nv_bfloat16 g_Bh[(size_t)NBH*NF*DH];
__device__ __align__(16) __nv_bfloat16 g_Bl[(size_t)NBH*NF*DH];

// ------------------------- f32x2 packed helpers ----------------------------
__device__ __forceinline__ unsigned long long pack2_dup(float x)
{
    unsigned long long r;
    unsigned int u = __float_as_uint(x);
    asm("mov.b64 %0, {%1, %1};" : "=l"(r) : "r"(u));
    return r;
}
__device__ __forceinline__ void ffma2(unsigned long long& d,
                                      unsigned long long a, unsigned long long b)
{
    asm("fma.rn.f32x2 %0, %1, %2, %0;" : "+l"(d) : "l"(a), "l"(b));
}
__device__ __forceinline__ float2 unpack2(unsigned long long v)
{
    unsigned int lo, hi;
    asm("mov.b64 {%0, %1}, %2;" : "=r"(lo), "=r"(hi) : "l"(v));
    return make_float2(__uint_as_float(lo), __uint_as_float(hi));
}

// -------- warp mma helper: m16n8k16 bf16 x bf16 -> f32 accumulate ----------
#define MMA16816(d, A, B)                                                      \
    asm volatile("mma.sync.aligned.m16n8k16.row.col.f32.bf16.bf16.f32 "        \
                 "{%0,%1,%2,%3},{%4,%5,%6,%7},{%8,%9},{%0,%1,%2,%3};"          \
                 : "+f"((d)[0]), "+f"((d)[1]), "+f"((d)[2]), "+f"((d)[3])      \
                 : "r"((A)[0]), "r"((A)[1]), "r"((A)[2]), "r"((A)[3]),         \
                   "r"((B)[0]), "r"((B)[1]))

// ---------------- tensor-core bf16-split GEMM: C[M,N] = A@B^T ---------------
__global__ __launch_bounds__(256, 2) void mma_gemm(
    const __nv_bfloat16* __restrict__ Ah, const __nv_bfloat16* __restrict__ Al,
    const __nv_bfloat16* __restrict__ Bh, const __nv_bfloat16* __restrict__ Bl,
    float* __restrict__ C, int Kv, int ldc,
    long long sA, long long sB, long long sC,
    const float* __restrict__ bias, const float* __restrict__ resid, int ldr,
    int relu)
{
    __shared__ __nv_bfloat16 sAh[2][128*16], sAl[2][128*16];
    __shared__ __nv_bfloat16 sBh[2][128*16], sBl[2][128*16];

    int tid = threadIdx.x;
    int lane = tid & 31, wid = tid >> 5;
    int z = blockIdx.z;
    int m0 = blockIdx.y * 128, n0 = blockIdx.x * 128;
    const __nv_bfloat16* pAh = Ah + (long long)z*sA + (long long)m0*Kv;
    const __nv_bfloat16* pAl = Al + (long long)z*sA + (long long)m0*Kv;
    const __nv_bfloat16* pBh = Bh + (long long)z*sB + (long long)n0*Kv;
    const __nv_bfloat16* pBl = Bl + (long long)z*sB + (long long)n0*Kv;
    float* Cz = C + (long long)z*sC;

    int row = tid >> 1, half = tid & 1;
    long long goff = (long long)row*Kv + half*8;
    int soff = row*16 + half*8;

    uint4 va_h, va_l, vb_h, vb_l;
    auto load = [&](int kk) {
        va_h = *(const uint4*)(pAh + goff + kk);
        va_l = *(const uint4*)(pAl + goff + kk);
        vb_h = *(const uint4*)(pBh + goff + kk);
        vb_l = *(const uint4*)(pBl + goff + kk);
    };
    auto store = [&](int pb) {
        *(uint4*)&sAh[pb][soff] = va_h;
        *(uint4*)&sAl[pb][soff] = va_l;
        *(uint4*)&sBh[pb][soff] = vb_h;
        *(uint4*)&sBl[pb][soff] = vb_l;
    };

    float acc[2][8][4];
    #pragma unroll
    for (int i = 0; i < 2; i++)
        #pragma unroll
        for (int j = 0; j < 8; j++)
            #pragma unroll
            for (int e = 0; e < 4; e++) acc[i][j][e] = 0.f;

    int warpM = (wid & 3) * 32, warpN = (wid >> 2) * 64;
    int ar = warpM + (lane >> 2);
    int kc = 2 * (lane & 3);
    int bro = (lane >> 2);

    int nchunk = Kv >> 4;
    load(0);
    store(0);
    __syncthreads();

    for (int t = 0; t < nchunk; t++) {
        if (t + 1 < nchunk) load((t + 1) << 4);
        int pb = t & 1;
        const __nv_bfloat16* a_h = sAh[pb];
        const __nv_bfloat16* a_l = sAl[pb];
        const __nv_bfloat16* b_h = sBh[pb];
        const __nv_bfloat16* b_l = sBl[pb];

        unsigned Af[2][4], Ag[2][4];
        #pragma unroll
        for (int mt = 0; mt < 2; mt++) {
            int base = (ar + mt*16)*16 + kc;
            Af[mt][0] = *(const unsigned*)&a_h[base];
            Af[mt][1] = *(const unsigned*)&a_h[base + 128];
            Af[mt][2] = *(const unsigned*)&a_h[base + 8];
            Af[mt][3] = *(const unsigned*)&a_h[base + 136];
            Ag[mt][0] = *(const unsigned*)&a_l[base];
            Ag[mt][1] = *(const unsigned*)&a_l[base + 128];
            Ag[mt][2] = *(const unsigned*)&a_l[base + 8];
            Ag[mt][3] = *(const unsigned*)&a_l[base + 136];
        }
        #pragma unroll
        for (int nt = 0; nt < 8; nt++) {
            int bb = (warpN + nt*8 + bro)*16 + kc;
            unsigned bh[2], bl[2];
            bh[0] = *(const unsigned*)&b_h[bb];
            bh[1] = *(const unsigned*)&b_h[bb + 8];
            bl[0] = *(const unsigned*)&b_l[bb];
            bl[1] = *(const unsigned*)&b_l[bb + 8];
            #pragma unroll
            for (int mt = 0; mt < 2; mt++) {
                MMA16816(acc[mt][nt], Af[mt], bh);
                MMA16816(acc[mt][nt], Ag[mt], bh);
                MMA16816(acc[mt][nt], Af[mt], bl);
            }
        }
        if (t + 1 < nchunk) {
            store((t + 1) & 1);
            __syncthreads();
        }
    }

    // epilogue
    #pragma unroll
    for (int mt = 0; mt < 2; mt++) {
        int r0 = m0 + warpM + mt*16 + (lane >> 2);
        #pragma unroll
        for (int nt = 0; nt < 8; nt++) {
            int c0 = n0 + warpN + nt*8 + kc;
            float v0 = acc[mt][nt][0], v1 = acc[mt][nt][1];
            float v2 = acc[mt][nt][2], v3 = acc[mt][nt][3];
            if (bias) {
                float b0 = bias[c0], b1 = bias[c0 + 1];
                v0 += b0; v1 += b1; v2 += b0; v3 += b1;
            }
            if (resid) {
                v0 += resid[(long long)r0*ldr + c0];
                v1 += resid[(long long)r0*ldr + c0 + 1];
                v2 += resid[(long long)(r0 + 8)*ldr + c0];
                v3 += resid[(long long)(r0 + 8)*ldr + c0 + 1];
            }
            if (relu) {
                v0 = fmaxf(v0, 0.f); v1 = fmaxf(v1, 0.f);
                v2 = fmaxf(v2, 0.f); v3 = fmaxf(v3, 0.f);
            }
            *(float2*)&Cz[(long long)r0*ldc + c0] = make_float2(v0, v1);
            *(float2*)&Cz[(long long)(r0 + 8)*ldc + c0] = make_float2(v2, v3);
        }
    }
}

// ------------- fp32 -> bf16 hi/lo conversion (straight, batched) ------------
__global__ void cvt_a_kernel(const float* __restrict__ src,
    __nv_bfloat16* __restrict__ hi, __nv_bfloat16* __restrict__ lo,
    int kshift, int lds, long long sb, long long sh, long long RK,
    float scale)
{
    long long idx = (long long)blockIdx.x * 256 + threadIdx.x;
    int z = blockIdx.y;
    int r = (int)(idx >> kshift);
    int k = (int)(idx & ((1 << kshift) - 1));
    float v = src[(long long)(z>>3)*sb + (long long)(z&7)*sh + (long long)r*lds + k] * scale;
    __nv_bfloat16 h = __float2bfloat16(v);
    float rem = v - __bfloat162float(h);
    long long o = (long long)z*RK + idx;
    hi[o] = h;
    lo[o] = __float2bfloat16(rem);
}

// ------- embed input: h (B,8191,1024) -> padded bf16 split A [16384,1024] ---
// row r: b = r>>13, t = r&8191; t==0 -> zeros (cls slot, overwritten later)
__global__ void cvt_h_kernel(const float* __restrict__ src,
    __nv_bfloat16* __restrict__ hi, __nv_bfloat16* __restrict__ lo)
{
    long long idx = (long long)blockIdx.x * 256 + threadIdx.x;
    int r = (int)(idx >> 10);
    int k = (int)(idx & 1023);
    int b = r >> 13, t = r & 8191;
    float v = 0.f;
    if (t > 0)
        v = src[((long long)b*8191 + (t - 1))*1024 + k];
    __nv_bfloat16 h = __float2bfloat16(v);
    float rem = v - __bfloat162float(h);
    hi[idx] = h;
    lo[idx] = __float2bfloat16(rem);
}

// ------ fp32 [K,N] -> bf16 hi/lo [N,K] (transpose conversion, batched) ------
__global__ void cvt_t_kernel(const float* __restrict__ src,
    __nv_bfloat16* __restrict__ hi, __nv_bfloat16* __restrict__ lo,
    int Kv, int Nv, long long sz)
{
    __shared__ float t[32][33];
    int z = blockIdx.z;
    const float* s = src + (long long)z*sz;
    int n = blockIdx.x*32 + threadIdx.x;
    #pragma unroll
    for (int i = 0; i < 4; i++) {
        int k = blockIdx.y*32 + threadIdx.y + i*8;
        t[threadIdx.y + i*8][threadIdx.x] = s[(long long)k*Nv + n];
    }
    __syncthreads();
    int k2 = blockIdx.y*32 + threadIdx.x;
    #pragma unroll
    for (int i = 0; i < 4; i++) {
        int n2 = blockIdx.x*32 + threadIdx.y + i*8;
        float v = t[threadIdx.x][threadIdx.y + i*8];
        __nv_bfloat16 h = __float2bfloat16(v);
        float rem = v - __bfloat162float(h);
        long long o = ((long long)z*Nv + n2)*Kv + k2;
        hi[o] = h;
        lo[o] = __float2bfloat16(rem);
    }
}

// -- softmax over 256 cols, writes NORMALIZED bf16 hi/lo directly (for S1) ---
__global__ void softmax_split_kernel(const float* __restrict__ X,
    __nv_bfloat16* __restrict__ hi, __nv_bfloat16* __restrict__ lo)
{
    long long row = blockIdx.x;
    int tid = threadIdx.x;   // 256, one col each
    float v = X[row*NLAND + tid];
    __shared__ float sred[8];
    float m = v;
    #pragma unroll
    for (int o = 16; o; o >>= 1) m = fmaxf(m, __shfl_xor_sync(0xffffffffu, m, o));
    if ((tid & 31) == 0) sred[tid>>5] = m;
    __syncthreads();
    m = fmaxf(fmaxf(fmaxf(sred[0], sred[1]), fmaxf(sred[2], sred[3])),
              fmaxf(fmaxf(sred[4], sred[5]), fmaxf(sred[6], sred[7])));
    float e = __expf(v - m);
    float s = e;
    #pragma unroll
    for (int o = 16; o; o >>= 1) s += __shfl_xor_sync(0xffffffffu, s, o);
    __syncthreads();
    if ((tid & 31) == 0) sred[tid>>5] = s;
    __syncthreads();
    s = sred[0]+sred[1]+sred[2]+sred[3]+sred[4]+sred[5]+sred[6]+sred[7];
    float ov = e / s;
    __nv_bfloat16 h = __float2bfloat16(ov);
    float rem = ov - __bfloat162float(h);
    long long o2 = row*NLAND + tid;
    hi[o2] = h;
    lo[o2] = __float2bfloat16(rem);
}

// ------------------------------- SGEMM (scalar f32x2) -----------------------
template<int BM, bool TRANSB, bool SPLITK>
__global__ __launch_bounds__(256) void sgemm(
    const float* __restrict__ A, const float* __restrict__ B, float* __restrict__ C,
    int M, int N, int K, int lda, int ldb, int ldc,
    long long sAb, long long sAh, long long sBb, long long sBh,
    long long sCb, long long sCh,
    const float* __restrict__ bias, const float* __restrict__ resid, int ldr,
    float alpha, int relu, int nsplit, int Kc, long long sSp,
    const float* __restrict__ rsA, int rsStride,
    float* __restrict__ aux, float diagc)
{
    constexpr int NI = BM / 16;
    int zAll = blockIdx.z;
    int zb = zAll / nsplit;
    int sp = zAll - zb * nsplit;
    int bb = zb >> 3, hh = zb & 7;
    const float* Ap = A + bb*sAb + hh*sAh;
    const float* Bp = B + bb*sBb + hh*sBh;
    float*       Cp = C + bb*sCb + hh*sCh + (SPLITK ? (long long)sp * sSp : 0LL);
    float*       Xp = aux ? aux + bb*sCb + hh*sCh : (float*)0;
    const float* rsp = rsA ? rsA + (long long)zb * rsStride : (const float*)0;

    int bm0 = blockIdx.y * BM;
    int bn0 = blockIdx.x * 128;
    int k0   = SPLITK ? sp * Kc : 0;
    int kEnd = SPLITK ? min(K, k0 + Kc) : K;

    __shared__ __align__(16) float As[2][8][128];
    __shared__ __align__(16) float Bs[2][8][128];

    int tid = threadIdx.x;
    int tx = tid & 15, ty = tid >> 4;
    unsigned long long acc[NI][4];
    #pragma unroll
    for (int i = 0; i < NI; i++)
        #pragma unroll
        for (int j = 0; j < 4; j++) acc[i][j] = 0ULL;

    int arow = bm0 + (tid >> 1);
    int akq  = (tid & 1) * 4;
    int bk = tid >> 5;
    int bn = (tid & 31) * 4;
    int gc = bn0 + bn;
    int nB = bn0 + (tid >> 1);

    float4 avS, bvS;

    auto loadTile = [&](int kk) {
        avS = make_float4(0.f,0.f,0.f,0.f);
        if ((BM == 128 || tid < 128) && arow < M)
            avS = *(const float4*)(Ap + (long long)arow*lda + kk + akq);
        if (TRANSB) {
            bvS = make_float4(0.f,0.f,0.f,0.f);
            if (nB < N) bvS = *(const float4*)(Bp + (long long)nB*ldb + kk + akq);
        } else {
            const float* p = Bp + (long long)(kk + bk)*ldb + gc;
            if (gc + 3 < N) bvS = *(const float4*)p;
            else {
                bvS.x = (gc+0 < N) ? p[0] : 0.f;
                bvS.y = (gc+1 < N) ? p[1] : 0.f;
                bvS.z = (gc+2 < N) ? p[2] : 0.f;
                bvS.w = (gc+3 < N) ? p[3] : 0.f;
            }
        }
    };
    auto storeTile = [&](int pb) {
        if (BM == 128 || tid < 128) {
            As[pb][akq+0][tid>>1] = avS.x;
            As[pb][akq+1][tid>>1] = avS.y;
            As[pb][akq+2][tid>>1] = avS.z;
            As[pb][akq+3][tid>>1] = avS.w;
        }
        if (TRANSB) {
            Bs[pb][akq+0][tid>>1] = bvS.x;
            Bs[pb][akq+1][tid>>1] = bvS.y;
            Bs[pb][akq+2][tid>>1] = bvS.z;
            Bs[pb][akq+3][tid>>1] = bvS.w;
        } else {
            *(float4*)&Bs[pb][bk][bn] = bvS;
        }
    };

    int nt = (kEnd - k0) >> 3;
    loadTile(k0);
    storeTile(0);
    __syncthreads();

    for (int t = 0; t < nt; t++) {
        if (t + 1 < nt) loadTile(k0 + ((t + 1) << 3));
        int pb = t & 1;
        #pragma unroll
        for (int k = 0; k < 8; k++) {
            float ra[NI];
            *(float4*)&ra[0] = *(const float4*)&As[pb][k][ty*4];
            if (BM == 128)
                *(float4*)&ra[4] = *(const float4*)&As[pb][k][64 + ty*4];
            ulonglong2 bq0 = *(const ulonglong2*)&Bs[pb][k][tx*4];
            ulonglong2 bq1 = *(const ulonglong2*)&Bs[pb][k][64 + tx*4];
            unsigned long long rb0 = bq0.x, rb1 = bq0.y, rb2 = bq1.x, rb3 = bq1.y;
            #pragma unroll
            for (int i = 0; i < NI; i++) {
                unsigned long long aa = pack2_dup(ra[i]);
                ffma2(acc[i][0], aa, rb0);
                ffma2(acc[i][1], aa, rb1);
                ffma2(acc[i][2], aa, rb2);
                ffma2(acc[i][3], aa, rb3);
            }
        }
        if (t + 1 < nt) {
            storeTile((t + 1) & 1);
            __syncthreads();
        }
    }

    #pragma unroll
    for (int i = 0; i < NI; i++) {
        int r = bm0 + ((i < 4) ? (ty*4 + i) : (64 + ty*4 + i - 4));
        if (r >= M) continue;
        float rsv = rsp ? rsp[r] : 1.f;
        #pragma unroll
        for (int jp = 0; jp < 4; jp++) {
            float2 pv = unpack2(acc[i][jp]);
            int cbase = bn0 + ((jp < 2) ? (tx*4 + jp*2) : (64 + tx*4 + (jp-2)*2));
            float vv[2] = {pv.x, pv.y};
            #pragma unroll
            for (int e = 0; e < 2; e++) {
                int c = cbase + e;
                if (c >= N) continue;
                float v = vv[e] * alpha;
                long long off = (long long)r*ldc + c;
                if (SPLITK) {
                    if (rsp) v *= rsv;
                    Cp[off] = v;
                } else {
                    if (rsp)  v *= rsv;
                    if (Xp)   Xp[off] = v;
                    if (diagc != 0.f) v = (r == c ? diagc : 0.f) - v;
                    if (bias)  v += bias[c];
                    if (resid) v += resid[(long long)r*ldr + c];
                    if (relu)  v = fmaxf(v, 0.f);
                    Cp[off] = v;
                }
            }
        }
    }
}

// ------------------------------ helpers ------------------------------------
__global__ void reduce_split_kernel(const float* __restrict__ Wp, float* __restrict__ W,
                                    long long stride)
{
    long long idx = (long long)blockIdx.x * blockDim.x + threadIdx.x;
    float s = 0.f;
    for (int k = 0; k < 8; k++) s += Wp[(long long)k*stride + idx];
    W[idx] = s;
}

__global__ void ln_kernel(const float* __restrict__ X, float* __restrict__ Y,
                          const float* __restrict__ g, const float* __restrict__ b)
{
    long long r = blockIdx.x;
    int tid = threadIdx.x;   // 128
    float4 v = ((const float4*)(X + r*DMODEL))[tid];
    float s = v.x+v.y+v.z+v.w;
    float q = v.x*v.x + v.y*v.y + v.z*v.z + v.w*v.w;
    #pragma unroll
    for (int o = 16; o; o >>= 1) {
        s += __shfl_xor_sync(0xffffffffu, s, o);
        q += __shfl_xor_sync(0xffffffffu, q, o);
    }
    __shared__ float ss[4], qq[4];
    if ((tid & 31) == 0) { ss[tid>>5] = s; qq[tid>>5] = q; }
    __syncthreads();
    s = ss[0]+ss[1]+ss[2]+ss[3];
    q = qq[0]+qq[1]+qq[2]+qq[3];
    float mu = s * (1.f/DMODEL);
    float var = q * (1.f/DMODEL) - mu*mu;
    float rs = rsqrtf(var + 1e-5f);
    float4 gv = ((const float4*)g)[tid];
    float4 bv = ((const float4*)b)[tid];
    float4 o;
    o.x = (v.x-mu)*rs*gv.x + bv.x;
    o.y = (v.y-mu)*rs*gv.y + bv.y;
    o.z = (v.z-mu)*rs*gv.z + bv.z;
    o.w = (v.w-mu)*rs*gv.w + bv.w;
    ((float4*)(Y + r*DMODEL))[tid] = o;
}

__global__ void cls_copy_kernel(float* __restrict__ X, const float* __restrict__ cls)
{
    int c = threadIdx.x;  // 512
    X[c] = cls[c];
    X[(long long)NF*DMODEL + c] = cls[c];
}

__global__ void landmark_kernel(const float* __restrict__ QKV, float* __restrict__ out, int off)
{
    int j = blockIdx.x;
    int z = blockIdx.y;
    int d = threadIdx.x;
    int b = z >> 3, h = z & 7;
    const float* base = QKV + ((long long)b*NF + (long long)j*32)*QKVW + off + h*DH + d;
    float s = 0.f;
    #pragma unroll
    for (int t = 0; t < 32; t++) s += base[(long long)t*QKVW];
    out[((long long)z*NLAND + j)*DH + d] = s * (1.f/32.f);
}

__global__ void softmax_kernel(float* __restrict__ X, int cols)
{
    long long row = blockIdx.x;
    float* p = X + row * cols;
    int tid = threadIdx.x;
    __shared__ float sred[8];
    __shared__ float sval;
    float m = -1e30f;
    for (int c = tid; c < cols; c += 256) m = fmaxf(m, p[c]);
    #pragma unroll
    for (int o = 16; o; o >>= 1) m = fmaxf(m, __shfl_xor_sync(0xffffffffu, m, o));
    if ((tid & 31) == 0) sred[tid>>5] = m;
    __syncthreads();
    if (tid == 0) {
        float mm = sred[0];
        for (int i = 1; i < 8; i++) mm = fmaxf(mm, sred[i]);
        sval = mm;
    }
    __syncthreads();
    m = sval;
    __syncthreads();
    float s = 0.f;
    for (int c = tid; c < cols; c += 256) {
        float e = __expf(p[c] - m);
        p[c] = e;
        s += e;
    }
    #pragma unroll
    for (int o = 16; o; o >>= 1) s += __shfl_xor_sync(0xffffffffu, s, o);
    if ((tid & 31) == 0) sred[tid>>5] = s;
    __syncthreads();
    if (tid == 0) {
        float t = 0.f;
        for (int i = 0; i < 8; i++) t += sred[i];
        sval = t;
    }
    __syncthreads();
    float inv = 1.f / sval;
    for (int c = tid; c < cols; c += 256) p[c] *= inv;
}

__global__ void softmax2_kernel(float* __restrict__ X, int cols, float* __restrict__ rs)
{
    long long row = blockIdx.x;
    float* p = X + row * cols;
    int tid = threadIdx.x;
    __shared__ float sred[8];
    __shared__ float sval;
    float m = -1e30f;
    for (int c = tid; c < cols; c += 256) m = fmaxf(m, p[c]);
    #pragma unroll
    for (int o = 16; o; o >>= 1) m = fmaxf(m, __shfl_xor_sync(0xffffffffu, m, o));
    if ((tid & 31) == 0) sred[tid>>5] = m;
    __syncthreads();
    if (tid == 0) {
        float mm = sred[0];
        for (int i = 1; i < 8; i++) mm = fmaxf(mm, sred[i]);
        sval = mm;
    }
    __syncthreads();
    m = sval;
    __syncthreads();
    float s = 0.f;
    for (int c = tid; c < cols; c += 256) {
        float e = __expf(p[c] - m);
        p[c] = e;
        s += e;
    }
    #pragma unroll
    for (int o = 16; o; o >>= 1) s += __shfl_xor_sync(0xffffffffu, s, o);
    if ((tid & 31) == 0) sred[tid>>5] = s;
    __syncthreads();
    if (tid == 0) {
        float t = 0.f;
        for (int i = 0; i < 8; i++) t += sred[i];
        rs[row] = 1.f / t;
    }
}

__device__ __forceinline__ void atomicMaxF(float* addr, float v)
{
    atomicMax((int*)addr, __float_as_int(v));
}

__global__ void pinv_reduce_kernel(const float* __restrict__ S2, float* __restrict__ scal)
{
    int z = blockIdx.x;
    int tid = threadIdx.x;
    const float* Mz = S2 + (long long)z * NLAND * NLAND;
    float rs = 0.f, cs = 0.f;
    for (int j = 0; j < NLAND; j++) rs += Mz[(long long)tid*NLAND + j];
    for (int i = 0; i < NLAND; i++) cs += Mz[(long long)i*NLAND + tid];
    __shared__ float sm[256];
    sm[tid] = rs; __syncthreads();
    for (int s = 128; s; s >>= 1) { if (tid < s) sm[tid] = fmaxf(sm[tid], sm[tid+s]); __syncthreads(); }
    if (tid == 0) atomicMaxF(&scal[0], sm[0]);
    __syncthreads();
    sm[tid] = cs; __syncthreads();
    for (int s = 128; s; s >>= 1) { if (tid < s) sm[tid] = fmaxf(sm[tid], sm[tid+s]); __syncthreads(); }
    if (tid == 0) atomicMaxF(&scal[1], sm[0]);
}

__global__ void zinit_kernel(float* __restrict__ Z, const float* __restrict__ S2,
                             const float* __restrict__ scal)
{
    long long idx = (long long)blockIdx.x * blockDim.x + threadIdx.x;
    float rcp = 1.f / (scal[0] * scal[1]);
    long long z = idx >> 16;
    int r = (int)((idx >> 8) & 255);
    int c = (int)(idx & 255);
    Z[idx] = S2[(z << 16) + ((long long)c << 8) + r] * rcp;
}

__global__ void conv_kernel(float* __restrict__ O, const float* __restrict__ QKV,
                            const float* __restrict__ cw)
{
    int t0 = blockIdx.x * 128;
    int h = blockIdx.y;
    int b = blockIdx.z;
    __shared__ float sv[160*64];
    __shared__ float ws[KCONV];
    int tid = threadIdx.x;
    if (tid < KCONV) ws[tid] = cw[h*KCONV + tid];
    for (int i = tid; i < 160*64; i += 256) {
        int tl = i >> 6, d = i & 63;
        int t = t0 + tl - 16;
        float v = 0.f;
        if (t >= 0 && t < NF)
            v = QKV[((long long)b*NF + t)*QKVW + 2*DMODEL + h*DH + d];
        sv[i] = v;
    }
    __syncthreads();
    float* Op = O + (((long long)(b*NHEADS + h))*NF + t0)*DH;
    for (int i = tid; i < 128*64; i += 256) {
        int tl = i >> 6, d = i & 63;
        float acc = 0.f;
        #pragma unroll
        for (int k = 0; k < KCONV; k++) acc += ws[k] * sv[(tl + k)*64 + d];
        Op[i] += acc;
    }
}

__global__ void merge_kernel(const float* __restrict__ O, float* __restrict__ OC)
{
    long long idx = (long long)blockIdx.x * blockDim.x + threadIdx.x;
    int c = (int)(idx & 511);
    int n = (int)((idx >> 9) & (NF - 1));
    int b = (int)(idx >> 22);
    int h = c >> 6, d = c & 63;
    OC[idx] = O[(((long long)(b*NHEADS + h))*NF + n)*DH + d];
}

__global__ void final_kernel(const float* __restrict__ X, const float* __restrict__ g,
                             const float* __restrict__ bt, const float* __restrict__ w2,
                             const float* __restrict__ b2, float* __restrict__ out)
{
    int b = blockIdx.x;
    int tid = threadIdx.x;
    const float* x = X + (long long)b*NF*DMODEL;
    float4 v = ((const float4*)x)[tid];
    float s = v.x+v.y+v.z+v.w;
    float q = v.x*v.x + v.y*v.y + v.z*v.z + v.w*v.w;
    #pragma unroll
    for (int o = 16; o; o >>= 1) {
        s += __shfl_xor_sync(0xffffffffu, s, o);
        q += __shfl_xor_sync(0xffffffffu, q, o);
    }
    __shared__ float ss[4], qq[4];
    if ((tid & 31) == 0) { ss[tid>>5] = s; qq[tid>>5] = q; }
    __syncthreads();
    s = ss[0]+ss[1]+ss[2]+ss[3];
    q = qq[0]+qq[1]+qq[2]+qq[3];
    float mu = s * (1.f/DMODEL);
    float var = q * (1.f/DMODEL) - mu*mu;
    float rs = rsqrtf(var + 1e-5f);
    __shared__ float xn[DMODEL];
    float4 gv = ((const float4*)g)[tid];
    float4 bv = ((const float4*)bt)[tid];
    xn[tid*4+0] = (v.x-mu)*rs*gv.x + bv.x;
    xn[tid*4+1] = (v.y-mu)*rs*gv.y + bv.y;
    xn[tid*4+2] = (v.z-mu)*rs*gv.z + bv.z;
    xn[tid*4+3] = (v.w-mu)*rs*gv.w + bv.w;
    __syncthreads();
    float s0 = 0.f, s1 = 0.f;
    for (int d = tid; d < DMODEL; d += 128) {
        float xv = xn[d];
        s0 += xv * w2[d*2+0];
        s1 += xv * w2[d*2+1];
    }
    __shared__ float r0[128], r1[128];
    r0[tid] = s0; r1[tid] = s1;
    __syncthreads();
    for (int st = 64; st; st >>= 1) {
        if (tid < st) { r0[tid] += r0[tid+st]; r1[tid] += r1[tid+st]; }
        __syncthreads();
    }
    if (tid == 0) {
        out[b*2+0] = r0[0] + b2[0];
        out[b*2+1] = r1[0] + b2[1];
    }
}

// ------------------------------ host side ----------------------------------
struct Bufs {
    float *X,*XLN,*QKV,*QL,*KL,*S1,*S3,*S2,*T,*U,*Rb,*Z,*Z2,*W,*Wp,*O,*OC,*RS3,*scal;
    __nv_bfloat16 *Ah,*Al,*Bh,*Bl;
};

static Bufs init_bufs()
{
    Bufs b;
    cudaGetSymbolAddress((void**)&b.X,   g_X);
    cudaGetSymbolAddress((void**)&b.XLN, g_XLN);
    cudaGetSymbolAddress((void**)&b.QKV, g_QKV);
    cudaGetSymbolAddress((void**)&b.QL,  g_QL);
    cudaGetSymbolAddress((void**)&b.KL,  g_KL);
    cudaGetSymbolAddress((void**)&b.S1,  g_S1);
    cudaGetSymbolAddress((void**)&b.S3,  g_S3);
    cudaGetSymbolAddress((void**)&b.S2,  g_S2);
    cudaGetSymbolAddress((void**)&b.T,   g_T);
    cudaGetSymbolAddress((void**)&b.U,   g_U);
    cudaGetSymbolAddress((void**)&b.Rb,  g_R);
    cudaGetSymbolAddress((void**)&b.Z,   g_Z);
    cudaGetSymbolAddress((void**)&b.Z2,  g_Z2);
    cudaGetSymbolAddress((void**)&b.W,   g_W);
    cudaGetSymbolAddress((void**)&b.Wp,  g_Wp);
    cudaGetSymbolAddress((void**)&b.O,   g_O);
    cudaGetSymbolAddress((void**)&b.OC,  g_OC);
    cudaGetSymbolAddress((void**)&b.RS3, g_RS3);
    cudaGetSymbolAddress((void**)&b.scal,g_scal);
    cudaGetSymbolAddress((void**)&b.Ah,  g_Ah);
    cudaGetSymbolAddress((void**)&b.Al,  g_Al);
    cudaGetSymbolAddress((void**)&b.Bh,  g_Bh);
    cudaGetSymbolAddress((void**)&b.Bl,  g_Bl);
    return b;
}

static inline void gemm_call(int bm, const float* A, const float* B, float* C,
    int M, int N, int K, int lda, int ldb, int ldc, int nb,
    long long sAb, long long sAh, long long sBb, long long sBh,
    long long sCb, long long sCh,
    const float* bias, const float* resid, int ldr,
    float alpha, int relu, bool transb,
    int nsplit = 1, int Kc = 0, long long sSp = 0,
    const float* rs = nullptr, int rsStride = 0,
    float* aux = nullptr, float diagc = 0.f)
{
    dim3 gr((N + 127)/128, (M + bm - 1)/bm, nb * nsplit);
    if (bm == 128) {
        if (nsplit > 1) {
            if (transb) sgemm<128,true ,true ><<<gr,256>>>(A,B,C,M,N,K,lda,ldb,ldc,sAb,sAh,sBb,sBh,sCb,sCh,bias,resid,ldr,alpha,relu,nsplit,Kc,sSp,rs,rsStride,aux,diagc);
            else        sgemm<128,false,true ><<<gr,256>>>(A,B,C,M,N,K,lda,ldb,ldc,sAb,sAh,sBb,sBh,sCb,sCh,bias,resid,ldr,alpha,relu,nsplit,Kc,sSp,rs,rsStride,aux,diagc);
        } else {
            if (transb) sgemm<128,true ,false><<<gr,256>>>(A,B,C,M,N,K,lda,ldb,ldc,sAb,sAh,sBb,sBh,sCb,sCh,bias,resid,ldr,alpha,relu,1,0,0,rs,rsStride,aux,diagc);
            else        sgemm<128,false,false><<<gr,256>>>(A,B,C,M,N,K,lda,ldb,ldc,sAb,sAh,sBb,sBh,sCb,sCh,bias,resid,ldr,alpha,relu,1,0,0,rs,rsStride,aux,diagc);
        }
    } else {
        if (nsplit > 1) {
            if (transb) sgemm<64,true ,true ><<<gr,256>>>(A,B,C,M,N,K,lda,ldb,ldc,sAb,sAh,sBb,sBh,sCb,sCh,bias,resid,ldr,alpha,relu,nsplit,Kc,sSp,rs,rsStride,aux,diagc);
            else        sgemm<64,false,true ><<<gr,256>>>(A,B,C,M,N,K,lda,ldb,ldc,sAb,sAh,sBb,sBh,sCb,sCh,bias,resid,ldr,alpha,relu,nsplit,Kc,sSp,rs,rsStride,aux,diagc);
        } else {
            if (transb) sgemm<64,true ,false><<<gr,256>>>(A,B,C,M,N,K,lda,ldb,ldc,sAb,sAh,sBb,sBh,sCb,sCh,bias,resid,ldr,alpha,relu,1,0,0,rs,rsStride,aux,diagc);
            else        sgemm<64,false,false><<<gr,256>>>(A,B,C,M,N,K,lda,ldb,ldc,sAb,sAh,sBb,sBh,sCb,sCh,bias,resid,ldr,alpha,relu,1,0,0,rs,rsStride,aux,diagc);
        }
    }
}

static inline void mma_call(const Bufs& bu, int M, int N, int K, float* C, int ldc,
                            long long sA, long long sB, long long sC, int nz,
                            const float* bias, const float* resid, int ldr,
                            int relu = 0)
{
    dim3 gr(N/128, M/128, nz);
    mma_gemm<<<gr,256>>>(bu.Ah, bu.Al, bu.Bh, bu.Bl, C, K, ldc,
                         sA, sB, sC, bias, resid, ldr, relu);
}

static void run_layer(const Bufs& bu, int L, void* const* d_in)
{
    const float* lng  = (const float*)d_in[4] + (size_t)L*DMODEL;
    const float* lnb  = (const float*)d_in[5] + (size_t)L*DMODEL;
    const float* wqkv = (const float*)d_in[6] + (size_t)L*DMODEL*QKVW;
    const float* wout = (const float*)d_in[7] + (size_t)L*DMODEL*DMODEL;
    const float* bout = (const float*)d_in[8] + (size_t)L*DMODEL;
    const float* cw   = (const float*)d_in[9] + (size_t)L*NHEADS*KCONV;

    const long long sQKVb = (long long)NF*QKVW;
    const long long sLh = (long long)NLAND*DH;
    const long long sLb = (long long)NHEADS*sLh;
    const long long sS1h = (long long)NF*NLAND;
    const long long sS1b = (long long)NHEADS*sS1h;
    const long long sS3h = (long long)NLAND*NF;
    const long long sS3b = (long long)NHEADS*sS3h;
    const long long sm = (long long)NLAND*NLAND;
    const long long smb = (long long)NHEADS*sm;
    const long long sOh = (long long)NF*DH;
    const long long sOb = (long long)NHEADS*sOh;

    // x_ln = LN(x)
    ln_kernel<<<NROWS,128>>>(bu.X, bu.XLN, lng, lnb);

    // ---- QKV = x_ln @ w_qkv  (tensor cores) ----
    cvt_a_kernel<<<dim3((NROWS*DMODEL)/256,1),256>>>(bu.XLN, bu.Ah, bu.Al,
        9, DMODEL, 0, 0, (long long)NROWS*DMODEL, 1.f);
    cvt_t_kernel<<<dim3(QKVW/32, DMODEL/32, 1), dim3(32,8)>>>(wqkv, bu.Bh, bu.Bl,
        DMODEL, QKVW, 0);
    mma_call(bu, NROWS, QKVW, DMODEL, bu.QKV, QKVW, 0, 0, 0, 1, nullptr, nullptr, 0);

    // landmarks
    landmark_kernel<<<dim3(NLAND,NBH),64>>>(bu.QKV, bu.QL, 0);
    landmark_kernel<<<dim3(NLAND,NBH),64>>>(bu.QKV, bu.KL, DMODEL);

    // ---- sim1 = (q*scale) @ k_l^T  (tensor cores; 0.125 folded into q cvt) ----
    cvt_a_kernel<<<dim3((NF*DH)/256, NBH),256>>>(bu.QKV, bu.Ah, bu.Al,
        6, QKVW, sQKVb, DH, (long long)NF*DH, 0.125f);
    cvt_a_kernel<<<dim3((NLAND*DH)/256, NBH),256>>>(bu.KL, bu.Bh, bu.Bl,
        6, DH, 8*sLh, sLh, sLh, 1.f);
    mma_call(bu, NF, NLAND, DH, bu.S1, NLAND, (long long)NF*DH, sLh, sS1h, NBH,
             nullptr, nullptr, 0);

    // ---- sim3 = (q_l*scale) @ k^T  (tensor cores) ----
    cvt_a_kernel<<<dim3((NLAND*DH)/256, NBH),256>>>(bu.QL, bu.Ah, bu.Al,
        6, DH, 8*sLh, sLh, sLh, 0.125f);
    cvt_a_kernel<<<dim3((NF*DH)/256, NBH),256>>>(bu.QKV + DMODEL, bu.Bh, bu.Bl,
        6, QKVW, sQKVb, DH, (long long)NF*DH, 1.f);
    mma_call(bu, NLAND, NF, DH, bu.S3, NF, sLh, (long long)NF*DH, sS3h, NBH,
             nullptr, nullptr, 0);

    // sim2 = (q_l*scale) @ k_l^T  (scalar)
    gemm_call(64, bu.QL, bu.KL, bu.S2, NLAND, NLAND, DH, DH, DH, NLAND, NBH,
              sLb, sLh, sLb, sLh, smb, sm, nullptr,nullptr,0, 0.125f,0,true);

    // softmaxes: S1 -> normalized bf16 split directly into Ah/Al;
    // S2 fully normalized; S3 keeps exp + rowscale (scalar consumer)
    softmax_split_kernel<<<NBH*NF,256>>>(bu.S1, bu.Ah, bu.Al);
    softmax_kernel<<<NBH*NLAND,256>>>(bu.S2, NLAND);
    softmax2_kernel<<<NBH*NLAND,256>>>(bu.S3, NF, bu.RS3);

    // Moore-Penrose pinv (scalar Newton-Schulz with fused diag epilogues)
    cudaMemsetAsync(bu.scal, 0, 2*sizeof(float));
    pinv_reduce_kernel<<<NBH,256>>>(bu.S2, bu.scal);
    zinit_kernel<<<(NBH*NLAND*NLAND)/256,256>>>(bu.Z, bu.S2, bu.scal);
    float* za = bu.Z;
    float* zb = bu.Z2;
    for (int it = 0; it < 6; it++) {
        gemm_call(64, bu.S2, za, bu.U, NLAND,NLAND,NLAND, NLAND,NLAND,NLAND, NBH,
                  smb,sm, smb,sm, smb,sm, nullptr,nullptr,0, 1.f,0,false,
                  1,0,0, nullptr,0, bu.T, 7.f);
        gemm_call(64, bu.T, bu.U, bu.Rb, NLAND,NLAND,NLAND, NLAND,NLAND,NLAND, NBH,
                  smb,sm, smb,sm, smb,sm, nullptr,nullptr,0, 1.f,0,false,
                  1,0,0, nullptr,0, nullptr, 15.f);
        gemm_call(64, bu.T, bu.Rb, bu.U, NLAND,NLAND,NLAND, NLAND,NLAND,NLAND, NBH,
                  smb,sm, smb,sm, smb,sm, nullptr,nullptr,0, 1.f,0,false,
                  1,0,0, nullptr,0, nullptr, 13.f);
        gemm_call(64, za, bu.U, zb, NLAND,NLAND,NLAND, NLAND,NLAND,NLAND, NBH,
                  smb,sm, smb,sm, smb,sm, nullptr,nullptr,0, 0.25f,0,false);
        float* tp = za; za = zb; zb = tp;
    }

    // W = attn3 @ v (scalar split-K; rowscale = 1/sum3)
    gemm_call(64, bu.S3, bu.QKV + 2*DMODEL, bu.Wp, NLAND, DH, NF, NF, QKVW, DH, NBH,
              sS3b, sS3h, sQKVb, DH, sLb, sLh, nullptr,nullptr,0, 1.f,0,false,
              8, 1024, (long long)NBH*NLAND*DH, bu.RS3, NLAND);
    reduce_split_kernel<<<(NBH*NLAND*DH)/256,256>>>(bu.Wp, bu.W, (long long)NBH*NLAND*DH);

    // ---- P = attn1 @ Z  (tensor cores; A already split-normalized in Ah/Al) ----
    cvt_t_kernel<<<dim3(NLAND/32, NLAND/32, NBH), dim3(32,8)>>>(za, bu.Bh, bu.Bl,
        NLAND, NLAND, sm);
    mma_call(bu, NF, NLAND, NLAND, bu.S3, NLAND, sS1h, sm, sS1h, NBH,
             nullptr, nullptr, 0);

    // O = P @ W  (scalar)
    gemm_call(128, bu.S3, bu.W, bu.O, NF, DH, NLAND, NLAND, DH, DH, NBH,
              sS1b, sS1h, sLb, sLh, sOb, sOh, nullptr,nullptr,0, 1.f,0,false);
    // O += depthwise conv of V
    conv_kernel<<<dim3(NF/128, NHEADS, NBATCH),256>>>(bu.O, bu.QKV, cw);
    // concat heads
    merge_kernel<<<((long long)NBATCH*NF*DMODEL)/256,256>>>(bu.O, bu.OC);

    // ---- x = x + (OC @ w_out + b_out)  (tensor cores) ----
    cvt_a_kernel<<<dim3((NROWS*DMODEL)/256,1),256>>>(bu.OC, bu.Ah, bu.Al,
        9, DMODEL, 0, 0, (long long)NROWS*DMODEL, 1.f);
    cvt_t_kernel<<<dim3(DMODEL/32, DMODEL/32, 1), dim3(32,8)>>>(wout, bu.Bh, bu.Bl,
        DMODEL, DMODEL, 0);
    mma_call(bu, NROWS, DMODEL, DMODEL, bu.X, DMODEL, 0, 0, 0, 1, bout, bu.X, DMODEL);
}

extern "C" void kernel_launch(void* const* d_in, const int* in_sizes, int n_in,
                              void* d_out, int out_size)
{
    static Bufs bu = init_bufs();
    const float* h    = (const float*)d_in[0];
    const float* w1   = (const float*)d_in[1];
    const float* b1   = (const float*)d_in[2];
    const float* cls  = (const float*)d_in[3];
    const float* fng  = (const float*)d_in[10];
    const float* fnb  = (const float*)d_in[11];
    const float* w2   = (const float*)d_in[12];
    const float* b2   = (const float*)d_in[13];

    // ---- x = relu(h @ w1 + b1)  (tensor cores; padded rows, cls after) ----
    cvt_h_kernel<<<(NROWS*1024)/256,256>>>(h, bu.Ah, bu.Al);
    cvt_t_kernel<<<dim3(DMODEL/32, 1024/32, 1), dim3(32,8)>>>(w1, bu.Bh, bu.Bl,
        1024, DMODEL, 0);
    mma_call(bu, NROWS, DMODEL, 1024, bu.X, DMODEL, 0, 0, 0, 1, b1, nullptr, 0, 1);
    cls_copy_kernel<<<1,512>>>(bu.X, cls);

    run_layer(bu, 0, d_in);
    run_layer(bu, 1, d_in);

    final_kernel<<<NBATCH,128>>>(bu.X, fng, fnb, w2, b2, (float*)d_out);
}

// round 14
// speedup vs baseline: 1.7143x; 1.0874x over previous
#include <cuda_runtime.h>
#include <cuda_bf16.h>

#define NF 8192
#define DMODEL 512
#define NHEADS 8
#define DH 64
#define NLAND 256
#define NBATCH 2
#define NBH 16
#define QKVW 1536
#define NROWS (NBATCH*NF)
#define KCONV 33

// ------------------------- scratch (device globals; no allocs allowed) -----
__device__ __align__(16) float g_X  [(size_t)NBATCH*NF*DMODEL];
__device__ __align__(16) float g_XLN[(size_t)NBATCH*NF*DMODEL];
__device__ __align__(16) float g_QKV[(size_t)NBATCH*NF*QKVW];
__device__ __align__(16) float g_QL [(size_t)NBH*NLAND*DH];
__device__ __align__(16) float g_KL [(size_t)NBH*NLAND*DH];
__device__ __align__(16) float g_S1 [(size_t)NBH*NF*NLAND];
__device__ __align__(16) float g_S3 [(size_t)NBH*NF*NLAND];
__device__ __align__(16) float g_S2 [(size_t)NBH*NLAND*NLAND];
__device__ __align__(16) float g_T  [(size_t)NBH*NLAND*NLAND];
__device__ __align__(16) float g_U  [(size_t)NBH*NLAND*NLAND];
__device__ __align__(16) float g_R  [(size_t)NBH*NLAND*NLAND];
__device__ __align__(16) float g_Z  [(size_t)NBH*NLAND*NLAND];
__device__ __align__(16) float g_Z2 [(size_t)NBH*NLAND*NLAND];
__device__ __align__(16) float g_W  [(size_t)NBH*NLAND*DH];
__device__ __align__(16) float g_Wp [(size_t)4*NBH*NLAND*DH];
__device__ __align__(16) float g_OC [(size_t)NBATCH*NF*DMODEL];
__device__ __align__(16) float g_RS3[(size_t)NBH*NLAND];
__device__ float g_scal[2];
// bf16 split operand buffers for the tensor-core path
__device__ __align__(16) __nv_bfloat16 g_Ah[(size_t)NBH*NF*NLAND];
__device__ __align__(16) __nv_bfloat16 g_Al[(size_t)NBH*NF*NLAND];
__device__ __align__(16) __nv_bfloat16 g_Bh[(size_t)NBH*NF*DH];
__device__ __align__(16) __nv_bfloat16 g_Bl[(size_t)NBH*NF*DH];
__device__ __align__(16) __nv_bfloat16 g_Ch[(size_t)NBH*NF*NLAND];
__device__ __align__(16) __nv_bfloat16 g_Cl[(size_t)NBH*NF*NLAND];

// ------------------------- f32x2 packed helpers ----------------------------
__device__ __forceinline__ unsigned long long pack2_dup(float x)
{
    unsigned long long r;
    unsigned int u = __float_as_uint(x);
    asm("mov.b64 %0, {%1, %1};" : "=l"(r) : "r"(u));
    return r;
}
__device__ __forceinline__ void ffma2(unsigned long long& d,
                                      unsigned long long a, unsigned long long b)
{
    asm("fma.rn.f32x2 %0, %1, %2, %0;" : "+l"(d) : "l"(a), "l"(b));
}
__device__ __forceinline__ float2 unpack2(unsigned long long v)
{
    unsigned int lo, hi;
    asm("mov.b64 {%0, %1}, %2;" : "=r"(lo), "=r"(hi) : "l"(v));
    return make_float2(__uint_as_float(lo), __uint_as_float(hi));
}

// -------- warp mma helper: m16n8k16 bf16 x bf16 -> f32 accumulate ----------
#define MMA16816(d, A, B)                                                      \
    asm volatile("mma.sync.aligned.m16n8k16.row.col.f32.bf16.bf16.f32 "        \
                 "{%0,%1,%2,%3},{%4,%5,%6,%7},{%8,%9},{%0,%1,%2,%3};"          \
                 : "+f"((d)[0]), "+f"((d)[1]), "+f"((d)[2]), "+f"((d)[3])      \
                 : "r"((A)[0]), "r"((A)[1]), "r"((A)[2]), "r"((A)[3]),         \
                   "r"((B)[0]), "r"((B)[1]))

// ---------------- tensor-core bf16-split GEMM: C[M,N] = A@B^T ---------------
// 128x128 tile. Optional split-bf16 output (oH/oL) instead of float C.
__global__ __launch_bounds__(256, 2) void mma_gemm(
    const __nv_bfloat16* __restrict__ Ah, const __nv_bfloat16* __restrict__ Al,
    const __nv_bfloat16* __restrict__ Bh, const __nv_bfloat16* __restrict__ Bl,
    float* __restrict__ C, int Kv, int ldc,
    long long sA, long long sB, long long sC,
    const float* __restrict__ bias, const float* __restrict__ resid, int ldr,
    int relu, __nv_bfloat16* __restrict__ oH, __nv_bfloat16* __restrict__ oL)
{
    __shared__ __nv_bfloat16 sAh[2][128*16], sAl[2][128*16];
    __shared__ __nv_bfloat16 sBh[2][128*16], sBl[2][128*16];

    int tid = threadIdx.x;
    int lane = tid & 31, wid = tid >> 5;
    int z = blockIdx.z;
    int m0 = blockIdx.y * 128, n0 = blockIdx.x * 128;
    const __nv_bfloat16* pAh = Ah + (long long)z*sA + (long long)m0*Kv;
    const __nv_bfloat16* pAl = Al + (long long)z*sA + (long long)m0*Kv;
    const __nv_bfloat16* pBh = Bh + (long long)z*sB + (long long)n0*Kv;
    const __nv_bfloat16* pBl = Bl + (long long)z*sB + (long long)n0*Kv;
    float* Cz = C ? C + (long long)z*sC : (float*)0;
    __nv_bfloat16* oHz = oH ? oH + (long long)z*sC : (__nv_bfloat16*)0;
    __nv_bfloat16* oLz = oL ? oL + (long long)z*sC : (__nv_bfloat16*)0;

    int row = tid >> 1, half = tid & 1;
    long long goff = (long long)row*Kv + half*8;
    int soff = row*16 + half*8;

    uint4 va_h, va_l, vb_h, vb_l;
    auto load = [&](int kk) {
        va_h = *(const uint4*)(pAh + goff + kk);
        va_l = *(const uint4*)(pAl + goff + kk);
        vb_h = *(const uint4*)(pBh + goff + kk);
        vb_l = *(const uint4*)(pBl + goff + kk);
    };
    auto store = [&](int pb) {
        *(uint4*)&sAh[pb][soff] = va_h;
        *(uint4*)&sAl[pb][soff] = va_l;
        *(uint4*)&sBh[pb][soff] = vb_h;
        *(uint4*)&sBl[pb][soff] = vb_l;
    };

    float acc[2][8][4];
    #pragma unroll
    for (int i = 0; i < 2; i++)
        #pragma unroll
        for (int j = 0; j < 8; j++)
            #pragma unroll
            for (int e = 0; e < 4; e++) acc[i][j][e] = 0.f;

    int warpM = (wid & 3) * 32, warpN = (wid >> 2) * 64;
    int ar = warpM + (lane >> 2);
    int kc = 2 * (lane & 3);
    int bro = (lane >> 2);

    int nchunk = Kv >> 4;
    load(0);
    store(0);
    __syncthreads();

    for (int t = 0; t < nchunk; t++) {
        if (t + 1 < nchunk) load((t + 1) << 4);
        int pb = t & 1;
        const __nv_bfloat16* a_h = sAh[pb];
        const __nv_bfloat16* a_l = sAl[pb];
        const __nv_bfloat16* b_h = sBh[pb];
        const __nv_bfloat16* b_l = sBl[pb];

        unsigned Af[2][4], Ag[2][4];
        #pragma unroll
        for (int mt = 0; mt < 2; mt++) {
            int base = (ar + mt*16)*16 + kc;
            Af[mt][0] = *(const unsigned*)&a_h[base];
            Af[mt][1] = *(const unsigned*)&a_h[base + 128];
            Af[mt][2] = *(const unsigned*)&a_h[base + 8];
            Af[mt][3] = *(const unsigned*)&a_h[base + 136];
            Ag[mt][0] = *(const unsigned*)&a_l[base];
            Ag[mt][1] = *(const unsigned*)&a_l[base + 128];
            Ag[mt][2] = *(const unsigned*)&a_l[base + 8];
            Ag[mt][3] = *(const unsigned*)&a_l[base + 136];
        }
        #pragma unroll
        for (int nt = 0; nt < 8; nt++) {
            int bb = (warpN + nt*8 + bro)*16 + kc;
            unsigned bh[2], bl[2];
            bh[0] = *(const unsigned*)&b_h[bb];
            bh[1] = *(const unsigned*)&b_h[bb + 8];
            bl[0] = *(const unsigned*)&b_l[bb];
            bl[1] = *(const unsigned*)&b_l[bb + 8];
            #pragma unroll
            for (int mt = 0; mt < 2; mt++) {
                MMA16816(acc[mt][nt], Af[mt], bh);
                MMA16816(acc[mt][nt], Ag[mt], bh);
                MMA16816(acc[mt][nt], Af[mt], bl);
            }
        }
        if (t + 1 < nchunk) {
            store((t + 1) & 1);
            __syncthreads();
        }
    }

    // epilogue
    #pragma unroll
    for (int mt = 0; mt < 2; mt++) {
        int r0 = m0 + warpM + mt*16 + (lane >> 2);
        #pragma unroll
        for (int nt = 0; nt < 8; nt++) {
            int c0 = n0 + warpN + nt*8 + kc;
            float v0 = acc[mt][nt][0], v1 = acc[mt][nt][1];
            float v2 = acc[mt][nt][2], v3 = acc[mt][nt][3];
            if (oHz) {
                __nv_bfloat16 h0 = __float2bfloat16(v0);
                __nv_bfloat16 h1 = __float2bfloat16(v1);
                __nv_bfloat16 h2 = __float2bfloat16(v2);
                __nv_bfloat16 h3 = __float2bfloat16(v3);
                long long o0 = (long long)r0*ldc + c0;
                long long o1 = (long long)(r0+8)*ldc + c0;
                oHz[o0] = h0; oHz[o0+1] = h1;
                oHz[o1] = h2; oHz[o1+1] = h3;
                oLz[o0]   = __float2bfloat16(v0 - __bfloat162float(h0));
                oLz[o0+1] = __float2bfloat16(v1 - __bfloat162float(h1));
                oLz[o1]   = __float2bfloat16(v2 - __bfloat162float(h2));
                oLz[o1+1] = __float2bfloat16(v3 - __bfloat162float(h3));
                continue;
            }
            if (bias) {
                float b0 = bias[c0], b1 = bias[c0 + 1];
                v0 += b0; v1 += b1; v2 += b0; v3 += b1;
            }
            if (resid) {
                v0 += resid[(long long)r0*ldr + c0];
                v1 += resid[(long long)r0*ldr + c0 + 1];
                v2 += resid[(long long)(r0 + 8)*ldr + c0];
                v3 += resid[(long long)(r0 + 8)*ldr + c0 + 1];
            }
            if (relu) {
                v0 = fmaxf(v0, 0.f); v1 = fmaxf(v1, 0.f);
                v2 = fmaxf(v2, 0.f); v3 = fmaxf(v3, 0.f);
            }
            *(float2*)&Cz[(long long)r0*ldc + c0] = make_float2(v0, v1);
            *(float2*)&Cz[(long long)(r0 + 8)*ldc + c0] = make_float2(v2, v3);
        }
    }
}

// ---- 128x64-tile variant; optional K-split; C offset via (b,h) strides ----
__global__ __launch_bounds__(256, 2) void mma_gemm64(
    const __nv_bfloat16* __restrict__ Ah, const __nv_bfloat16* __restrict__ Al,
    const __nv_bfloat16* __restrict__ Bh, const __nv_bfloat16* __restrict__ Bl,
    float* __restrict__ C, int Kv, int ldc,
    long long sA, long long sB, long long sCb, long long sCh,
    int nsplit, int Kc, long long sSp)
{
    __shared__ __nv_bfloat16 sAh[2][128*16], sAl[2][128*16];
    __shared__ __nv_bfloat16 sBh[2][64*16], sBl[2][64*16];

    int tid = threadIdx.x;
    int lane = tid & 31, wid = tid >> 5;
    int zAll = blockIdx.z;
    int z = zAll / nsplit;
    int sp = zAll - z * nsplit;
    int m0 = blockIdx.y * 128;
    int k0 = sp * Kc;
    const __nv_bfloat16* pAh = Ah + (long long)z*sA + (long long)m0*Kv;
    const __nv_bfloat16* pAl = Al + (long long)z*sA + (long long)m0*Kv;
    const __nv_bfloat16* pBh = Bh + (long long)z*sB;
    const __nv_bfloat16* pBl = Bl + (long long)z*sB;
    float* Cz = C + (long long)(z>>3)*sCb + (long long)(z&7)*sCh
                  + (long long)sp*sSp;

    int row = tid >> 1, half = tid & 1;
    long long goffA = (long long)row*Kv + half*8 + k0;
    int soff = row*16 + half*8;

    uint4 va_h, va_l, vb_h, vb_l;
    auto load = [&](int kk) {
        va_h = *(const uint4*)(pAh + goffA + kk);
        va_l = *(const uint4*)(pAl + goffA + kk);
        if (tid < 128) {
            vb_h = *(const uint4*)(pBh + goffA + kk);  // same row formula, rows 0..63
            vb_l = *(const uint4*)(pBl + goffA + kk);
        }
    };
    auto store = [&](int pb) {
        *(uint4*)&sAh[pb][soff] = va_h;
        *(uint4*)&sAl[pb][soff] = va_l;
        if (tid < 128) {
            *(uint4*)&sBh[pb][soff] = vb_h;
            *(uint4*)&sBl[pb][soff] = vb_l;
        }
    };

    float acc[2][4][4];
    #pragma unroll
    for (int i = 0; i < 2; i++)
        #pragma unroll
        for (int j = 0; j < 4; j++)
            #pragma unroll
            for (int e = 0; e < 4; e++) acc[i][j][e] = 0.f;

    int warpM = (wid & 3) * 32, warpN = (wid >> 2) * 32;
    int ar = warpM + (lane >> 2);
    int kc = 2 * (lane & 3);
    int bro = (lane >> 2);

    int nchunk = Kc >> 4;
    load(0);
    store(0);
    __syncthreads();

    for (int t = 0; t < nchunk; t++) {
        if (t + 1 < nchunk) load((t + 1) << 4);
        int pb = t & 1;
        const __nv_bfloat16* a_h = sAh[pb];
        const __nv_bfloat16* a_l = sAl[pb];
        const __nv_bfloat16* b_h = sBh[pb];
        const __nv_bfloat16* b_l = sBl[pb];

        unsigned Af[2][4], Ag[2][4];
        #pragma unroll
        for (int mt = 0; mt < 2; mt++) {
            int base = (ar + mt*16)*16 + kc;
            Af[mt][0] = *(const unsigned*)&a_h[base];
            Af[mt][1] = *(const unsigned*)&a_h[base + 128];
            Af[mt][2] = *(const unsigned*)&a_h[base + 8];
            Af[mt][3] = *(const unsigned*)&a_h[base + 136];
            Ag[mt][0] = *(const unsigned*)&a_l[base];
            Ag[mt][1] = *(const unsigned*)&a_l[base + 128];
            Ag[mt][2] = *(const unsigned*)&a_l[base + 8];
            Ag[mt][3] = *(const unsigned*)&a_l[base + 136];
        }
        #pragma unroll
        for (int nt = 0; nt < 4; nt++) {
            int bb = (warpN + nt*8 + bro)*16 + kc;
            unsigned bh[2], bl[2];
            bh[0] = *(const unsigned*)&b_h[bb];
            bh[1] = *(const unsigned*)&b_h[bb + 8];
            bl[0] = *(const unsigned*)&b_l[bb];
            bl[1] = *(const unsigned*)&b_l[bb + 8];
            #pragma unroll
            for (int mt = 0; mt < 2; mt++) {
                MMA16816(acc[mt][nt], Af[mt], bh);
                MMA16816(acc[mt][nt], Ag[mt], bh);
                MMA16816(acc[mt][nt], Af[mt], bl);
            }
        }
        if (t + 1 < nchunk) {
            store((t + 1) & 1);
            __syncthreads();
        }
    }

    #pragma unroll
    for (int mt = 0; mt < 2; mt++) {
        int r0 = m0 + warpM + mt*16 + (lane >> 2);
        #pragma unroll
        for (int nt = 0; nt < 4; nt++) {
            int c0 = warpN + nt*8 + kc;
            *(float2*)&Cz[(long long)r0*ldc + c0] =
                make_float2(acc[mt][nt][0], acc[mt][nt][1]);
            *(float2*)&Cz[(long long)(r0 + 8)*ldc + c0] =
                make_float2(acc[mt][nt][2], acc[mt][nt][3]);
        }
    }
}

// ------------- fp32 -> bf16 hi/lo conversion (straight, batched) ------------
__global__ void cvt_a_kernel(const float* __restrict__ src,
    __nv_bfloat16* __restrict__ hi, __nv_bfloat16* __restrict__ lo,
    int kshift, int lds, long long sb, long long sh, long long RK,
    float scale)
{
    long long idx = (long long)blockIdx.x * 256 + threadIdx.x;
    int z = blockIdx.y;
    int r = (int)(idx >> kshift);
    int k = (int)(idx & ((1 << kshift) - 1));
    float v = src[(long long)(z>>3)*sb + (long long)(z&7)*sh + (long long)r*lds + k] * scale;
    __nv_bfloat16 h = __float2bfloat16(v);
    float rem = v - __bfloat162float(h);
    long long o = (long long)z*RK + idx;
    hi[o] = h;
    lo[o] = __float2bfloat16(rem);
}

// ------- embed input: h (B,8191,1024) -> padded bf16 split A [16384,1024] ---
__global__ void cvt_h_kernel(const float* __restrict__ src,
    __nv_bfloat16* __restrict__ hi, __nv_bfloat16* __restrict__ lo)
{
    long long idx = (long long)blockIdx.x * 256 + threadIdx.x;
    int r = (int)(idx >> 10);
    int k = (int)(idx & 1023);
    int b = r >> 13, t = r & 8191;
    float v = 0.f;
    if (t > 0)
        v = src[((long long)b*8191 + (t - 1))*1024 + k];
    __nv_bfloat16 h = __float2bfloat16(v);
    float rem = v - __bfloat162float(h);
    hi[idx] = h;
    lo[idx] = __float2bfloat16(rem);
}

// --- fp32 [K,N] (row stride ldS, (b,h)-strided) -> bf16 hi/lo [N,K] ---------
__global__ void cvt_t_kernel(const float* __restrict__ src,
    __nv_bfloat16* __restrict__ hi, __nv_bfloat16* __restrict__ lo,
    int Kv, int Nv, int ldS, long long szB, long long szH)
{
    __shared__ float t[32][33];
    int z = blockIdx.z;
    const float* s = src + (long long)(z>>3)*szB + (long long)(z&7)*szH;
    int n = blockIdx.x*32 + threadIdx.x;
    #pragma unroll
    for (int i = 0; i < 4; i++) {
        int k = blockIdx.y*32 + threadIdx.y + i*8;
        t[threadIdx.y + i*8][threadIdx.x] = s[(long long)k*ldS + n];
    }
    __syncthreads();
    int k2 = blockIdx.y*32 + threadIdx.x;
    #pragma unroll
    for (int i = 0; i < 4; i++) {
        int n2 = blockIdx.x*32 + threadIdx.y + i*8;
        float v = t[threadIdx.x][threadIdx.y + i*8];
        __nv_bfloat16 h = __float2bfloat16(v);
        float rem = v - __bfloat162float(h);
        long long o = ((long long)z*Nv + n2)*Kv + k2;
        hi[o] = h;
        lo[o] = __float2bfloat16(rem);
    }
}

// -- softmax over 256 cols, writes NORMALIZED bf16 hi/lo directly (for S1) ---
__global__ void softmax_split_kernel(const float* __restrict__ X,
    __nv_bfloat16* __restrict__ hi, __nv_bfloat16* __restrict__ lo)
{
    long long row = blockIdx.x;
    int tid = threadIdx.x;
    float v = X[row*NLAND + tid];
    __shared__ float sred[8];
    float m = v;
    #pragma unroll
    for (int o = 16; o; o >>= 1) m = fmaxf(m, __shfl_xor_sync(0xffffffffu, m, o));
    if ((tid & 31) == 0) sred[tid>>5] = m;
    __syncthreads();
    m = fmaxf(fmaxf(fmaxf(sred[0], sred[1]), fmaxf(sred[2], sred[3])),
              fmaxf(fmaxf(sred[4], sred[5]), fmaxf(sred[6], sred[7])));
    float e = __expf(v - m);
    float s = e;
    #pragma unroll
    for (int o = 16; o; o >>= 1) s += __shfl_xor_sync(0xffffffffu, s, o);
    __syncthreads();
    if ((tid & 31) == 0) sred[tid>>5] = s;
    __syncthreads();
    s = sred[0]+sred[1]+sred[2]+sred[3]+sred[4]+sred[5]+sred[6]+sred[7];
    float ov = e / s;
    __nv_bfloat16 h = __float2bfloat16(ov);
    float rem = ov - __bfloat162float(h);
    long long o2 = row*NLAND + tid;
    hi[o2] = h;
    lo[o2] = __float2bfloat16(rem);
}

// -- softmax over NF cols: writes UNNORMALIZED exp split + 1/sum (for S3) ----
__global__ void softmax_split_wide_kernel(const float* __restrict__ X,
    __nv_bfloat16* __restrict__ hi, __nv_bfloat16* __restrict__ lo,
    float* __restrict__ rs)
{
    long long row = blockIdx.x;
    const float* p = X + row * NF;
    int tid = threadIdx.x;   // 256
    __shared__ float sred[8];
    __shared__ float sval;
    float m = -1e30f;
    for (int c = tid; c < NF; c += 256) m = fmaxf(m, p[c]);
    #pragma unroll
    for (int o = 16; o; o >>= 1) m = fmaxf(m, __shfl_xor_sync(0xffffffffu, m, o));
    if ((tid & 31) == 0) sred[tid>>5] = m;
    __syncthreads();
    if (tid == 0) {
        float mm = sred[0];
        for (int i = 1; i < 8; i++) mm = fmaxf(mm, sred[i]);
        sval = mm;
    }
    __syncthreads();
    m = sval;
    float s = 0.f;
    for (int c = tid; c < NF; c += 256) {
        float e = __expf(p[c] - m);
        __nv_bfloat16 h = __float2bfloat16(e);
        hi[row*NF + c] = h;
        lo[row*NF + c] = __float2bfloat16(e - __bfloat162float(h));
        s += e;
    }
    #pragma unroll
    for (int o = 16; o; o >>= 1) s += __shfl_xor_sync(0xffffffffu, s, o);
    __syncthreads();
    if ((tid & 31) == 0) sred[tid>>5] = s;
    __syncthreads();
    if (tid == 0) {
        float t = 0.f;
        for (int i = 0; i < 8; i++) t += sred[i];
        rs[row] = 1.f / t;
    }
}

// ------------------------------- SGEMM (scalar f32x2) -----------------------
template<int BM, bool TRANSB>
__global__ __launch_bounds__(256) void sgemm(
    const float* __restrict__ A, const float* __restrict__ B, float* __restrict__ C,
    int M, int N, int K, int lda, int ldb, int ldc,
    long long sAb, long long sAh, long long sBb, long long sBh,
    long long sCb, long long sCh,
    float alpha, float* __restrict__ aux, float diagc)
{
    constexpr int NI = BM / 16;
    int zb = blockIdx.z;
    int bb = zb >> 3, hh = zb & 7;
    const float* Ap = A + bb*sAb + hh*sAh;
    const float* Bp = B + bb*sBb + hh*sBh;
    float*       Cp = C + bb*sCb + hh*sCh;
    float*       Xp = aux ? aux + bb*sCb + hh*sCh : (float*)0;

    int bm0 = blockIdx.y * BM;
    int bn0 = blockIdx.x * 128;

    __shared__ __align__(16) float As[2][8][128];
    __shared__ __align__(16) float Bs[2][8][128];

    int tid = threadIdx.x;
    int tx = tid & 15, ty = tid >> 4;
    unsigned long long acc[NI][4];
    #pragma unroll
    for (int i = 0; i < NI; i++)
        #pragma unroll
        for (int j = 0; j < 4; j++) acc[i][j] = 0ULL;

    int arow = bm0 + (tid >> 1);
    int akq  = (tid & 1) * 4;
    int bk = tid >> 5;
    int bn = (tid & 31) * 4;
    int gc = bn0 + bn;
    int nB = bn0 + (tid >> 1);

    float4 avS, bvS;

    auto loadTile = [&](int kk) {
        avS = make_float4(0.f,0.f,0.f,0.f);
        if ((BM == 128 || tid < 128) && arow < M)
            avS = *(const float4*)(Ap + (long long)arow*lda + kk + akq);
        if (TRANSB) {
            bvS = make_float4(0.f,0.f,0.f,0.f);
            if (nB < N) bvS = *(const float4*)(Bp + (long long)nB*ldb + kk + akq);
        } else {
            const float* p = Bp + (long long)(kk + bk)*ldb + gc;
            if (gc + 3 < N) bvS = *(const float4*)p;
            else {
                bvS.x = (gc+0 < N) ? p[0] : 0.f;
                bvS.y = (gc+1 < N) ? p[1] : 0.f;
                bvS.z = (gc+2 < N) ? p[2] : 0.f;
                bvS.w = (gc+3 < N) ? p[3] : 0.f;
            }
        }
    };
    auto storeTile = [&](int pb) {
        if (BM == 128 || tid < 128) {
            As[pb][akq+0][tid>>1] = avS.x;
            As[pb][akq+1][tid>>1] = avS.y;
            As[pb][akq+2][tid>>1] = avS.z;
            As[pb][akq+3][tid>>1] = avS.w;
        }
        if (TRANSB) {
            Bs[pb][akq+0][tid>>1] = bvS.x;
            Bs[pb][akq+1][tid>>1] = bvS.y;
            Bs[pb][akq+2][tid>>1] = bvS.z;
            Bs[pb][akq+3][tid>>1] = bvS.w;
        } else {
            *(float4*)&Bs[pb][bk][bn] = bvS;
        }
    };

    int nt = K >> 3;
    loadTile(0);
    storeTile(0);
    __syncthreads();

    for (int t = 0; t < nt; t++) {
        if (t + 1 < nt) loadTile((t + 1) << 3);
        int pb = t & 1;
        #pragma unroll
        for (int k = 0; k < 8; k++) {
            float ra[NI];
            *(float4*)&ra[0] = *(const float4*)&As[pb][k][ty*4];
            if (BM == 128)
                *(float4*)&ra[4] = *(const float4*)&As[pb][k][64 + ty*4];
            ulonglong2 bq0 = *(const ulonglong2*)&Bs[pb][k][tx*4];
            ulonglong2 bq1 = *(const ulonglong2*)&Bs[pb][k][64 + tx*4];
            unsigned long long rb0 = bq0.x, rb1 = bq0.y, rb2 = bq1.x, rb3 = bq1.y;
            #pragma unroll
            for (int i = 0; i < NI; i++) {
                unsigned long long aa = pack2_dup(ra[i]);
                ffma2(acc[i][0], aa, rb0);
                ffma2(acc[i][1], aa, rb1);
                ffma2(acc[i][2], aa, rb2);
                ffma2(acc[i][3], aa, rb3);
            }
        }
        if (t + 1 < nt) {
            storeTile((t + 1) & 1);
            __syncthreads();
        }
    }

    #pragma unroll
    for (int i = 0; i < NI; i++) {
        int r = bm0 + ((i < 4) ? (ty*4 + i) : (64 + ty*4 + i - 4));
        if (r >= M) continue;
        #pragma unroll
        for (int jp = 0; jp < 4; jp++) {
            float2 pv = unpack2(acc[i][jp]);
            int cbase = bn0 + ((jp < 2) ? (tx*4 + jp*2) : (64 + tx*4 + (jp-2)*2));
            float vv[2] = {pv.x, pv.y};
            #pragma unroll
            for (int e = 0; e < 2; e++) {
                int c = cbase + e;
                if (c >= N) continue;
                float v = vv[e] * alpha;
                long long off = (long long)r*ldc + c;
                if (Xp)   Xp[off] = v;
                if (diagc != 0.f) v = (r == c ? diagc : 0.f) - v;
                Cp[off] = v;
            }
        }
    }
}

// ------------------------------ helpers ------------------------------------
__global__ void reduce4_rs_kernel(const float* __restrict__ Wp, float* __restrict__ W,
                                  const float* __restrict__ rs, long long stride)
{
    long long idx = (long long)blockIdx.x * blockDim.x + threadIdx.x;
    float s = 0.f;
    #pragma unroll
    for (int k = 0; k < 4; k++) s += Wp[(long long)k*stride + idx];
    long long zr = idx >> 6;     // z*256 + r
    W[idx] = s * rs[zr];
}

__global__ void ln_kernel(const float* __restrict__ X, float* __restrict__ Y,
                          const float* __restrict__ g, const float* __restrict__ b)
{
    long long r = blockIdx.x;
    int tid = threadIdx.x;   // 128
    float4 v = ((const float4*)(X + r*DMODEL))[tid];
    float s = v.x+v.y+v.z+v.w;
    float q = v.x*v.x + v.y*v.y + v.z*v.z + v.w*v.w;
    #pragma unroll
    for (int o = 16; o; o >>= 1) {
        s += __shfl_xor_sync(0xffffffffu, s, o);
        q += __shfl_xor_sync(0xffffffffu, q, o);
    }
    __shared__ float ss[4], qq[4];
    if ((tid & 31) == 0) { ss[tid>>5] = s; qq[tid>>5] = q; }
    __syncthreads();
    s = ss[0]+ss[1]+ss[2]+ss[3];
    q = qq[0]+qq[1]+qq[2]+qq[3];
    float mu = s * (1.f/DMODEL);
    float var = q * (1.f/DMODEL) - mu*mu;
    float rs = rsqrtf(var + 1e-5f);
    float4 gv = ((const float4*)g)[tid];
    float4 bv = ((const float4*)b)[tid];
    float4 o;
    o.x = (v.x-mu)*rs*gv.x + bv.x;
    o.y = (v.y-mu)*rs*gv.y + bv.y;
    o.z = (v.z-mu)*rs*gv.z + bv.z;
    o.w = (v.w-mu)*rs*gv.w + bv.w;
    ((float4*)(Y + r*DMODEL))[tid] = o;
}

__global__ void cls_copy_kernel(float* __restrict__ X, const float* __restrict__ cls)
{
    int c = threadIdx.x;  // 512
    X[c] = cls[c];
    X[(long long)NF*DMODEL + c] = cls[c];
}

__global__ void landmark_kernel(const float* __restrict__ QKV, float* __restrict__ out, int off)
{
    int j = blockIdx.x;
    int z = blockIdx.y;
    int d = threadIdx.x;
    int b = z >> 3, h = z & 7;
    const float* base = QKV + ((long long)b*NF + (long long)j*32)*QKVW + off + h*DH + d;
    float s = 0.f;
    #pragma unroll
    for (int t = 0; t < 32; t++) s += base[(long long)t*QKVW];
    out[((long long)z*NLAND + j)*DH + d] = s * (1.f/32.f);
}

__global__ void softmax_kernel(float* __restrict__ X, int cols)
{
    long long row = blockIdx.x;
    float* p = X + row * cols;
    int tid = threadIdx.x;
    __shared__ float sred[8];
    __shared__ float sval;
    float m = -1e30f;
    for (int c = tid; c < cols; c += 256) m = fmaxf(m, p[c]);
    #pragma unroll
    for (int o = 16; o; o >>= 1) m = fmaxf(m, __shfl_xor_sync(0xffffffffu, m, o));
    if ((tid & 31) == 0) sred[tid>>5] = m;
    __syncthreads();
    if (tid == 0) {
        float mm = sred[0];
        for (int i = 1; i < 8; i++) mm = fmaxf(mm, sred[i]);
        sval = mm;
    }
    __syncthreads();
    m = sval;
    __syncthreads();
    float s = 0.f;
    for (int c = tid; c < cols; c += 256) {
        float e = __expf(p[c] - m);
        p[c] = e;
        s += e;
    }
    #pragma unroll
    for (int o = 16; o; o >>= 1) s += __shfl_xor_sync(0xffffffffu, s, o);
    if ((tid & 31) == 0) sred[tid>>5] = s;
    __syncthreads();
    if (tid == 0) {
        float t = 0.f;
        for (int i = 0; i < 8; i++) t += sred[i];
        sval = t;
    }
    __syncthreads();
    float inv = 1.f / sval;
    for (int c = tid; c < cols; c += 256) p[c] *= inv;
}

__device__ __forceinline__ void atomicMaxF(float* addr, float v)
{
    atomicMax((int*)addr, __float_as_int(v));
}

__global__ void pinv_reduce_kernel(const float* __restrict__ S2, float* __restrict__ scal)
{
    int z = blockIdx.x;
    int tid = threadIdx.x;
    const float* Mz = S2 + (long long)z * NLAND * NLAND;
    float rs = 0.f, cs = 0.f;
    for (int j = 0; j < NLAND; j++) rs += Mz[(long long)tid*NLAND + j];
    for (int i = 0; i < NLAND; i++) cs += Mz[(long long)i*NLAND + tid];
    __shared__ float sm[256];
    sm[tid] = rs; __syncthreads();
    for (int s = 128; s; s >>= 1) { if (tid < s) sm[tid] = fmaxf(sm[tid], sm[tid+s]); __syncthreads(); }
    if (tid == 0) atomicMaxF(&scal[0], sm[0]);
    __syncthreads();
    sm[tid] = cs; __syncthreads();
    for (int s = 128; s; s >>= 1) { if (tid < s) sm[tid] = fmaxf(sm[tid], sm[tid+s]); __syncthreads(); }
    if (tid == 0) atomicMaxF(&scal[1], sm[0]);
}

__global__ void zinit_kernel(float* __restrict__ Z, const float* __restrict__ S2,
                             const float* __restrict__ scal)
{
    long long idx = (long long)blockIdx.x * blockDim.x + threadIdx.x;
    float rcp = 1.f / (scal[0] * scal[1]);
    long long z = idx >> 16;
    int r = (int)((idx >> 8) & 255);
    int c = (int)(idx & 255);
    Z[idx] = S2[(z << 16) + ((long long)c << 8) + r] * rcp;
}

// conv accumulates into OC layout [b][t][h*64 + d]
__global__ void conv_kernel(float* __restrict__ OC, const float* __restrict__ QKV,
                            const float* __restrict__ cw)
{
    int t0 = blockIdx.x * 128;
    int h = blockIdx.y;
    int b = blockIdx.z;
    __shared__ float sv[160*64];
    __shared__ float ws[KCONV];
    int tid = threadIdx.x;
    if (tid < KCONV) ws[tid] = cw[h*KCONV + tid];
    for (int i = tid; i < 160*64; i += 256) {
        int tl = i >> 6, d = i & 63;
        int t = t0 + tl - 16;
        float v = 0.f;
        if (t >= 0 && t < NF)
            v = QKV[((long long)b*NF + t)*QKVW + 2*DMODEL + h*DH + d];
        sv[i] = v;
    }
    __syncthreads();
    float* Op = OC + ((long long)b*NF + t0)*DMODEL + h*DH;
    for (int i = tid; i < 128*64; i += 256) {
        int tl = i >> 6, d = i & 63;
        float acc = 0.f;
        #pragma unroll
        for (int k = 0; k < KCONV; k++) acc += ws[k] * sv[(tl + k)*64 + d];
        Op[(long long)tl*DMODEL + d] += acc;
    }
}

__global__ void final_kernel(const float* __restrict__ X, const float* __restrict__ g,
                             const float* __restrict__ bt, const float* __restrict__ w2,
                             const float* __restrict__ b2, float* __restrict__ out)
{
    int b = blockIdx.x;
    int tid = threadIdx.x;
    const float* x = X + (long long)b*NF*DMODEL;
    float4 v = ((const float4*)x)[tid];
    float s = v.x+v.y+v.z+v.w;
    float q = v.x*v.x + v.y*v.y + v.z*v.z + v.w*v.w;
    #pragma unroll
    for (int o = 16; o; o >>= 1) {
        s += __shfl_xor_sync(0xffffffffu, s, o);
        q += __shfl_xor_sync(0xffffffffu, q, o);
    }
    __shared__ float ss[4], qq[4];
    if ((tid & 31) == 0) { ss[tid>>5] = s; qq[tid>>5] = q; }
    __syncthreads();
    s = ss[0]+ss[1]+ss[2]+ss[3];
    q = qq[0]+qq[1]+qq[2]+qq[3];
    float mu = s * (1.f/DMODEL);
    float var = q * (1.f/DMODEL) - mu*mu;
    float rs = rsqrtf(var + 1e-5f);
    __shared__ float xn[DMODEL];
    float4 gv = ((const float4*)g)[tid];
    float4 bv = ((const float4*)bt)[tid];
    xn[tid*4+0] = (v.x-mu)*rs*gv.x + bv.x;
    xn[tid*4+1] = (v.y-mu)*rs*gv.y + bv.y;
    xn[tid*4+2] = (v.z-mu)*rs*gv.z + bv.z;
    xn[tid*4+3] = (v.w-mu)*rs*gv.w + bv.w;
    __syncthreads();
    float s0 = 0.f, s1 = 0.f;
    for (int d = tid; d < DMODEL; d += 128) {
        float xv = xn[d];
        s0 += xv * w2[d*2+0];
        s1 += xv * w2[d*2+1];
    }
    __shared__ float r0[128], r1[128];
    r0[tid] = s0; r1[tid] = s1;
    __syncthreads();
    for (int st = 64; st; st >>= 1) {
        if (tid < st) { r0[tid] += r0[tid+st]; r1[tid] += r1[tid+st]; }
        __syncthreads();
    }
    if (tid == 0) {
        out[b*2+0] = r0[0] + b2[0];
        out[b*2+1] = r1[0] + b2[1];
    }
}

// ------------------------------ host side ----------------------------------
struct Bufs {
    float *X,*XLN,*QKV,*QL,*KL,*S1,*S3,*S2,*T,*U,*Rb,*Z,*Z2,*W,*Wp,*OC,*RS3,*scal;
    __nv_bfloat16 *Ah,*Al,*Bh,*Bl,*Ch,*Cl;
};

static Bufs init_bufs()
{
    Bufs b;
    cudaGetSymbolAddress((void**)&b.X,   g_X);
    cudaGetSymbolAddress((void**)&b.XLN, g_XLN);
    cudaGetSymbolAddress((void**)&b.QKV, g_QKV);
    cudaGetSymbolAddress((void**)&b.QL,  g_QL);
    cudaGetSymbolAddress((void**)&b.KL,  g_KL);
    cudaGetSymbolAddress((void**)&b.S1,  g_S1);
    cudaGetSymbolAddress((void**)&b.S3,  g_S3);
    cudaGetSymbolAddress((void**)&b.S2,  g_S2);
    cudaGetSymbolAddress((void**)&b.T,   g_T);
    cudaGetSymbolAddress((void**)&b.U,   g_U);
    cudaGetSymbolAddress((void**)&b.Rb,  g_R);
    cudaGetSymbolAddress((void**)&b.Z,   g_Z);
    cudaGetSymbolAddress((void**)&b.Z2,  g_Z2);
    cudaGetSymbolAddress((void**)&b.W,   g_W);
    cudaGetSymbolAddress((void**)&b.Wp,  g_Wp);
    cudaGetSymbolAddress((void**)&b.OC,  g_OC);
    cudaGetSymbolAddress((void**)&b.RS3, g_RS3);
    cudaGetSymbolAddress((void**)&b.scal,g_scal);
    cudaGetSymbolAddress((void**)&b.Ah,  g_Ah);
    cudaGetSymbolAddress((void**)&b.Al,  g_Al);
    cudaGetSymbolAddress((void**)&b.Bh,  g_Bh);
    cudaGetSymbolAddress((void**)&b.Bl,  g_Bl);
    cudaGetSymbolAddress((void**)&b.Ch,  g_Ch);
    cudaGetSymbolAddress((void**)&b.Cl,  g_Cl);
    return b;
}

static inline void gemm_call(int bm, const float* A, const float* B, float* C,
    int M, int N, int K, int lda, int ldb, int ldc, int nb,
    long long sAb, long long sAh, long long sBb, long long sBh,
    long long sCb, long long sCh,
    float alpha, bool transb,
    float* aux = nullptr, float diagc = 0.f)
{
    dim3 gr((N + 127)/128, (M + bm - 1)/bm, nb);
    if (bm == 128) {
        if (transb) sgemm<128,true ><<<gr,256>>>(A,B,C,M,N,K,lda,ldb,ldc,sAb,sAh,sBb,sBh,sCb,sCh,alpha,aux,diagc);
        else        sgemm<128,false><<<gr,256>>>(A,B,C,M,N,K,lda,ldb,ldc,sAb,sAh,sBb,sBh,sCb,sCh,alpha,aux,diagc);
    } else {
        if (transb) sgemm<64,true ><<<gr,256>>>(A,B,C,M,N,K,lda,ldb,ldc,sAb,sAh,sBb,sBh,sCb,sCh,alpha,aux,diagc);
        else        sgemm<64,false><<<gr,256>>>(A,B,C,M,N,K,lda,ldb,ldc,sAb,sAh,sBb,sBh,sCb,sCh,alpha,aux,diagc);
    }
}

static void run_layer(const Bufs& bu, int L, void* const* d_in)
{
    const float* lng  = (const float*)d_in[4] + (size_t)L*DMODEL;
    const float* lnb  = (const float*)d_in[5] + (size_t)L*DMODEL;
    const float* wqkv = (const float*)d_in[6] + (size_t)L*DMODEL*QKVW;
    const float* wout = (const float*)d_in[7] + (size_t)L*DMODEL*DMODEL;
    const float* bout = (const float*)d_in[8] + (size_t)L*DMODEL;
    const float* cw   = (const float*)d_in[9] + (size_t)L*NHEADS*KCONV;

    const long long sQKVb = (long long)NF*QKVW;
    const long long sLh = (long long)NLAND*DH;
    const long long sLb = (long long)NHEADS*sLh;
    const long long sS1h = (long long)NF*NLAND;
    const long long sS3h = (long long)NLAND*NF;
    const long long sm = (long long)NLAND*NLAND;
    const long long smb = (long long)NHEADS*sm;

    // x_ln = LN(x)
    ln_kernel<<<NROWS,128>>>(bu.X, bu.XLN, lng, lnb);

    // ---- QKV = x_ln @ w_qkv  (tensor) ----
    cvt_a_kernel<<<dim3((NROWS*DMODEL)/256,1),256>>>(bu.XLN, bu.Ah, bu.Al,
        9, DMODEL, 0, 0, (long long)NROWS*DMODEL, 1.f);
    cvt_t_kernel<<<dim3(QKVW/32, DMODEL/32, 1), dim3(32,8)>>>(wqkv, bu.Bh, bu.Bl,
        DMODEL, QKVW, QKVW, 0, 0);
    mma_gemm<<<dim3(QKVW/128, NROWS/128, 1),256>>>(bu.Ah, bu.Al, bu.Bh, bu.Bl,
        bu.QKV, DMODEL, QKVW, 0, 0, 0, nullptr, nullptr, 0, 0, nullptr, nullptr);

    // landmarks
    landmark_kernel<<<dim3(NLAND,NBH),64>>>(bu.QKV, bu.QL, 0);
    landmark_kernel<<<dim3(NLAND,NBH),64>>>(bu.QKV, bu.KL, DMODEL);

    // ---- sim1 = (q*scale) @ k_l^T  (tensor) ----
    cvt_a_kernel<<<dim3((NF*DH)/256, NBH),256>>>(bu.QKV, bu.Ah, bu.Al,
        6, QKVW, sQKVb, DH, (long long)NF*DH, 0.125f);
    cvt_a_kernel<<<dim3((NLAND*DH)/256, NBH),256>>>(bu.KL, bu.Bh, bu.Bl,
        6, DH, 8*sLh, sLh, sLh, 1.f);
    mma_gemm<<<dim3(NLAND/128, NF/128, NBH),256>>>(bu.Ah, bu.Al, bu.Bh, bu.Bl,
        bu.S1, DH, NLAND, (long long)NF*DH, sLh, sS1h,
        nullptr, nullptr, 0, 0, nullptr, nullptr);

    // ---- sim3 = (q_l*scale) @ k^T  (tensor) ----
    cvt_a_kernel<<<dim3((NLAND*DH)/256, NBH),256>>>(bu.QL, bu.Ah, bu.Al,
        6, DH, 8*sLh, sLh, sLh, 0.125f);
    cvt_a_kernel<<<dim3((NF*DH)/256, NBH),256>>>(bu.QKV + DMODEL, bu.Bh, bu.Bl,
        6, QKVW, sQKVb, DH, (long long)NF*DH, 1.f);
    mma_gemm<<<dim3(NF/128, NLAND/128, NBH),256>>>(bu.Ah, bu.Al, bu.Bh, bu.Bl,
        bu.S3, DH, NF, sLh, (long long)NF*DH, sS3h,
        nullptr, nullptr, 0, 0, nullptr, nullptr);

    // sim2 = (q_l*scale) @ k_l^T  (scalar)
    gemm_call(64, bu.QL, bu.KL, bu.S2, NLAND, NLAND, DH, DH, DH, NLAND, NBH,
              sLb, sLh, sLb, sLh, smb, sm, 0.125f, true);

    // softmaxes: S1 -> normalized split (Ah/Al); S3 -> exp split (Ch/Cl) + 1/sum;
    // S2 fully normalized float
    softmax_split_kernel<<<NBH*NF,256>>>(bu.S1, bu.Ah, bu.Al);
    softmax_split_wide_kernel<<<NBH*NLAND,256>>>(bu.S3, bu.Ch, bu.Cl, bu.RS3);
    softmax_kernel<<<NBH*NLAND,256>>>(bu.S2, NLAND);

    // Moore-Penrose pinv (scalar Newton-Schulz, fused diag epilogues)
    cudaMemsetAsync(bu.scal, 0, 2*sizeof(float));
    pinv_reduce_kernel<<<NBH,256>>>(bu.S2, bu.scal);
    zinit_kernel<<<(NBH*NLAND*NLAND)/256,256>>>(bu.Z, bu.S2, bu.scal);
    float* za = bu.Z;
    float* zb = bu.Z2;
    for (int it = 0; it < 6; it++) {
        gemm_call(64, bu.S2, za, bu.U, NLAND,NLAND,NLAND, NLAND,NLAND,NLAND, NBH,
                  smb,sm, smb,sm, smb,sm, 1.f, false, bu.T, 7.f);
        gemm_call(64, bu.T, bu.U, bu.Rb, NLAND,NLAND,NLAND, NLAND,NLAND,NLAND, NBH,
                  smb,sm, smb,sm, smb,sm, 1.f, false, nullptr, 15.f);
        gemm_call(64, bu.T, bu.Rb, bu.U, NLAND,NLAND,NLAND, NLAND,NLAND,NLAND, NBH,
                  smb,sm, smb,sm, smb,sm, 1.f, false, nullptr, 13.f);
        gemm_call(64, za, bu.U, zb, NLAND,NLAND,NLAND, NLAND,NLAND,NLAND, NBH,
                  smb,sm, smb,sm, smb,sm, 0.25f, false);
        float* tp = za; za = zb; zb = tp;
    }

    // ---- W = softmax(sim3) @ v  (tensor, K-split x4, rowscale in reduce) ----
    cvt_t_kernel<<<dim3(DH/32, NF/32, NBH), dim3(32,8)>>>(bu.QKV + 2*DMODEL,
        bu.Bh, bu.Bl, NF, DH, QKVW, sQKVb, DH);
    mma_gemm64<<<dim3(1, NLAND/128, NBH*4),256>>>(bu.Ch, bu.Cl, bu.Bh, bu.Bl,
        bu.Wp, NF, DH, sS3h, (long long)DH*NF, 8*sLh, sLh,
        4, NF/4, (long long)NBH*NLAND*DH);
    reduce4_rs_kernel<<<(NBH*NLAND*DH)/256,256>>>(bu.Wp, bu.W, bu.RS3,
        (long long)NBH*NLAND*DH);

    // ---- P = attn1 @ Z  (tensor; split-bf16 output into Ch/Cl) ----
    cvt_t_kernel<<<dim3(NLAND/32, NLAND/32, NBH), dim3(32,8)>>>(za, bu.Bh, bu.Bl,
        NLAND, NLAND, NLAND, 8*sm, sm);
    mma_gemm<<<dim3(NLAND/128, NF/128, NBH),256>>>(bu.Ah, bu.Al, bu.Bh, bu.Bl,
        nullptr, NLAND, NLAND, sS1h, sm, sS1h,
        nullptr, nullptr, 0, 0, bu.Ch, bu.Cl);

    // ---- OC = P @ W  (tensor, writes directly into [b][n][512] layout) ----
    cvt_t_kernel<<<dim3(DH/32, NLAND/32, NBH), dim3(32,8)>>>(bu.W, bu.Bh, bu.Bl,
        NLAND, DH, DH, 8*sLh, sLh);
    mma_gemm64<<<dim3(1, NF/128, NBH),256>>>(bu.Ch, bu.Cl, bu.Bh, bu.Bl,
        bu.OC, NLAND, DMODEL, sS1h, (long long)DH*NLAND,
        (long long)NF*DMODEL, DH, 1, NLAND, 0);

    // OC += depthwise conv of V
    conv_kernel<<<dim3(NF/128, NHEADS, NBATCH),256>>>(bu.OC, bu.QKV, cw);

    // ---- x = x + (OC @ w_out + b_out)  (tensor) ----
    cvt_a_kernel<<<dim3((NROWS*DMODEL)/256,1),256>>>(bu.OC, bu.Ah, bu.Al,
        9, DMODEL, 0, 0, (long long)NROWS*DMODEL, 1.f);
    cvt_t_kernel<<<dim3(DMODEL/32, DMODEL/32, 1), dim3(32,8)>>>(wout, bu.Bh, bu.Bl,
        DMODEL, DMODEL, DMODEL, 0, 0);
    mma_gemm<<<dim3(DMODEL/128, NROWS/128, 1),256>>>(bu.Ah, bu.Al, bu.Bh, bu.Bl,
        bu.X, DMODEL, DMODEL, 0, 0, 0, bout, bu.X, DMODEL, 0, nullptr, nullptr);
}

extern "C" void kernel_launch(void* const* d_in, const int* in_sizes, int n_in,
                              void* d_out, int out_size)
{
    static Bufs bu = init_bufs();
    const float* h    = (const float*)d_in[0];
    const float* w1   = (const float*)d_in[1];
    const float* b1   = (const float*)d_in[2];
    const float* cls  = (const float*)d_in[3];
    const float* fng  = (const float*)d_in[10];
    const float* fnb  = (const float*)d_in[11];
    const float* w2   = (const float*)d_in[12];
    const float* b2   = (const float*)d_in[13];

    // ---- x = relu(h @ w1 + b1)  (tensor; padded rows, cls after) ----
    cvt_h_kernel<<<(NROWS*1024)/256,256>>>(h, bu.Ah, bu.Al);
    cvt_t_kernel<<<dim3(DMODEL/32, 1024/32, 1), dim3(32,8)>>>(w1, bu.Bh, bu.Bl,
        1024, DMODEL, DMODEL, 0, 0);
    mma_gemm<<<dim3(DMODEL/128, NROWS/128, 1),256>>>(bu.Ah, bu.Al, bu.Bh, bu.Bl,
        bu.X, 1024, DMODEL, 0, 0, 0, b1, nullptr, 0, 1, nullptr, nullptr);
    cls_copy_kernel<<<1,512>>>(bu.X, cls);

    run_layer(bu, 0, d_in);
    run_layer(bu, 1, d_in);

    final_kernel<<<NBATCH,128>>>(bu.X, fng, fnb, w2, b2, (float*)d_out);
}